// round 11
// baseline (speedup 1.0000x reference)
#include <cuda_runtime.h>
#include <cuda_bf16.h>
#include <cstdint>
#include <math.h>

// ---------------- problem constants ----------------
#define NS    4096          // N samples
#define LS    16            // L tokens
#define DE    768           // D embedding
#define NHN   4             // heads (name attn)
#define DHN   192           // head dim (name attn)
#define HD    1024          // H
#define NLAY  4             // NL
#define NCLS  16            // C
#define XFD   256           // XF

// ---------------- scratch (device globals; no cudaMalloc allowed) ----------------
__device__ float g_qkv[(size_t)NS * LS * 2 * DE];   // compacted Q,K rows, fp32
__device__ float g_h[(size_t)NS * HD];              // fp32 residual stream
__device__ float g_ta[(size_t)NS * HD];             // fp32 (pre-LN sum)

__device__ int g_off[NS + 1];
__device__ int g_total[1];
__device__ int g_rowtok[NS * LS];

__device__ float g_zero[4096];
__device__ float g_bc[NLAY * HD];
__device__ float g_bao[HD];

// bf16 hi/lo split buffers (activations)
__device__ __align__(16) __nv_bfloat16 g_gah[(size_t)NS * LS * DE],   g_gal[(size_t)NS * LS * DE];
__device__ __align__(16) __nv_bfloat16 g_ce_h[(size_t)NS * NHN * DE], g_ce_l[(size_t)NS * NHN * DE];
__device__ __align__(16) __nv_bfloat16 g_attn_h[(size_t)NS * DE],     g_attn_l[(size_t)NS * DE];
__device__ __align__(16) __nv_bfloat16 g_xf_h[(size_t)NS * XFD],      g_xf_l[(size_t)NS * XFD];
__device__ __align__(16) __nv_bfloat16 g_hh[(size_t)NS * HD],         g_hl[(size_t)NS * HD];
__device__ __align__(16) __nv_bfloat16 g_t1_h[(size_t)NS * 2 * HD],   g_t1_l[(size_t)NS * 2 * HD];

// bf16 hi/lo split buffers (weights)
__device__ __align__(16) __nv_bfloat16 g_wqkv_h[(size_t)3 * DE * DE], g_wqkv_l[(size_t)3 * DE * DE];
__device__ __align__(16) __nv_bfloat16 g_wbott_h[(size_t)HD * (XFD + DE)], g_wbott_l[(size_t)HD * (XFD + DE)];
__device__ __align__(16) __nv_bfloat16 g_wo_h[(size_t)NLAY * HD * HD],  g_wo_l[(size_t)NLAY * HD * HD];
__device__ __align__(16) __nv_bfloat16 g_wf1_h[(size_t)NLAY * 2 * HD * HD], g_wf1_l[(size_t)NLAY * 2 * HD * HD];
__device__ __align__(16) __nv_bfloat16 g_wf2_h[(size_t)NLAY * HD * 2 * HD], g_wf2_l[(size_t)NLAY * HD * 2 * HD];
__device__ __align__(16) __nv_bfloat16 g_wvt_h[(size_t)NLAY * HD * HD],  g_wvt_l[(size_t)NLAY * HD * HD];
__device__ __align__(16) __nv_bfloat16 g_woutt_h[(size_t)DE * DE],       g_woutt_l[(size_t)DE * DE];
__device__ __align__(16) __nv_bfloat16 g_wc_h[(size_t)NLAY * HD * HD],   g_wc_l[(size_t)NLAY * HD * HD];
__device__ __align__(16) __nv_bfloat16 g_wao_h[(size_t)HD * DE],         g_wao_l[(size_t)HD * DE];

// ================= helpers =================
__device__ __forceinline__ uint32_t smem_u32(const void* p) {
    uint32_t a;
    asm("{ .reg .u64 t; cvta.to.shared.u64 t, %1; cvt.u32.u64 %0, t; }" : "=r"(a) : "l"(p));
    return a;
}
__device__ __forceinline__ uint32_t sw128(uint32_t o) { return o ^ ((o >> 3) & 0x70); }

#define LDSM4(r, addr) \
    asm volatile("ldmatrix.sync.aligned.m8n8.x4.shared.b16 {%0,%1,%2,%3}, [%4];" \
        : "=r"((r)[0]), "=r"((r)[1]), "=r"((r)[2]), "=r"((r)[3]) : "r"(addr))

__device__ __forceinline__ void mma16816(float* c, const uint32_t* a, uint32_t b0, uint32_t b1) {
    asm volatile("mma.sync.aligned.m16n8k16.row.col.f32.bf16.bf16.f32 "
        "{%0,%1,%2,%3},{%4,%5,%6,%7},{%8,%9},{%0,%1,%2,%3};"
        : "+f"(c[0]), "+f"(c[1]), "+f"(c[2]), "+f"(c[3])
        : "r"(a[0]), "r"(a[1]), "r"(a[2]), "r"(a[3]), "r"(b0), "r"(b1));
}

#define CP_ASYNC16(dst, src) \
    asm volatile("cp.async.cg.shared.global [%0], [%1], 16;" :: "r"(dst), "l"(src))
#define CP_COMMIT() asm volatile("cp.async.commit_group;" ::: "memory")
#define CP_WAIT(n)  asm volatile("cp.async.wait_group %0;" :: "n"(n) : "memory")

// split fp32 pair -> packed bf16 hi (p) and lo residual (q)
__device__ __forceinline__ void split2(float x, float y, uint32_t& p, uint32_t& q) {
    asm("cvt.rn.bf16x2.f32 %0, %1, %2;" : "=r"(p) : "f"(y), "f"(x));
    float h0 = __uint_as_float(p << 16);
    float h1 = __uint_as_float(p & 0xffff0000u);
    float r0 = x - h0, r1 = y - h1;
    asm("cvt.rn.bf16x2.f32 %0, %1, %2;" : "=r"(q) : "f"(r1), "f"(r0));
}

// ---------------- fp32 -> bf16 hi/lo split ----------------
__global__ __launch_bounds__(256) void split_kernel(
    const float* __restrict__ src,
    __nv_bfloat16* __restrict__ hi, __nv_bfloat16* __restrict__ lo, int n2)
{
    const int i = blockIdx.x * blockDim.x + threadIdx.x;
    if (i < n2) {
        const float2 v = reinterpret_cast<const float2*>(src)[i];
        uint32_t p, q;
        split2(v.x, v.y, p, q);
        reinterpret_cast<uint32_t*>(hi)[i] = p;
        reinterpret_cast<uint32_t*>(lo)[i] = q;
    }
}

// ---------------- batched fp32 [R x C] -> transposed bf16 hi/lo [C x R] ----------------
__global__ __launch_bounds__(256) void transpose_split_kernel(
    const float* __restrict__ src, int ld, int R,
    __nv_bfloat16* __restrict__ dh, __nv_bfloat16* __restrict__ dl,
    size_t srcStride, size_t dstStride)
{
    __shared__ float tile[32][33];
    const int z = blockIdx.z;
    src += (size_t)z * srcStride;
    dh  += (size_t)z * dstStride;
    dl  += (size_t)z * dstStride;
    const int c0 = blockIdx.x * 32, r0 = blockIdx.y * 32;
    const int tx = threadIdx.x, ty = threadIdx.y;   // (32, 8)
#pragma unroll
    for (int i = ty; i < 32; i += 8)
        tile[i][tx] = src[(size_t)(r0 + i) * ld + c0 + tx];
    __syncthreads();
    if (tx < 16) {
#pragma unroll
        for (int i = ty; i < 32; i += 8) {
            uint32_t p, q;
            split2(tile[2 * tx][i], tile[2 * tx + 1][i], p, q);
            const size_t id2 = ((size_t)(c0 + i) * R + r0) / 2 + tx;
            reinterpret_cast<uint32_t*>(dh)[id2] = p;
            reinterpret_cast<uint32_t*>(dl)[id2] = q;
        }
    }
}

// ---------------- batched bias fold: out[row] = W[row,:]·v + base[row] ----------------
__global__ __launch_bounds__(128) void bias_fold_kernel(
    const float* __restrict__ W, int ldw, int coff,
    const float* __restrict__ v, const float* __restrict__ base,
    float* __restrict__ out, int K,
    size_t wStride, size_t vStride, size_t baseStride, size_t outStride)
{
    __shared__ float red[4];
    const int z = blockIdx.y;
    W += (size_t)z * wStride;
    v += (size_t)z * vStride;
    if (base) base += (size_t)z * baseStride;
    out += (size_t)z * outStride;
    const int row = blockIdx.x;
    const int t = threadIdx.x, lane = t & 31, warp = t >> 5;
    const float* wr = W + (size_t)row * ldw + coff;
    float s = 0.f;
    for (int k = t; k < K; k += 128) s += wr[k] * v[k];
#pragma unroll
    for (int o = 16; o; o >>= 1) s += __shfl_down_sync(0xffffffffu, s, o);
    if (lane == 0) red[warp] = s;
    __syncthreads();
    if (t == 0) out[row] = red[0] + red[1] + red[2] + red[3] + (base ? base[row] : 0.f);
}

// ---------------- compaction scan ----------------
__global__ __launch_bounds__(1024) void scan_kernel(
    const int* __restrict__ lens, int* __restrict__ off, int* __restrict__ total)
{
    __shared__ int wsum[32];
    const int tid = threadIdx.x, lane = tid & 31, warp = tid >> 5;
    int v[4], s = 0;
#pragma unroll
    for (int i = 0; i < 4; i++) { v[i] = lens[tid * 4 + i]; s += v[i]; }
    int ws = s;
#pragma unroll
    for (int o = 1; o < 32; o <<= 1) { int t = __shfl_up_sync(0xffffffffu, ws, o); if (lane >= o) ws += t; }
    if (lane == 31) wsum[warp] = ws;
    __syncthreads();
    if (warp == 0) {
        int t = wsum[lane];
#pragma unroll
        for (int o = 1; o < 32; o <<= 1) { int u = __shfl_up_sync(0xffffffffu, t, o); if (lane >= o) t += u; }
        wsum[lane] = t;
    }
    __syncthreads();
    int run = ws - s + (warp ? wsum[warp - 1] : 0);
#pragma unroll
    for (int i = 0; i < 4; i++) { off[tid * 4 + i] = run; run += v[i]; }
    if (tid == 1023) { off[NS] = run; total[0] = run; }
}

__global__ __launch_bounds__(32) void fill_rows_kernel(
    const int* __restrict__ lens, const int* __restrict__ off,
    const int* __restrict__ toks, int* __restrict__ rowtok)
{
    const int b = blockIdx.x;
    const int len = lens[b], o = off[b];
    for (int s = threadIdx.x; s < len; s += 32) rowtok[o + s] = toks[b * LS + s];
}

__global__ __launch_bounds__(128) void gather_split_kernel(
    const float* __restrict__ wte, const int* __restrict__ rowtok,
    const int* __restrict__ total,
    __nv_bfloat16* __restrict__ Ah, __nv_bfloat16* __restrict__ Al)
{
    const int r = blockIdx.x;
    if (r >= total[0]) return;
    const float2* src = reinterpret_cast<const float2*>(wte + (size_t)rowtok[r] * DE);
    uint32_t* dh = reinterpret_cast<uint32_t*>(Ah) + (size_t)r * (DE / 2);
    uint32_t* dl = reinterpret_cast<uint32_t*>(Al) + (size_t)r * (DE / 2);
#pragma unroll
    for (int i = 0; i < 3; i++) {
        const int j = threadIdx.x + 128 * i;
        const float2 v = src[j];
        uint32_t p, q;
        split2(v.x, v.y, p, q);
        dh[j] = p; dl[j] = q;
    }
}

// ================= HMMA GEMM: C[M,N] = A[M,K] @ B[N,K]^T + bias (+rs*bias2) (+RES) =================
#define CHUNK  64
#define STG_BYTES (96 * 1024)
#define OFF_AH 0
#define OFF_AL 32768
#define OFF_BH 65536
#define OFF_BL 81920
#define TG_SMEM  (2 * STG_BYTES + 256)

template<int AMODE, int BMODE, bool RELU, bool WF32, bool WSPLIT, bool MDYN, bool HASB2, bool NDYN, bool RESID>
__global__ __launch_bounds__(256, 1) void tgemm_kernel(
    int M, int N, int K, int K1,
    const __nv_bfloat16* __restrict__ Ah, const __nv_bfloat16* __restrict__ Al, int lda,
    const __nv_bfloat16* __restrict__ A2h, const __nv_bfloat16* __restrict__ A2l, int lda2,
    const int* __restrict__ Mlim,
    const __nv_bfloat16* __restrict__ Bh, const __nv_bfloat16* __restrict__ Bl, int ldb,
    const __nv_bfloat16* __restrict__ B2h, const __nv_bfloat16* __restrict__ B2l, int ldb2,
    const float* __restrict__ bias, const float* __restrict__ bias2,
    const int* __restrict__ rowscale,
    float* __restrict__ C,
    __nv_bfloat16* __restrict__ Ch, __nv_bfloat16* __restrict__ Cl,
    size_t strideA, size_t strideB, size_t strideC,
    int ldc, int Nlim, size_t strideB2,
    const float* __restrict__ RES)
{
    extern __shared__ char smem[];
    const uint32_t sb = smem_u32(smem);

    const int z = blockIdx.z;
    if (strideA) { Ah += (size_t)z * strideA; Al += (size_t)z * strideA; }
    if (strideB) { Bh += (size_t)z * strideB; Bl += (size_t)z * strideB; }
    if (strideC) { Ch += (size_t)z * strideC; Cl += (size_t)z * strideC; }
    if (HASB2 && strideB2) bias2 += (size_t)z * strideB2;

    const int tid  = threadIdx.x;
    const int lane = tid & 31;
    const int wid  = tid >> 5;
    const int bm = blockIdx.y * 256, bn = blockIdx.x * 128;

    int Mtot = M;
    if (MDYN) {
        Mtot = Mlim[0];
        if (bm >= Mtot) return;
    }

    const int nch = K / CHUNK;

    auto issue_stage = [&](int c) {
        const int k0 = c * CHUNK;
        const uint32_t st = sb + (c & 1) * STG_BYTES;
#pragma unroll
        for (int i = 0; i < 8; i++) {
            const int idx = tid + 256 * i;
            const int row = idx >> 3;
            const int seg = idx & 7;
            const uint32_t sw = sw128(row * 128 + seg * 16);
            int ar = bm + row;
            if (MDYN && ar >= Mtot) ar = Mtot - 1;
            const __nv_bfloat16 *pah, *pal;
            if (AMODE == 2 && k0 >= K1) {
                const size_t off = (size_t)ar * lda2 + (k0 - K1) + seg * 8;
                pah = A2h + off; pal = A2l + off;
            } else {
                const size_t off = (size_t)ar * lda + k0 + seg * 8;
                pah = Ah + off; pal = Al + off;
            }
            CP_ASYNC16(st + OFF_AH + sw, pah);
            CP_ASYNC16(st + OFF_AL + sw, pal);
        }
#pragma unroll
        for (int i = 0; i < 4; i++) {
            const int idx = tid + 256 * i;
            const int row = idx >> 3;
            const int seg = idx & 7;
            const uint32_t sw = sw128(row * 128 + seg * 16);
            int br = bn + row;
            if (NDYN && br >= Nlim) br = Nlim - 1;
            const __nv_bfloat16 *pbh, *pbl;
            if (BMODE == 2 && k0 >= K1) {
                const size_t off = (size_t)br * ldb2 + (k0 - K1) + seg * 8;
                pbh = B2h + off; pbl = B2l + off;
            } else {
                const size_t off = (size_t)br * ldb + k0 + seg * 8;
                pbh = Bh + off; pbl = Bl + off;
            }
            CP_ASYNC16(st + OFF_BH + sw, pbh);
            CP_ASYNC16(st + OFF_BL + sw, pbl);
        }
        CP_COMMIT();
    };

    issue_stage(0);

    const int wm = (wid >> 1) * 64;
    const int wn = (wid & 1) * 64;

    float acc[4][8][4];
#pragma unroll
    for (int i = 0; i < 4; i++)
#pragma unroll
        for (int j = 0; j < 8; j++)
#pragma unroll
            for (int t = 0; t < 4; t++) acc[i][j][t] = 0.f;

    const int a_row  = (lane & 15);
    const int a_kb   = (lane >> 4) * 16;
    const int b_row  = (lane & 7) + ((lane >> 4) << 3);
    const int b_kb   = ((lane >> 3) & 1) * 16;

    for (int c = 0; c < nch; c++) {
        CP_WAIT(0);
        __syncthreads();
        if (c + 1 < nch) issue_stage(c + 1);

        const uint32_t st = sb + (c & 1) * STG_BYTES;

#pragma unroll
        for (int ks = 0; ks < 4; ks++) {
            const int kb = ks * 32;
            uint32_t ah[4][4], al[4][4];
#pragma unroll
            for (int i = 0; i < 4; i++) {
                const uint32_t oa = sw128((wm + i * 16 + a_row) * 128 + kb + a_kb);
                LDSM4(ah[i], st + OFF_AH + oa);
                LDSM4(al[i], st + OFF_AL + oa);
            }
            uint32_t bf[4][4];
#pragma unroll
            for (int j2 = 0; j2 < 4; j2++) {
                const uint32_t ob = sw128((wn + j2 * 16 + b_row) * 128 + kb + b_kb);
                LDSM4(bf[j2], st + OFF_BH + ob);
            }
#pragma unroll
            for (int i = 0; i < 4; i++)
#pragma unroll
                for (int j2 = 0; j2 < 4; j2++) {
                    mma16816(acc[i][2 * j2 + 0], ah[i], bf[j2][0], bf[j2][1]);
                    mma16816(acc[i][2 * j2 + 1], ah[i], bf[j2][2], bf[j2][3]);
                    mma16816(acc[i][2 * j2 + 0], al[i], bf[j2][0], bf[j2][1]);
                    mma16816(acc[i][2 * j2 + 1], al[i], bf[j2][2], bf[j2][3]);
                }
#pragma unroll
            for (int j2 = 0; j2 < 4; j2++) {
                const uint32_t ob = sw128((wn + j2 * 16 + b_row) * 128 + kb + b_kb);
                LDSM4(bf[j2], st + OFF_BL + ob);
            }
#pragma unroll
            for (int i = 0; i < 4; i++)
#pragma unroll
                for (int j2 = 0; j2 < 4; j2++) {
                    mma16816(acc[i][2 * j2 + 0], ah[i], bf[j2][0], bf[j2][1]);
                    mma16816(acc[i][2 * j2 + 1], ah[i], bf[j2][2], bf[j2][3]);
                }
        }
    }

    // ---- epilogue ----
#pragma unroll
    for (int i = 0; i < 4; i++) {
        const int r0 = bm + wm + i * 16 + (lane >> 2);
        const int r1 = r0 + 8;
        const bool ok0 = !MDYN || (r0 < Mtot);
        const bool ok1 = !MDYN || (r1 < Mtot);
        const float rs0 = HASB2 ? (float)rowscale[r0] : 0.f;
        const float rs1 = HASB2 ? (float)rowscale[r1] : 0.f;
#pragma unroll
        for (int j = 0; j < 8; j++) {
            const int col = bn + wn + j * 8 + (lane & 3) * 2;
            const bool okc = !NDYN || (col < Nlim);
            float b00 = bias[col], b01 = bias[col + 1];
            float b10 = b00, b11 = b01;
            if (HASB2) {
                b00 += rs0 * bias2[col]; b01 += rs0 * bias2[col + 1];
                b10 += rs1 * bias2[col]; b11 += rs1 * bias2[col + 1];
            }
            float2 v0 = make_float2(acc[i][j][0] + b00, acc[i][j][1] + b01);
            float2 v1 = make_float2(acc[i][j][2] + b10, acc[i][j][3] + b11);
            if (RESID) {
                const float2 h0 = *reinterpret_cast<const float2*>(RES + (size_t)r0 * ldc + col);
                const float2 h1 = *reinterpret_cast<const float2*>(RES + (size_t)r1 * ldc + col);
                v0.x += h0.x; v0.y += h0.y;
                v1.x += h1.x; v1.y += h1.y;
            }
            if (RELU) {
                v0.x = fmaxf(v0.x, 0.f); v0.y = fmaxf(v0.y, 0.f);
                v1.x = fmaxf(v1.x, 0.f); v1.y = fmaxf(v1.y, 0.f);
            }
            if (WF32) {
                if (ok0 && okc) *reinterpret_cast<float2*>(C + (size_t)r0 * ldc + col) = v0;
                if (ok1 && okc) *reinterpret_cast<float2*>(C + (size_t)r1 * ldc + col) = v1;
            }
            if (WSPLIT) {
                uint32_t p, q;
                if (ok0 && okc) {
                    split2(v0.x, v0.y, p, q);
                    reinterpret_cast<uint32_t*>(Ch)[((size_t)r0 * ldc + col) >> 1] = p;
                    reinterpret_cast<uint32_t*>(Cl)[((size_t)r0 * ldc + col) >> 1] = q;
                }
                if (ok1 && okc) {
                    split2(v1.x, v1.y, p, q);
                    reinterpret_cast<uint32_t*>(Ch)[((size_t)r1 * ldc + col) >> 1] = p;
                    reinterpret_cast<uint32_t*>(Cl)[((size_t)r1 * ldc + col) >> 1] = q;
                }
            }
        }
    }
}

// ---------------- name attention: one block per SAMPLE, all 4 heads; emits CE ----------------
// CE_h = sum_j (sum_{s<len} a_h[s,j]) * e_j
#define ATTN_SMEM (2 * LS * DE * 4 + NHN * LS * (LS + 1) * 4 + NHN * LS * 4 + 256)
__global__ __launch_bounds__(256) void name_attn_kernel(
    const float* __restrict__ qk, const int* __restrict__ off,
    const __nv_bfloat16* __restrict__ eh, const __nv_bfloat16* __restrict__ el,
    __nv_bfloat16* __restrict__ CEh, __nv_bfloat16* __restrict__ CEl)
{
    extern __shared__ char asmem[];
    float (*Qs)[DE] = reinterpret_cast<float(*)[DE]>(asmem);                       // [LS][DE]
    float (*Ks)[DE] = reinterpret_cast<float(*)[DE]>(asmem + LS * DE * 4);         // [LS][DE]
    float (*sc)[LS][LS + 1] = reinterpret_cast<float(*)[LS][LS + 1]>(asmem + 2 * LS * DE * 4);
    float (*cw)[LS] = reinterpret_cast<float(*)[LS]>(asmem + 2 * LS * DE * 4 + NHN * LS * (LS + 1) * 4);

    const int b = blockIdx.x;
    const int tid = threadIdx.x;
    const int warp = tid >> 5, lane = tid & 31;

    const int o   = off[b];
    const int len = off[b + 1] - o;

    // load Q,K rows once (all heads)
    for (int s = 0; s < len; s++) {
        const float* src = qk + (size_t)(o + s) * (2 * DE);
        for (int i = tid; i < DE; i += 256) {
            Qs[s][i] = src[i];
            Ks[s][i] = src[DE + i];
        }
    }
    __syncthreads();

    // scores for all heads: pairs (h, q, j)
    const float scale = 1.0f / sqrtf((float)DHN);
    const int npp = len * len;
    const int np4 = NHN * npp;
    for (int p = warp; p < np4; p += 8) {
        const int h = p / npp;
        const int r = p - h * npp;
        const int q = r / len, j = r - q * len;
        const int base = h * DHN;
        float s = 0.f;
#pragma unroll
        for (int i = 0; i < 6; i++) s += Qs[q][base + lane + 32 * i] * Ks[j][base + lane + 32 * i];
#pragma unroll
        for (int ofs = 16; ofs; ofs >>= 1) s += __shfl_down_sync(0xffffffffu, s, ofs);
        if (lane == 0) sc[h][q][j] = s * scale;
    }
    __syncthreads();

    // softmax per (h, q)
    if (tid < NHN * LS) {
        const int h = tid >> 4, q = tid & 15;
        if (q < len) {
            float mx = -1e30f;
            for (int j = 0; j < len; j++) mx = fmaxf(mx, sc[h][q][j]);
            float sum = 0.f;
            float row[LS];
            for (int j = 0; j < len; j++) { row[j] = expf(sc[h][q][j] - mx); sum += row[j]; }
            const float inv = 1.f / sum;
            for (int j = 0; j < len; j++) sc[h][q][j] = row[j] * inv;
        }
    }
    __syncthreads();

    // column weights cw[h][j] = sum over q rows
    if (tid < NHN * LS) {
        const int h = tid >> 4, j = tid & 15;
        if (j < len) {
            float c = 0.f;
            for (int s = 0; s < len; s++) c += sc[h][s][j];
            cw[h][j] = c;
        }
    }
    __syncthreads();

    // CE: read E once, accumulate all 4 heads
    const uint32_t* ehp = reinterpret_cast<const uint32_t*>(eh);
    const uint32_t* elp = reinterpret_cast<const uint32_t*>(el);
    for (int p = tid; p < DE / 2; p += 256) {
        float ce[NHN][2];
#pragma unroll
        for (int h = 0; h < NHN; h++) { ce[h][0] = 0.f; ce[h][1] = 0.f; }
        for (int j = 0; j < len; j++) {
            const size_t idx = (size_t)(o + j) * (DE / 2) + p;
            const uint32_t uh = ehp[idx], ul = elp[idx];
            const float e0 = __uint_as_float(uh << 16) + __uint_as_float(ul << 16);
            const float e1 = __uint_as_float(uh & 0xffff0000u) + __uint_as_float(ul & 0xffff0000u);
#pragma unroll
            for (int h = 0; h < NHN; h++) {
                ce[h][0] += cw[h][j] * e0;
                ce[h][1] += cw[h][j] * e1;
            }
        }
#pragma unroll
        for (int h = 0; h < NHN; h++) {
            uint32_t P, Q;
            split2(ce[h][0], ce[h][1], P, Q);
            const size_t id2 = (size_t)b * (NHN * DE / 2) + h * (DE / 2) + p;
            reinterpret_cast<uint32_t*>(CEh)[id2] = P;
            reinterpret_cast<uint32_t*>(CEl)[id2] = Q;
        }
    }
}

// ---------------- LayerNorm of ta (residual already added in GEMM epilogue) ----------------
__device__ __forceinline__ float block_reduce_sum(float v) {
    __shared__ float red[8];
    const int lane = threadIdx.x & 31, warp = threadIdx.x >> 5;
#pragma unroll
    for (int o = 16; o; o >>= 1) v += __shfl_down_sync(0xffffffffu, v, o);
    if (lane == 0) red[warp] = v;
    __syncthreads();
    v = (threadIdx.x < 8) ? red[threadIdx.x] : 0.f;
    if (warp == 0)
#pragma unroll
        for (int o = 4; o; o >>= 1) v += __shfl_down_sync(0xffffffffu, v, o);
    return v;
}

template<bool WRITEH, bool DOCLS>
__global__ __launch_bounds__(256) void ln_kernel(
    const float* __restrict__ ta,
    const float* __restrict__ g, const float* __restrict__ b,
    float* __restrict__ h,
    __nv_bfloat16* __restrict__ hh, __nv_bfloat16* __restrict__ hl,
    const float* __restrict__ clsw, const float* __restrict__ clsb,
    float* __restrict__ out)
{
    const int row = blockIdx.x;
    const int t = threadIdx.x;
    float v[4];
    float s = 0.f;
#pragma unroll
    for (int i = 0; i < 4; i++) {
        const int c = t + 256 * i;
        v[i] = ta[(size_t)row * HD + c];
        s += v[i];
    }
    s = block_reduce_sum(s);
    __shared__ float mean_s, rstd_s;
    if (t == 0) mean_s = s * (1.f / HD);
    __syncthreads();
    const float m = mean_s;
    float s2 = 0.f;
#pragma unroll
    for (int i = 0; i < 4; i++) { const float dd = v[i] - m; s2 += dd * dd; }
    s2 = block_reduce_sum(s2);
    if (t == 0) rstd_s = rsqrtf(s2 * (1.f / HD) + 1e-5f);
    __syncthreads();
    const float r = rstd_s;

    __shared__ float ys[HD];
#pragma unroll
    for (int i = 0; i < 4; i++) {
        const int c = t + 256 * i;
        const float y = (v[i] - m) * r * g[c] + b[c];
        if (WRITEH) {
            h[(size_t)row * HD + c] = y;
            const float y1 = __shfl_down_sync(0xffffffffu, y, 1);
            if (!(t & 1)) {
                uint32_t p, q;
                split2(y, y1, p, q);
                const size_t id2 = ((size_t)row * HD + c) >> 1;
                reinterpret_cast<uint32_t*>(hh)[id2] = p;
                reinterpret_cast<uint32_t*>(hl)[id2] = q;
            }
        }
        if (DOCLS) ys[c] = y;
    }
    if (DOCLS) {
        __syncthreads();
        const int warp = t >> 5, lane = t & 31;
        for (int cc = warp; cc < NCLS; cc += 8) {
            const float* wr = clsw + (size_t)cc * HD;
            float sum = 0.f;
#pragma unroll
            for (int i = lane; i < HD; i += 32) sum += ys[i] * wr[i];
#pragma unroll
            for (int o = 16; o; o >>= 1) sum += __shfl_down_sync(0xffffffffu, sum, o);
            if (lane == 0) out[(size_t)row * NCLS + cc] = sum + clsb[cc];
        }
    }
}

// ---------------- orchestration ----------------
static inline void launch_split_s(cudaStream_t st, const float* src,
                                  __nv_bfloat16* hi, __nv_bfloat16* lo, size_t n) {
    const int n2 = (int)(n / 2);
    split_kernel<<<(n2 + 255) / 256, 256, 0, st>>>(src, hi, lo, n2);
}

extern "C" void kernel_launch(void* const* d_in, const int* in_sizes, int n_in,
                              void* d_out, int out_size)
{
    const int*   name_tokens = (const int*)d_in[0];
    const int*   name_lens   = (const int*)d_in[1];
    const float* x_feats     = (const float*)d_in[2];
    const float* wte         = (const float*)d_in[3];
    const float* mha_in_w    = (const float*)d_in[4];
    const float* mha_in_b    = (const float*)d_in[5];
    const float* mha_out_w   = (const float*)d_in[6];
    const float* mha_out_b   = (const float*)d_in[7];
    const float* bott_w      = (const float*)d_in[8];
    const float* bott_b      = (const float*)d_in[9];
    const float* enc_in_w    = (const float*)d_in[10];
    const float* enc_in_b    = (const float*)d_in[11];
    const float* enc_out_w   = (const float*)d_in[12];
    const float* enc_out_b   = (const float*)d_in[13];
    const float* enc_ln1_g   = (const float*)d_in[14];
    const float* enc_ln1_b   = (const float*)d_in[15];
    const float* enc_ln2_g   = (const float*)d_in[16];
    const float* enc_ln2_b   = (const float*)d_in[17];
    const float* enc_ff1_w   = (const float*)d_in[18];
    const float* enc_ff1_b   = (const float*)d_in[19];
    const float* enc_ff2_w   = (const float*)d_in[20];
    const float* enc_ff2_b   = (const float*)d_in[21];
    const float* cls_w       = (const float*)d_in[22];
    const float* cls_b       = (const float*)d_in[23];
    float* out = (float*)d_out;

    float *qkv, *h, *ta, *zero, *bc, *bao;
    int *off, *total, *rowtok;
    cudaGetSymbolAddress((void**)&qkv,    g_qkv);
    cudaGetSymbolAddress((void**)&h,      g_h);
    cudaGetSymbolAddress((void**)&ta,     g_ta);
    cudaGetSymbolAddress((void**)&zero,   g_zero);
    cudaGetSymbolAddress((void**)&bc,     g_bc);
    cudaGetSymbolAddress((void**)&bao,    g_bao);
    cudaGetSymbolAddress((void**)&off,    g_off);
    cudaGetSymbolAddress((void**)&total,  g_total);
    cudaGetSymbolAddress((void**)&rowtok, g_rowtok);

    __nv_bfloat16 *gah, *gal, *ce_h, *ce_l, *attn_h, *attn_l, *xf_h, *xf_l, *hh, *hl, *t1_h, *t1_l;
    __nv_bfloat16 *wqkv_h, *wqkv_l, *wbott_h, *wbott_l, *wo_h, *wo_l, *wf1_h, *wf1_l, *wf2_h, *wf2_l;
    __nv_bfloat16 *wvt_h, *wvt_l, *woutt_h, *woutt_l, *wc_h, *wc_l, *wao_h, *wao_l;
    cudaGetSymbolAddress((void**)&gah,    g_gah);     cudaGetSymbolAddress((void**)&gal,    g_gal);
    cudaGetSymbolAddress((void**)&ce_h,   g_ce_h);    cudaGetSymbolAddress((void**)&ce_l,   g_ce_l);
    cudaGetSymbolAddress((void**)&attn_h, g_attn_h);  cudaGetSymbolAddress((void**)&attn_l, g_attn_l);
    cudaGetSymbolAddress((void**)&xf_h,   g_xf_h);    cudaGetSymbolAddress((void**)&xf_l,   g_xf_l);
    cudaGetSymbolAddress((void**)&hh,     g_hh);      cudaGetSymbolAddress((void**)&hl,     g_hl);
    cudaGetSymbolAddress((void**)&t1_h,   g_t1_h);    cudaGetSymbolAddress((void**)&t1_l,   g_t1_l);
    cudaGetSymbolAddress((void**)&wqkv_h, g_wqkv_h);  cudaGetSymbolAddress((void**)&wqkv_l, g_wqkv_l);
    cudaGetSymbolAddress((void**)&wbott_h,g_wbott_h); cudaGetSymbolAddress((void**)&wbott_l,g_wbott_l);
    cudaGetSymbolAddress((void**)&wo_h,   g_wo_h);    cudaGetSymbolAddress((void**)&wo_l,   g_wo_l);
    cudaGetSymbolAddress((void**)&wf1_h,  g_wf1_h);   cudaGetSymbolAddress((void**)&wf1_l,  g_wf1_l);
    cudaGetSymbolAddress((void**)&wf2_h,  g_wf2_h);   cudaGetSymbolAddress((void**)&wf2_l,  g_wf2_l);
    cudaGetSymbolAddress((void**)&wvt_h,  g_wvt_h);   cudaGetSymbolAddress((void**)&wvt_l,  g_wvt_l);
    cudaGetSymbolAddress((void**)&woutt_h,g_woutt_h); cudaGetSymbolAddress((void**)&woutt_l,g_woutt_l);
    cudaGetSymbolAddress((void**)&wc_h,   g_wc_h);    cudaGetSymbolAddress((void**)&wc_l,   g_wc_l);
    cudaGetSymbolAddress((void**)&wao_h,  g_wao_h);   cudaGetSymbolAddress((void**)&wao_l,  g_wao_l);

    auto k_qk    = tgemm_kernel<0, 0, false, true,  false, true,  false, false, false>;
    auto k_csum  = tgemm_kernel<0, 0, false, false, true,  false, true,  true,  false>;
    auto k_bott  = tgemm_kernel<2, 2, false, true,  true,  false, true,  false, false>;
    auto k_resid = tgemm_kernel<0, 0, false, true,  false, false, false, false, true >;
    auto k_ff1   = tgemm_kernel<0, 0, true,  false, true,  false, false, false, false>;
    auto k_pre   = tgemm_kernel<0, 0, false, false, true,  false, false, false, false>;
    cudaFuncSetAttribute(k_qk,    cudaFuncAttributeMaxDynamicSharedMemorySize, TG_SMEM);
    cudaFuncSetAttribute(k_csum,  cudaFuncAttributeMaxDynamicSharedMemorySize, TG_SMEM);
    cudaFuncSetAttribute(k_bott,  cudaFuncAttributeMaxDynamicSharedMemorySize, TG_SMEM);
    cudaFuncSetAttribute(k_resid, cudaFuncAttributeMaxDynamicSharedMemorySize, TG_SMEM);
    cudaFuncSetAttribute(k_ff1,   cudaFuncAttributeMaxDynamicSharedMemorySize, TG_SMEM);
    cudaFuncSetAttribute(k_pre,   cudaFuncAttributeMaxDynamicSharedMemorySize, TG_SMEM);
    cudaFuncSetAttribute(name_attn_kernel, cudaFuncAttributeMaxDynamicSharedMemorySize, ATTN_SMEM);

    cudaStream_t side = 0;
    cudaEvent_t evFork = 0, evJoin = 0;
    bool use_side = (cudaStreamCreateWithFlags(&side, cudaStreamNonBlocking) == cudaSuccess)
                 && (cudaEventCreateWithFlags(&evFork, cudaEventDisableTiming) == cudaSuccess)
                 && (cudaEventCreateWithFlags(&evJoin, cudaEventDisableTiming) == cudaSuccess);
    cudaStream_t prepSt = use_side ? side : (cudaStream_t)0;

    // ---- main-path prep ----
    scan_kernel<<<1, 1024>>>(name_lens, off, total);
    fill_rows_kernel<<<NS, 32>>>(name_lens, off, name_tokens, rowtok);
    gather_split_kernel<<<NS * LS, 128>>>(wte, rowtok, total, gah, gal);
    launch_split_s(0, mha_in_w, wqkv_h, wqkv_l, (size_t)3 * DE * DE);
    launch_split_s(0, bott_w,   wbott_h, wbott_l, (size_t)HD * (XFD + DE));
    launch_split_s(0, x_feats,  xf_h, xf_l, (size_t)NS * XFD);
    transpose_split_kernel<<<dim3(DE / 32, DE / 32, 1), dim3(32, 8)>>>(
        mha_out_w, DE, DE, woutt_h, woutt_l, 0, 0);
    bias_fold_kernel<<<dim3(HD, 1), 128>>>(
        bott_w, XFD + DE, XFD, mha_out_b, nullptr, bao, DE, 0, 0, 0, 0);

    // ---- fork: encoder-weight prep on side stream ----
    if (use_side) {
        cudaEventRecord(evFork, 0);
        cudaStreamWaitEvent(side, evFork, 0);
    }
    launch_split_s(prepSt, enc_out_w, wo_h,  wo_l,  (size_t)NLAY * HD * HD);
    launch_split_s(prepSt, enc_ff1_w, wf1_h, wf1_l, (size_t)NLAY * 2 * HD * HD);
    launch_split_s(prepSt, enc_ff2_w, wf2_h, wf2_l, (size_t)NLAY * HD * 2 * HD);
    transpose_split_kernel<<<dim3(HD / 32, HD / 32, NLAY), dim3(32, 8), 0, prepSt>>>(
        enc_in_w + (size_t)2 * HD * HD, HD, HD, wvt_h, wvt_l,
        (size_t)3 * HD * HD, (size_t)HD * HD);
    bias_fold_kernel<<<dim3(HD, NLAY), 128, 0, prepSt>>>(
        enc_out_w, HD, 0, enc_in_b + 2 * HD, enc_out_b, bc, HD,
        (size_t)HD * HD, (size_t)3 * HD, (size_t)HD, (size_t)HD);
    k_pre<<<dim3(HD / 128, HD / 256, NLAY), 256, TG_SMEM, prepSt>>>(
        HD, HD, HD, 0,
        wo_h, wo_l, HD, nullptr, nullptr, 0, nullptr,
        wvt_h, wvt_l, HD, nullptr, nullptr, 0,
        zero, nullptr, nullptr,
        nullptr, wc_h, wc_l,
        (size_t)HD * HD, (size_t)HD * HD, (size_t)HD * HD, HD, HD, 0, nullptr);
    k_pre<<<dim3(DE / 128, HD / 256, 1), 256, TG_SMEM, prepSt>>>(
        HD, DE, DE, 0,
        wbott_h + XFD, wbott_l + XFD, XFD + DE, nullptr, nullptr, 0, nullptr,
        woutt_h, woutt_l, DE, nullptr, nullptr, 0,
        zero, nullptr, nullptr,
        nullptr, wao_h, wao_l, 0, 0, 0, DE, DE, 0, nullptr);
    if (use_side) cudaEventRecord(evJoin, side);

    const int MQ = NS * LS;
    const int KQ = DE;
    const int NQ = 2 * DE;       // Q,K only

    // 1. qk(compact) = gathered_emb @ [Wq;Wk]^T + bias
    k_qk<<<dim3(NQ / 128, MQ / 256, 1), 256, TG_SMEM>>>(
        MQ, NQ, KQ, 0,
        gah, gal, KQ, nullptr, nullptr, 0, total,
        wqkv_h, wqkv_l, KQ, nullptr, nullptr, 0,
        mha_in_b, nullptr, nullptr, qkv, nullptr, nullptr, 0, 0, 0, NQ, NQ, 0, nullptr);

    // 2. attention weights -> per-head mixed embeddings CE (one block per sample)
    name_attn_kernel<<<NS, 256, ATTN_SMEM>>>(qkv, off, gah, gal, ce_h, ce_l);

    // 2b. attnsum_h = CE_h @ Wv_h^T + len*bv_h
    k_csum<<<dim3(2, NS / 256, NHN), 256, TG_SMEM>>>(
        NS, DHN, DE, 0,
        ce_h, ce_l, NHN * DE, nullptr, nullptr, 0, nullptr,
        wqkv_h + (size_t)2 * DE * DE, wqkv_l + (size_t)2 * DE * DE, DE, nullptr, nullptr, 0,
        zero, mha_in_b + 2 * DE, name_lens,
        nullptr, attn_h, attn_l,
        (size_t)DE, (size_t)DHN * DE, (size_t)DHN,
        DE, DHN, (size_t)DHN, nullptr);

    // ---- join ----
    if (use_side) cudaStreamWaitEvent(0, evJoin, 0);

    // 3. x = xf@Wb1^T + attnsum@Wao^T + bbott + len*bao -> h fp32 + split
    k_bott<<<dim3(HD / 128, NS / 256, 1), 256, TG_SMEM>>>(
        NS, HD, XFD + DE, XFD,
        xf_h, xf_l, XFD, attn_h, attn_l, DE, nullptr,
        wbott_h, wbott_l, XFD + DE, wao_h, wao_l, DE,
        bott_b, bao, name_lens, h, hh, hl, 0, 0, 0, HD, HD, 0, nullptr);

    // 4. encoder layers (residual fused into GEMM epilogue; LN reads only ta)
    for (int l = 0; l < NLAY; l++) {
        k_resid<<<dim3(HD / 128, NS / 256, 1), 256, TG_SMEM>>>(
            NS, HD, HD, 0,
            hh, hl, HD, nullptr, nullptr, 0, nullptr,
            wc_h + (size_t)l * HD * HD, wc_l + (size_t)l * HD * HD, HD,
            nullptr, nullptr, 0,
            bc + (size_t)l * HD, nullptr, nullptr, ta, nullptr, nullptr, 0, 0, 0, HD, HD, 0, h);
        ln_kernel<true, false><<<NS, 256>>>(
            ta, enc_ln1_g + (size_t)l * HD, enc_ln1_b + (size_t)l * HD,
            h, hh, hl, nullptr, nullptr, nullptr);

        k_ff1<<<dim3(2 * HD / 128, NS / 256, 1), 256, TG_SMEM>>>(
            NS, 2 * HD, HD, 0,
            hh, hl, HD, nullptr, nullptr, 0, nullptr,
            wf1_h + (size_t)l * 2 * HD * HD, wf1_l + (size_t)l * 2 * HD * HD, HD,
            nullptr, nullptr, 0,
            enc_ff1_b + (size_t)l * 2 * HD, nullptr, nullptr, nullptr, t1_h, t1_l,
            0, 0, 0, 2 * HD, 2 * HD, 0, nullptr);
        k_resid<<<dim3(HD / 128, NS / 256, 1), 256, TG_SMEM>>>(
            NS, HD, 2 * HD, 0,
            t1_h, t1_l, 2 * HD, nullptr, nullptr, 0, nullptr,
            wf2_h + (size_t)l * HD * 2 * HD, wf2_l + (size_t)l * HD * 2 * HD, 2 * HD,
            nullptr, nullptr, 0,
            enc_ff2_b + (size_t)l * HD, nullptr, nullptr, ta, nullptr, nullptr, 0, 0, 0, HD, HD, 0, h);
        if (l < NLAY - 1) {
            ln_kernel<true, false><<<NS, 256>>>(
                ta, enc_ln2_g + (size_t)l * HD, enc_ln2_b + (size_t)l * HD,
                h, hh, hl, nullptr, nullptr, nullptr);
        } else {
            // final LN fused with classifier head -> out [4096 x 16]
            ln_kernel<false, true><<<NS, 256>>>(
                ta, enc_ln2_g + (size_t)l * HD, enc_ln2_b + (size_t)l * HD,
                nullptr, nullptr, nullptr, cls_w, cls_b, out);
        }
    }
}

// round 12
// speedup vs baseline: 1.0827x; 1.0827x over previous
#include <cuda_runtime.h>
#include <cuda_bf16.h>
#include <cstdint>
#include <math.h>

// ---------------- problem constants ----------------
#define NS    4096          // N samples
#define LS    16            // L tokens
#define DE    768           // D embedding
#define NHN   4             // heads (name attn)
#define DHN   192           // head dim (name attn)
#define HD    1024          // H
#define NLAY  4             // NL
#define NCLS  16            // C
#define XFD   256           // XF

// ---------------- scratch (device globals; no cudaMalloc allowed) ----------------
__device__ float g_qkv[(size_t)NS * LS * 2 * DE];   // compacted Q,K rows, fp32
__device__ float g_h[(size_t)NS * HD];              // fp32 residual stream
__device__ float g_ta[(size_t)NS * HD];             // fp32 (pre-LN sum)

__device__ int g_off[NS + 1];
__device__ int g_total[1];
__device__ int g_rowtok[NS * LS];

__device__ float g_zero[4096];
__device__ float g_bc[NLAY * HD];
__device__ float g_bao[HD];

// bf16 hi/lo split buffers (activations)
__device__ __align__(16) __nv_bfloat16 g_gah[(size_t)NS * LS * DE],   g_gal[(size_t)NS * LS * DE];
__device__ __align__(16) __nv_bfloat16 g_ce_h[(size_t)NS * NHN * DE], g_ce_l[(size_t)NS * NHN * DE];
__device__ __align__(16) __nv_bfloat16 g_attn_h[(size_t)NS * DE],     g_attn_l[(size_t)NS * DE];
__device__ __align__(16) __nv_bfloat16 g_xf_h[(size_t)NS * XFD],      g_xf_l[(size_t)NS * XFD];
__device__ __align__(16) __nv_bfloat16 g_hh[(size_t)NS * HD],         g_hl[(size_t)NS * HD];
__device__ __align__(16) __nv_bfloat16 g_t1_h[(size_t)NS * 2 * HD],   g_t1_l[(size_t)NS * 2 * HD];

// bf16 hi/lo split buffers (weights)
__device__ __align__(16) __nv_bfloat16 g_wqkv_h[(size_t)3 * DE * DE], g_wqkv_l[(size_t)3 * DE * DE];
__device__ __align__(16) __nv_bfloat16 g_wbott_h[(size_t)HD * (XFD + DE)], g_wbott_l[(size_t)HD * (XFD + DE)];
__device__ __align__(16) __nv_bfloat16 g_wo_h[(size_t)NLAY * HD * HD],  g_wo_l[(size_t)NLAY * HD * HD];
__device__ __align__(16) __nv_bfloat16 g_wf1_h[(size_t)NLAY * 2 * HD * HD], g_wf1_l[(size_t)NLAY * 2 * HD * HD];
__device__ __align__(16) __nv_bfloat16 g_wf2_h[(size_t)NLAY * HD * 2 * HD], g_wf2_l[(size_t)NLAY * HD * 2 * HD];
__device__ __align__(16) __nv_bfloat16 g_wvt_h[(size_t)NLAY * HD * HD],  g_wvt_l[(size_t)NLAY * HD * HD];
__device__ __align__(16) __nv_bfloat16 g_woutt_h[(size_t)DE * DE],       g_woutt_l[(size_t)DE * DE];
__device__ __align__(16) __nv_bfloat16 g_wc_h[(size_t)NLAY * HD * HD],   g_wc_l[(size_t)NLAY * HD * HD];
__device__ __align__(16) __nv_bfloat16 g_wao_h[(size_t)HD * DE],         g_wao_l[(size_t)HD * DE];

// ================= helpers =================
__device__ __forceinline__ uint32_t smem_u32(const void* p) {
    uint32_t a;
    asm("{ .reg .u64 t; cvta.to.shared.u64 t, %1; cvt.u32.u64 %0, t; }" : "=r"(a) : "l"(p));
    return a;
}
__device__ __forceinline__ uint32_t sw128(uint32_t o) { return o ^ ((o >> 3) & 0x70); }

#define LDSM4(r, addr) \
    asm volatile("ldmatrix.sync.aligned.m8n8.x4.shared.b16 {%0,%1,%2,%3}, [%4];" \
        : "=r"((r)[0]), "=r"((r)[1]), "=r"((r)[2]), "=r"((r)[3]) : "r"(addr))

__device__ __forceinline__ void mma16816(float* c, const uint32_t* a, uint32_t b0, uint32_t b1) {
    asm volatile("mma.sync.aligned.m16n8k16.row.col.f32.bf16.bf16.f32 "
        "{%0,%1,%2,%3},{%4,%5,%6,%7},{%8,%9},{%0,%1,%2,%3};"
        : "+f"(c[0]), "+f"(c[1]), "+f"(c[2]), "+f"(c[3])
        : "r"(a[0]), "r"(a[1]), "r"(a[2]), "r"(a[3]), "r"(b0), "r"(b1));
}

#define CP_ASYNC16(dst, src) \
    asm volatile("cp.async.cg.shared.global [%0], [%1], 16;" :: "r"(dst), "l"(src))
#define CP_COMMIT() asm volatile("cp.async.commit_group;" ::: "memory")
#define CP_WAIT(n)  asm volatile("cp.async.wait_group %0;" :: "n"(n) : "memory")

// split fp32 pair -> packed bf16 hi (p) and lo residual (q)
__device__ __forceinline__ void split2(float x, float y, uint32_t& p, uint32_t& q) {
    asm("cvt.rn.bf16x2.f32 %0, %1, %2;" : "=r"(p) : "f"(y), "f"(x));
    float h0 = __uint_as_float(p << 16);
    float h1 = __uint_as_float(p & 0xffff0000u);
    float r0 = x - h0, r1 = y - h1;
    asm("cvt.rn.bf16x2.f32 %0, %1, %2;" : "=r"(q) : "f"(r1), "f"(r0));
}

// ---------------- fp32 -> bf16 hi/lo split ----------------
__global__ __launch_bounds__(256) void split_kernel(
    const float* __restrict__ src,
    __nv_bfloat16* __restrict__ hi, __nv_bfloat16* __restrict__ lo, int n2)
{
    const int i = blockIdx.x * blockDim.x + threadIdx.x;
    if (i < n2) {
        const float2 v = reinterpret_cast<const float2*>(src)[i];
        uint32_t p, q;
        split2(v.x, v.y, p, q);
        reinterpret_cast<uint32_t*>(hi)[i] = p;
        reinterpret_cast<uint32_t*>(lo)[i] = q;
    }
}

// ---------------- batched fp32 [R x C] -> transposed bf16 hi/lo [C x R] ----------------
__global__ __launch_bounds__(256) void transpose_split_kernel(
    const float* __restrict__ src, int ld, int R,
    __nv_bfloat16* __restrict__ dh, __nv_bfloat16* __restrict__ dl,
    size_t srcStride, size_t dstStride)
{
    __shared__ float tile[32][33];
    const int z = blockIdx.z;
    src += (size_t)z * srcStride;
    dh  += (size_t)z * dstStride;
    dl  += (size_t)z * dstStride;
    const int c0 = blockIdx.x * 32, r0 = blockIdx.y * 32;
    const int tx = threadIdx.x, ty = threadIdx.y;   // (32, 8)
#pragma unroll
    for (int i = ty; i < 32; i += 8)
        tile[i][tx] = src[(size_t)(r0 + i) * ld + c0 + tx];
    __syncthreads();
    if (tx < 16) {
#pragma unroll
        for (int i = ty; i < 32; i += 8) {
            uint32_t p, q;
            split2(tile[2 * tx][i], tile[2 * tx + 1][i], p, q);
            const size_t id2 = ((size_t)(c0 + i) * R + r0) / 2 + tx;
            reinterpret_cast<uint32_t*>(dh)[id2] = p;
            reinterpret_cast<uint32_t*>(dl)[id2] = q;
        }
    }
}

// ---------------- batched bias fold: out[row] = W[row,:]·v + base[row] ----------------
__global__ __launch_bounds__(128) void bias_fold_kernel(
    const float* __restrict__ W, int ldw, int coff,
    const float* __restrict__ v, const float* __restrict__ base,
    float* __restrict__ out, int K,
    size_t wStride, size_t vStride, size_t baseStride, size_t outStride)
{
    __shared__ float red[4];
    const int z = blockIdx.y;
    W += (size_t)z * wStride;
    v += (size_t)z * vStride;
    if (base) base += (size_t)z * baseStride;
    out += (size_t)z * outStride;
    const int row = blockIdx.x;
    const int t = threadIdx.x, lane = t & 31, warp = t >> 5;
    const float* wr = W + (size_t)row * ldw + coff;
    float s = 0.f;
    for (int k = t; k < K; k += 128) s += wr[k] * v[k];
#pragma unroll
    for (int o = 16; o; o >>= 1) s += __shfl_down_sync(0xffffffffu, s, o);
    if (lane == 0) red[warp] = s;
    __syncthreads();
    if (t == 0) out[row] = red[0] + red[1] + red[2] + red[3] + (base ? base[row] : 0.f);
}

// ---------------- compaction scan ----------------
__global__ __launch_bounds__(1024) void scan_kernel(
    const int* __restrict__ lens, int* __restrict__ off, int* __restrict__ total)
{
    __shared__ int wsum[32];
    const int tid = threadIdx.x, lane = tid & 31, warp = tid >> 5;
    int v[4], s = 0;
#pragma unroll
    for (int i = 0; i < 4; i++) { v[i] = lens[tid * 4 + i]; s += v[i]; }
    int ws = s;
#pragma unroll
    for (int o = 1; o < 32; o <<= 1) { int t = __shfl_up_sync(0xffffffffu, ws, o); if (lane >= o) ws += t; }
    if (lane == 31) wsum[warp] = ws;
    __syncthreads();
    if (warp == 0) {
        int t = wsum[lane];
#pragma unroll
        for (int o = 1; o < 32; o <<= 1) { int u = __shfl_up_sync(0xffffffffu, t, o); if (lane >= o) t += u; }
        wsum[lane] = t;
    }
    __syncthreads();
    int run = ws - s + (warp ? wsum[warp - 1] : 0);
#pragma unroll
    for (int i = 0; i < 4; i++) { off[tid * 4 + i] = run; run += v[i]; }
    if (tid == 1023) { off[NS] = run; total[0] = run; }
}

__global__ __launch_bounds__(32) void fill_rows_kernel(
    const int* __restrict__ lens, const int* __restrict__ off,
    const int* __restrict__ toks, int* __restrict__ rowtok)
{
    const int b = blockIdx.x;
    const int len = lens[b], o = off[b];
    for (int s = threadIdx.x; s < len; s += 32) rowtok[o + s] = toks[b * LS + s];
}

__global__ __launch_bounds__(128) void gather_split_kernel(
    const float* __restrict__ wte, const int* __restrict__ rowtok,
    const int* __restrict__ total,
    __nv_bfloat16* __restrict__ Ah, __nv_bfloat16* __restrict__ Al)
{
    const int r = blockIdx.x;
    if (r >= total[0]) return;
    const float2* src = reinterpret_cast<const float2*>(wte + (size_t)rowtok[r] * DE);
    uint32_t* dh = reinterpret_cast<uint32_t*>(Ah) + (size_t)r * (DE / 2);
    uint32_t* dl = reinterpret_cast<uint32_t*>(Al) + (size_t)r * (DE / 2);
#pragma unroll
    for (int i = 0; i < 3; i++) {
        const int j = threadIdx.x + 128 * i;
        const float2 v = src[j];
        uint32_t p, q;
        split2(v.x, v.y, p, q);
        dh[j] = p; dl[j] = q;
    }
}

// ================= HMMA GEMM: C[M,N] = A[M,K] @ B[N,K]^T + bias (+rs*bias2) (+RES) =================
#define CHUNK  64
#define STG_BYTES (96 * 1024)
#define OFF_AH 0
#define OFF_AL 32768
#define OFF_BH 65536
#define OFF_BL 81920
#define TG_SMEM  (2 * STG_BYTES + 256)

template<int AMODE, int BMODE, bool RELU, bool WF32, bool WSPLIT, bool MDYN, bool HASB2, bool NDYN, bool RESID>
__global__ __launch_bounds__(256, 1) void tgemm_kernel(
    int M, int N, int K, int K1,
    const __nv_bfloat16* __restrict__ Ah, const __nv_bfloat16* __restrict__ Al, int lda,
    const __nv_bfloat16* __restrict__ A2h, const __nv_bfloat16* __restrict__ A2l, int lda2,
    const int* __restrict__ Mlim,
    const __nv_bfloat16* __restrict__ Bh, const __nv_bfloat16* __restrict__ Bl, int ldb,
    const __nv_bfloat16* __restrict__ B2h, const __nv_bfloat16* __restrict__ B2l, int ldb2,
    const float* __restrict__ bias, const float* __restrict__ bias2,
    const int* __restrict__ rowscale,
    float* __restrict__ C,
    __nv_bfloat16* __restrict__ Ch, __nv_bfloat16* __restrict__ Cl,
    size_t strideA, size_t strideB, size_t strideC,
    int ldc, int Nlim, size_t strideB2,
    const float* __restrict__ RES)
{
    extern __shared__ char smem[];
    const uint32_t sb = smem_u32(smem);

    const int z = blockIdx.z;
    if (strideA) { Ah += (size_t)z * strideA; Al += (size_t)z * strideA; }
    if (strideB) { Bh += (size_t)z * strideB; Bl += (size_t)z * strideB; }
    if (strideC) { Ch += (size_t)z * strideC; Cl += (size_t)z * strideC; }
    if (HASB2 && strideB2) bias2 += (size_t)z * strideB2;

    const int tid  = threadIdx.x;
    const int lane = tid & 31;
    const int wid  = tid >> 5;
    const int bm = blockIdx.y * 256, bn = blockIdx.x * 128;

    int Mtot = M;
    if (MDYN) {
        Mtot = Mlim[0];
        if (bm >= Mtot) return;
    }

    const int nch = K / CHUNK;

    auto issue_stage = [&](int c) {
        const int k0 = c * CHUNK;
        const uint32_t st = sb + (c & 1) * STG_BYTES;
#pragma unroll
        for (int i = 0; i < 8; i++) {
            const int idx = tid + 256 * i;
            const int row = idx >> 3;
            const int seg = idx & 7;
            const uint32_t sw = sw128(row * 128 + seg * 16);
            int ar = bm + row;
            if (MDYN && ar >= Mtot) ar = Mtot - 1;
            const __nv_bfloat16 *pah, *pal;
            if (AMODE == 2 && k0 >= K1) {
                const size_t off = (size_t)ar * lda2 + (k0 - K1) + seg * 8;
                pah = A2h + off; pal = A2l + off;
            } else {
                const size_t off = (size_t)ar * lda + k0 + seg * 8;
                pah = Ah + off; pal = Al + off;
            }
            CP_ASYNC16(st + OFF_AH + sw, pah);
            CP_ASYNC16(st + OFF_AL + sw, pal);
        }
#pragma unroll
        for (int i = 0; i < 4; i++) {
            const int idx = tid + 256 * i;
            const int row = idx >> 3;
            const int seg = idx & 7;
            const uint32_t sw = sw128(row * 128 + seg * 16);
            int br = bn + row;
            if (NDYN && br >= Nlim) br = Nlim - 1;
            const __nv_bfloat16 *pbh, *pbl;
            if (BMODE == 2 && k0 >= K1) {
                const size_t off = (size_t)br * ldb2 + (k0 - K1) + seg * 8;
                pbh = B2h + off; pbl = B2l + off;
            } else {
                const size_t off = (size_t)br * ldb + k0 + seg * 8;
                pbh = Bh + off; pbl = Bl + off;
            }
            CP_ASYNC16(st + OFF_BH + sw, pbh);
            CP_ASYNC16(st + OFF_BL + sw, pbl);
        }
        CP_COMMIT();
    };

    issue_stage(0);

    const int wm = (wid >> 1) * 64;
    const int wn = (wid & 1) * 64;

    float acc[4][8][4];
#pragma unroll
    for (int i = 0; i < 4; i++)
#pragma unroll
        for (int j = 0; j < 8; j++)
#pragma unroll
            for (int t = 0; t < 4; t++) acc[i][j][t] = 0.f;

    const int a_row  = (lane & 15);
    const int a_kb   = (lane >> 4) * 16;
    const int b_row  = (lane & 7) + ((lane >> 4) << 3);
    const int b_kb   = ((lane >> 3) & 1) * 16;

    for (int c = 0; c < nch; c++) {
        CP_WAIT(0);
        __syncthreads();
        if (c + 1 < nch) issue_stage(c + 1);

        const uint32_t st = sb + (c & 1) * STG_BYTES;

#pragma unroll
        for (int ks = 0; ks < 4; ks++) {
            const int kb = ks * 32;
            uint32_t ah[4][4], al[4][4];
#pragma unroll
            for (int i = 0; i < 4; i++) {
                const uint32_t oa = sw128((wm + i * 16 + a_row) * 128 + kb + a_kb);
                LDSM4(ah[i], st + OFF_AH + oa);
                LDSM4(al[i], st + OFF_AL + oa);
            }
            uint32_t bf[4][4];
#pragma unroll
            for (int j2 = 0; j2 < 4; j2++) {
                const uint32_t ob = sw128((wn + j2 * 16 + b_row) * 128 + kb + b_kb);
                LDSM4(bf[j2], st + OFF_BH + ob);
            }
#pragma unroll
            for (int i = 0; i < 4; i++)
#pragma unroll
                for (int j2 = 0; j2 < 4; j2++) {
                    mma16816(acc[i][2 * j2 + 0], ah[i], bf[j2][0], bf[j2][1]);
                    mma16816(acc[i][2 * j2 + 1], ah[i], bf[j2][2], bf[j2][3]);
                    mma16816(acc[i][2 * j2 + 0], al[i], bf[j2][0], bf[j2][1]);
                    mma16816(acc[i][2 * j2 + 1], al[i], bf[j2][2], bf[j2][3]);
                }
#pragma unroll
            for (int j2 = 0; j2 < 4; j2++) {
                const uint32_t ob = sw128((wn + j2 * 16 + b_row) * 128 + kb + b_kb);
                LDSM4(bf[j2], st + OFF_BL + ob);
            }
#pragma unroll
            for (int i = 0; i < 4; i++)
#pragma unroll
                for (int j2 = 0; j2 < 4; j2++) {
                    mma16816(acc[i][2 * j2 + 0], ah[i], bf[j2][0], bf[j2][1]);
                    mma16816(acc[i][2 * j2 + 1], ah[i], bf[j2][2], bf[j2][3]);
                }
        }
    }

    // ---- epilogue ----
#pragma unroll
    for (int i = 0; i < 4; i++) {
        const int r0 = bm + wm + i * 16 + (lane >> 2);
        const int r1 = r0 + 8;
        const bool ok0 = !MDYN || (r0 < Mtot);
        const bool ok1 = !MDYN || (r1 < Mtot);
        const float rs0 = HASB2 ? (float)rowscale[r0] : 0.f;
        const float rs1 = HASB2 ? (float)rowscale[r1] : 0.f;
#pragma unroll
        for (int j = 0; j < 8; j++) {
            const int col = bn + wn + j * 8 + (lane & 3) * 2;
            const bool okc = !NDYN || (col < Nlim);
            float b00 = bias[col], b01 = bias[col + 1];
            float b10 = b00, b11 = b01;
            if (HASB2) {
                b00 += rs0 * bias2[col]; b01 += rs0 * bias2[col + 1];
                b10 += rs1 * bias2[col]; b11 += rs1 * bias2[col + 1];
            }
            float2 v0 = make_float2(acc[i][j][0] + b00, acc[i][j][1] + b01);
            float2 v1 = make_float2(acc[i][j][2] + b10, acc[i][j][3] + b11);
            if (RESID) {
                const float2 h0 = *reinterpret_cast<const float2*>(RES + (size_t)r0 * ldc + col);
                const float2 h1 = *reinterpret_cast<const float2*>(RES + (size_t)r1 * ldc + col);
                v0.x += h0.x; v0.y += h0.y;
                v1.x += h1.x; v1.y += h1.y;
            }
            if (RELU) {
                v0.x = fmaxf(v0.x, 0.f); v0.y = fmaxf(v0.y, 0.f);
                v1.x = fmaxf(v1.x, 0.f); v1.y = fmaxf(v1.y, 0.f);
            }
            if (WF32) {
                if (ok0 && okc) *reinterpret_cast<float2*>(C + (size_t)r0 * ldc + col) = v0;
                if (ok1 && okc) *reinterpret_cast<float2*>(C + (size_t)r1 * ldc + col) = v1;
            }
            if (WSPLIT) {
                uint32_t p, q;
                if (ok0 && okc) {
                    split2(v0.x, v0.y, p, q);
                    reinterpret_cast<uint32_t*>(Ch)[((size_t)r0 * ldc + col) >> 1] = p;
                    reinterpret_cast<uint32_t*>(Cl)[((size_t)r0 * ldc + col) >> 1] = q;
                }
                if (ok1 && okc) {
                    split2(v1.x, v1.y, p, q);
                    reinterpret_cast<uint32_t*>(Ch)[((size_t)r1 * ldc + col) >> 1] = p;
                    reinterpret_cast<uint32_t*>(Cl)[((size_t)r1 * ldc + col) >> 1] = q;
                }
            }
        }
    }
}

// ---------------- name attention (R10 version): block per (head, sample); emits CE ----------------
__global__ __launch_bounds__(192) void name_attn_kernel(
    const float* __restrict__ qk, const int* __restrict__ off,
    const __nv_bfloat16* __restrict__ eh, const __nv_bfloat16* __restrict__ el,
    __nv_bfloat16* __restrict__ CEh, __nv_bfloat16* __restrict__ CEl)
{
    __shared__ float Qs[LS][DHN];
    __shared__ float Ks[LS][DHN];
    __shared__ float sc[LS][LS + 1];
    __shared__ float cw[LS];

    const int h = blockIdx.x;
    const int b = blockIdx.y;
    const int d = threadIdx.x;

    const int o   = off[b];
    const int len = off[b + 1] - o;

    const float* base = qk + (size_t)o * (2 * DE) + h * DHN + d;
    for (int s = 0; s < len; s++) {
        Qs[s][d] = base[s * (2 * DE)];
        Ks[s][d] = base[s * (2 * DE) + DE];
    }
    if (d < LS) cw[d] = 0.f;
    __syncthreads();

    const int warp = d >> 5, lane = d & 31;
    const float scale = 1.0f / sqrtf((float)DHN);
    const int np = len * len;
    for (int p = warp; p < np; p += 6) {
        const int q = p / len, j = p - q * len;
        float s = 0.f;
#pragma unroll
        for (int i = 0; i < 6; i++) s += Qs[q][lane + 32 * i] * Ks[j][lane + 32 * i];
#pragma unroll
        for (int ofs = 16; ofs; ofs >>= 1) s += __shfl_down_sync(0xffffffffu, s, ofs);
        if (lane == 0) sc[q][j] = s * scale;
    }
    __syncthreads();

    if (d < len) {
        float mx = -1e30f;
        for (int j = 0; j < len; j++) mx = fmaxf(mx, sc[d][j]);
        float sum = 0.f;
        float row[LS];
        for (int j = 0; j < len; j++) { row[j] = expf(sc[d][j] - mx); sum += row[j]; }
        const float inv = 1.f / sum;
        for (int j = 0; j < len; j++) sc[d][j] = row[j] * inv;
    }
    __syncthreads();

    if (d < len) {
        float c = 0.f;
        for (int s = 0; s < len; s++) c += sc[s][d];
        cw[d] = c;
    }
    __syncthreads();

    const uint32_t* ehp = reinterpret_cast<const uint32_t*>(eh);
    const uint32_t* elp = reinterpret_cast<const uint32_t*>(el);
    for (int p = d; p < DE / 2; p += 192) {
        float ce0 = 0.f, ce1 = 0.f;
        for (int j = 0; j < len; j++) {
            const size_t idx = (size_t)(o + j) * (DE / 2) + p;
            const uint32_t uh = ehp[idx], ul = elp[idx];
            const float e0 = __uint_as_float(uh << 16) + __uint_as_float(ul << 16);
            const float e1 = __uint_as_float(uh & 0xffff0000u) + __uint_as_float(ul & 0xffff0000u);
            ce0 += cw[j] * e0;
            ce1 += cw[j] * e1;
        }
        uint32_t P, Q;
        split2(ce0, ce1, P, Q);
        const size_t id2 = (size_t)b * (NHN * DE / 2) + h * (DE / 2) + p;
        reinterpret_cast<uint32_t*>(CEh)[id2] = P;
        reinterpret_cast<uint32_t*>(CEl)[id2] = Q;
    }
}

// ---------------- LayerNorm of ta (residual already added in GEMM epilogue) ----------------
__device__ __forceinline__ float block_reduce_sum(float v) {
    __shared__ float red[8];
    const int lane = threadIdx.x & 31, warp = threadIdx.x >> 5;
#pragma unroll
    for (int o = 16; o; o >>= 1) v += __shfl_down_sync(0xffffffffu, v, o);
    if (lane == 0) red[warp] = v;
    __syncthreads();
    v = (threadIdx.x < 8) ? red[threadIdx.x] : 0.f;
    if (warp == 0)
#pragma unroll
        for (int o = 4; o; o >>= 1) v += __shfl_down_sync(0xffffffffu, v, o);
    return v;
}

template<bool WRITEH, bool DOCLS>
__global__ __launch_bounds__(256) void ln_kernel(
    const float* __restrict__ ta,
    const float* __restrict__ g, const float* __restrict__ b,
    float* __restrict__ h,
    __nv_bfloat16* __restrict__ hh, __nv_bfloat16* __restrict__ hl,
    const float* __restrict__ clsw, const float* __restrict__ clsb,
    float* __restrict__ out)
{
    const int row = blockIdx.x;
    const int t = threadIdx.x;
    float v[4];
    float s = 0.f;
#pragma unroll
    for (int i = 0; i < 4; i++) {
        const int c = t + 256 * i;
        v[i] = ta[(size_t)row * HD + c];
        s += v[i];
    }
    s = block_reduce_sum(s);
    __shared__ float mean_s, rstd_s;
    if (t == 0) mean_s = s * (1.f / HD);
    __syncthreads();
    const float m = mean_s;
    float s2 = 0.f;
#pragma unroll
    for (int i = 0; i < 4; i++) { const float dd = v[i] - m; s2 += dd * dd; }
    s2 = block_reduce_sum(s2);
    if (t == 0) rstd_s = rsqrtf(s2 * (1.f / HD) + 1e-5f);
    __syncthreads();
    const float r = rstd_s;

    __shared__ float ys[HD];
#pragma unroll
    for (int i = 0; i < 4; i++) {
        const int c = t + 256 * i;
        const float y = (v[i] - m) * r * g[c] + b[c];
        if (WRITEH) {
            h[(size_t)row * HD + c] = y;
            const float y1 = __shfl_down_sync(0xffffffffu, y, 1);
            if (!(t & 1)) {
                uint32_t p, q;
                split2(y, y1, p, q);
                const size_t id2 = ((size_t)row * HD + c) >> 1;
                reinterpret_cast<uint32_t*>(hh)[id2] = p;
                reinterpret_cast<uint32_t*>(hl)[id2] = q;
            }
        }
        if (DOCLS) ys[c] = y;
    }
    if (DOCLS) {
        __syncthreads();
        const int warp = t >> 5, lane = t & 31;
        for (int cc = warp; cc < NCLS; cc += 8) {
            const float* wr = clsw + (size_t)cc * HD;
            float sum = 0.f;
#pragma unroll
            for (int i = lane; i < HD; i += 32) sum += ys[i] * wr[i];
#pragma unroll
            for (int o = 16; o; o >>= 1) sum += __shfl_down_sync(0xffffffffu, sum, o);
            if (lane == 0) out[(size_t)row * NCLS + cc] = sum + clsb[cc];
        }
    }
}

// ---------------- orchestration ----------------
static inline void launch_split_s(cudaStream_t st, const float* src,
                                  __nv_bfloat16* hi, __nv_bfloat16* lo, size_t n) {
    const int n2 = (int)(n / 2);
    split_kernel<<<(n2 + 255) / 256, 256, 0, st>>>(src, hi, lo, n2);
}

extern "C" void kernel_launch(void* const* d_in, const int* in_sizes, int n_in,
                              void* d_out, int out_size)
{
    const int*   name_tokens = (const int*)d_in[0];
    const int*   name_lens   = (const int*)d_in[1];
    const float* x_feats     = (const float*)d_in[2];
    const float* wte         = (const float*)d_in[3];
    const float* mha_in_w    = (const float*)d_in[4];
    const float* mha_in_b    = (const float*)d_in[5];
    const float* mha_out_w   = (const float*)d_in[6];
    const float* mha_out_b   = (const float*)d_in[7];
    const float* bott_w      = (const float*)d_in[8];
    const float* bott_b      = (const float*)d_in[9];
    const float* enc_in_w    = (const float*)d_in[10];
    const float* enc_in_b    = (const float*)d_in[11];
    const float* enc_out_w   = (const float*)d_in[12];
    const float* enc_out_b   = (const float*)d_in[13];
    const float* enc_ln1_g   = (const float*)d_in[14];
    const float* enc_ln1_b   = (const float*)d_in[15];
    const float* enc_ln2_g   = (const float*)d_in[16];
    const float* enc_ln2_b   = (const float*)d_in[17];
    const float* enc_ff1_w   = (const float*)d_in[18];
    const float* enc_ff1_b   = (const float*)d_in[19];
    const float* enc_ff2_w   = (const float*)d_in[20];
    const float* enc_ff2_b   = (const float*)d_in[21];
    const float* cls_w       = (const float*)d_in[22];
    const float* cls_b       = (const float*)d_in[23];
    float* out = (float*)d_out;

    float *qkv, *h, *ta, *zero, *bc, *bao;
    int *off, *total, *rowtok;
    cudaGetSymbolAddress((void**)&qkv,    g_qkv);
    cudaGetSymbolAddress((void**)&h,      g_h);
    cudaGetSymbolAddress((void**)&ta,     g_ta);
    cudaGetSymbolAddress((void**)&zero,   g_zero);
    cudaGetSymbolAddress((void**)&bc,     g_bc);
    cudaGetSymbolAddress((void**)&bao,    g_bao);
    cudaGetSymbolAddress((void**)&off,    g_off);
    cudaGetSymbolAddress((void**)&total,  g_total);
    cudaGetSymbolAddress((void**)&rowtok, g_rowtok);

    __nv_bfloat16 *gah, *gal, *ce_h, *ce_l, *attn_h, *attn_l, *xf_h, *xf_l, *hh, *hl, *t1_h, *t1_l;
    __nv_bfloat16 *wqkv_h, *wqkv_l, *wbott_h, *wbott_l, *wo_h, *wo_l, *wf1_h, *wf1_l, *wf2_h, *wf2_l;
    __nv_bfloat16 *wvt_h, *wvt_l, *woutt_h, *woutt_l, *wc_h, *wc_l, *wao_h, *wao_l;
    cudaGetSymbolAddress((void**)&gah,    g_gah);     cudaGetSymbolAddress((void**)&gal,    g_gal);
    cudaGetSymbolAddress((void**)&ce_h,   g_ce_h);    cudaGetSymbolAddress((void**)&ce_l,   g_ce_l);
    cudaGetSymbolAddress((void**)&attn_h, g_attn_h);  cudaGetSymbolAddress((void**)&attn_l, g_attn_l);
    cudaGetSymbolAddress((void**)&xf_h,   g_xf_h);    cudaGetSymbolAddress((void**)&xf_l,   g_xf_l);
    cudaGetSymbolAddress((void**)&hh,     g_hh);      cudaGetSymbolAddress((void**)&hl,     g_hl);
    cudaGetSymbolAddress((void**)&t1_h,   g_t1_h);    cudaGetSymbolAddress((void**)&t1_l,   g_t1_l);
    cudaGetSymbolAddress((void**)&wqkv_h, g_wqkv_h);  cudaGetSymbolAddress((void**)&wqkv_l, g_wqkv_l);
    cudaGetSymbolAddress((void**)&wbott_h,g_wbott_h); cudaGetSymbolAddress((void**)&wbott_l,g_wbott_l);
    cudaGetSymbolAddress((void**)&wo_h,   g_wo_h);    cudaGetSymbolAddress((void**)&wo_l,   g_wo_l);
    cudaGetSymbolAddress((void**)&wf1_h,  g_wf1_h);   cudaGetSymbolAddress((void**)&wf1_l,  g_wf1_l);
    cudaGetSymbolAddress((void**)&wf2_h,  g_wf2_h);   cudaGetSymbolAddress((void**)&wf2_l,  g_wf2_l);
    cudaGetSymbolAddress((void**)&wvt_h,  g_wvt_h);   cudaGetSymbolAddress((void**)&wvt_l,  g_wvt_l);
    cudaGetSymbolAddress((void**)&woutt_h,g_woutt_h); cudaGetSymbolAddress((void**)&woutt_l,g_woutt_l);
    cudaGetSymbolAddress((void**)&wc_h,   g_wc_h);    cudaGetSymbolAddress((void**)&wc_l,   g_wc_l);
    cudaGetSymbolAddress((void**)&wao_h,  g_wao_h);   cudaGetSymbolAddress((void**)&wao_l,  g_wao_l);

    auto k_qk    = tgemm_kernel<0, 0, false, true,  false, true,  false, false, false>;
    auto k_csum  = tgemm_kernel<0, 0, false, false, true,  false, true,  true,  false>;
    auto k_bott  = tgemm_kernel<2, 2, false, true,  true,  false, true,  false, false>;
    auto k_resid = tgemm_kernel<0, 0, false, true,  false, false, false, false, true >;
    auto k_ff1   = tgemm_kernel<0, 0, true,  false, true,  false, false, false, false>;
    auto k_pre   = tgemm_kernel<0, 0, false, false, true,  false, false, false, false>;
    cudaFuncSetAttribute(k_qk,    cudaFuncAttributeMaxDynamicSharedMemorySize, TG_SMEM);
    cudaFuncSetAttribute(k_csum,  cudaFuncAttributeMaxDynamicSharedMemorySize, TG_SMEM);
    cudaFuncSetAttribute(k_bott,  cudaFuncAttributeMaxDynamicSharedMemorySize, TG_SMEM);
    cudaFuncSetAttribute(k_resid, cudaFuncAttributeMaxDynamicSharedMemorySize, TG_SMEM);
    cudaFuncSetAttribute(k_ff1,   cudaFuncAttributeMaxDynamicSharedMemorySize, TG_SMEM);
    cudaFuncSetAttribute(k_pre,   cudaFuncAttributeMaxDynamicSharedMemorySize, TG_SMEM);

    cudaStream_t side = 0;
    cudaEvent_t evFork = 0, evJoin = 0;
    bool use_side = (cudaStreamCreateWithFlags(&side, cudaStreamNonBlocking) == cudaSuccess)
                 && (cudaEventCreateWithFlags(&evFork, cudaEventDisableTiming) == cudaSuccess)
                 && (cudaEventCreateWithFlags(&evJoin, cudaEventDisableTiming) == cudaSuccess);
    cudaStream_t prepSt = use_side ? side : (cudaStream_t)0;

    // ---- main-path prep ----
    scan_kernel<<<1, 1024>>>(name_lens, off, total);
    fill_rows_kernel<<<NS, 32>>>(name_lens, off, name_tokens, rowtok);
    gather_split_kernel<<<NS * LS, 128>>>(wte, rowtok, total, gah, gal);
    launch_split_s(0, mha_in_w, wqkv_h, wqkv_l, (size_t)3 * DE * DE);
    launch_split_s(0, bott_w,   wbott_h, wbott_l, (size_t)HD * (XFD + DE));
    launch_split_s(0, x_feats,  xf_h, xf_l, (size_t)NS * XFD);
    transpose_split_kernel<<<dim3(DE / 32, DE / 32, 1), dim3(32, 8)>>>(
        mha_out_w, DE, DE, woutt_h, woutt_l, 0, 0);
    bias_fold_kernel<<<dim3(HD, 1), 128>>>(
        bott_w, XFD + DE, XFD, mha_out_b, nullptr, bao, DE, 0, 0, 0, 0);

    // ---- fork: encoder-weight prep on side stream ----
    if (use_side) {
        cudaEventRecord(evFork, 0);
        cudaStreamWaitEvent(side, evFork, 0);
    }
    launch_split_s(prepSt, enc_out_w, wo_h,  wo_l,  (size_t)NLAY * HD * HD);
    launch_split_s(prepSt, enc_ff1_w, wf1_h, wf1_l, (size_t)NLAY * 2 * HD * HD);
    launch_split_s(prepSt, enc_ff2_w, wf2_h, wf2_l, (size_t)NLAY * HD * 2 * HD);
    transpose_split_kernel<<<dim3(HD / 32, HD / 32, NLAY), dim3(32, 8), 0, prepSt>>>(
        enc_in_w + (size_t)2 * HD * HD, HD, HD, wvt_h, wvt_l,
        (size_t)3 * HD * HD, (size_t)HD * HD);
    bias_fold_kernel<<<dim3(HD, NLAY), 128, 0, prepSt>>>(
        enc_out_w, HD, 0, enc_in_b + 2 * HD, enc_out_b, bc, HD,
        (size_t)HD * HD, (size_t)3 * HD, (size_t)HD, (size_t)HD);
    k_pre<<<dim3(HD / 128, HD / 256, NLAY), 256, TG_SMEM, prepSt>>>(
        HD, HD, HD, 0,
        wo_h, wo_l, HD, nullptr, nullptr, 0, nullptr,
        wvt_h, wvt_l, HD, nullptr, nullptr, 0,
        zero, nullptr, nullptr,
        nullptr, wc_h, wc_l,
        (size_t)HD * HD, (size_t)HD * HD, (size_t)HD * HD, HD, HD, 0, nullptr);
    k_pre<<<dim3(DE / 128, HD / 256, 1), 256, TG_SMEM, prepSt>>>(
        HD, DE, DE, 0,
        wbott_h + XFD, wbott_l + XFD, XFD + DE, nullptr, nullptr, 0, nullptr,
        woutt_h, woutt_l, DE, nullptr, nullptr, 0,
        zero, nullptr, nullptr,
        nullptr, wao_h, wao_l, 0, 0, 0, DE, DE, 0, nullptr);
    if (use_side) cudaEventRecord(evJoin, side);

    const int MQ = NS * LS;
    const int KQ = DE;
    const int NQ = 2 * DE;       // Q,K only

    // 1. qk(compact) = gathered_emb @ [Wq;Wk]^T + bias
    k_qk<<<dim3(NQ / 128, MQ / 256, 1), 256, TG_SMEM>>>(
        MQ, NQ, KQ, 0,
        gah, gal, KQ, nullptr, nullptr, 0, total,
        wqkv_h, wqkv_l, KQ, nullptr, nullptr, 0,
        mha_in_b, nullptr, nullptr, qkv, nullptr, nullptr, 0, 0, 0, NQ, NQ, 0, nullptr);

    // 2. attention weights -> per-head mixed embeddings CE [4096 x 4 x 768]
    name_attn_kernel<<<dim3(NHN, NS), 192>>>(qkv, off, gah, gal, ce_h, ce_l);

    // 2b. attnsum_h = CE_h @ Wv_h^T + len*bv_h
    k_csum<<<dim3(2, NS / 256, NHN), 256, TG_SMEM>>>(
        NS, DHN, DE, 0,
        ce_h, ce_l, NHN * DE, nullptr, nullptr, 0, nullptr,
        wqkv_h + (size_t)2 * DE * DE, wqkv_l + (size_t)2 * DE * DE, DE, nullptr, nullptr, 0,
        zero, mha_in_b + 2 * DE, name_lens,
        nullptr, attn_h, attn_l,
        (size_t)DE, (size_t)DHN * DE, (size_t)DHN,
        DE, DHN, (size_t)DHN, nullptr);

    // ---- join ----
    if (use_side) cudaStreamWaitEvent(0, evJoin, 0);

    // 3. x = xf@Wb1^T + attnsum@Wao^T + bbott + len*bao -> h fp32 + split
    k_bott<<<dim3(HD / 128, NS / 256, 1), 256, TG_SMEM>>>(
        NS, HD, XFD + DE, XFD,
        xf_h, xf_l, XFD, attn_h, attn_l, DE, nullptr,
        wbott_h, wbott_l, XFD + DE, wao_h, wao_l, DE,
        bott_b, bao, name_lens, h, hh, hl, 0, 0, 0, HD, HD, 0, nullptr);

    // 4. encoder layers (residual fused into GEMM epilogue; LN reads only ta)
    for (int l = 0; l < NLAY; l++) {
        k_resid<<<dim3(HD / 128, NS / 256, 1), 256, TG_SMEM>>>(
            NS, HD, HD, 0,
            hh, hl, HD, nullptr, nullptr, 0, nullptr,
            wc_h + (size_t)l * HD * HD, wc_l + (size_t)l * HD * HD, HD,
            nullptr, nullptr, 0,
            bc + (size_t)l * HD, nullptr, nullptr, ta, nullptr, nullptr, 0, 0, 0, HD, HD, 0, h);
        ln_kernel<true, false><<<NS, 256>>>(
            ta, enc_ln1_g + (size_t)l * HD, enc_ln1_b + (size_t)l * HD,
            h, hh, hl, nullptr, nullptr, nullptr);

        k_ff1<<<dim3(2 * HD / 128, NS / 256, 1), 256, TG_SMEM>>>(
            NS, 2 * HD, HD, 0,
            hh, hl, HD, nullptr, nullptr, 0, nullptr,
            wf1_h + (size_t)l * 2 * HD * HD, wf1_l + (size_t)l * 2 * HD * HD, HD,
            nullptr, nullptr, 0,
            enc_ff1_b + (size_t)l * 2 * HD, nullptr, nullptr, nullptr, t1_h, t1_l,
            0, 0, 0, 2 * HD, 2 * HD, 0, nullptr);
        k_resid<<<dim3(HD / 128, NS / 256, 1), 256, TG_SMEM>>>(
            NS, HD, 2 * HD, 0,
            t1_h, t1_l, 2 * HD, nullptr, nullptr, 0, nullptr,
            wf2_h + (size_t)l * HD * 2 * HD, wf2_l + (size_t)l * HD * 2 * HD, 2 * HD,
            nullptr, nullptr, 0,
            enc_ff2_b + (size_t)l * HD, nullptr, nullptr, ta, nullptr, nullptr, 0, 0, 0, HD, HD, 0, h);
        if (l < NLAY - 1) {
            ln_kernel<true, false><<<NS, 256>>>(
                ta, enc_ln2_g + (size_t)l * HD, enc_ln2_b + (size_t)l * HD,
                h, hh, hl, nullptr, nullptr, nullptr);
        } else {
            // final LN fused with classifier head -> out [4096 x 16]
            ln_kernel<false, true><<<NS, 256>>>(
                ta, enc_ln2_g + (size_t)l * HD, enc_ln2_b + (size_t)l * HD,
                nullptr, nullptr, nullptr, cls_w, cls_b, out);
        }
    }
}

// round 13
// speedup vs baseline: 1.4131x; 1.3051x over previous
#include <cuda_runtime.h>
#include <cuda_fp16.h>
#include <cstdint>
#include <math.h>

// ---------------- problem constants ----------------
#define NS    4096          // N samples
#define LS    16            // L tokens
#define DE    768           // D embedding
#define NHN   4             // heads (name attn)
#define DHN   192           // head dim (name attn)
#define HD    1024          // H
#define NLAY  4             // NL
#define NCLS  16            // C
#define XFD   256           // XF

// ---------------- scratch (device globals; no cudaMalloc allowed) ----------------
__device__ float g_qkv[(size_t)NS * LS * 2 * DE];   // compacted Q,K rows, fp32
__device__ float g_h[(size_t)NS * HD];              // fp32 residual stream
__device__ float g_ta[(size_t)NS * HD];             // fp32 (pre-LN sum)

__device__ int g_off[NS + 1];
__device__ int g_total[1];
__device__ int g_rowtok[NS * LS];

__device__ float g_zero[4096];
__device__ float g_bc[NLAY * HD];
__device__ float g_bao[HD];

// fp16 hi/lo split buffers (activations)
__device__ __align__(16) __half g_gah[(size_t)NS * LS * DE],   g_gal[(size_t)NS * LS * DE];
__device__ __align__(16) __half g_ce_h[(size_t)NS * NHN * DE], g_ce_l[(size_t)NS * NHN * DE];
__device__ __align__(16) __half g_attn_h[(size_t)NS * DE],     g_attn_l[(size_t)NS * DE];
__device__ __align__(16) __half g_xf_h[(size_t)NS * XFD],      g_xf_l[(size_t)NS * XFD];
__device__ __align__(16) __half g_hh[(size_t)NS * HD],         g_hl[(size_t)NS * HD];
__device__ __align__(16) __half g_t1_h[(size_t)NS * 2 * HD],   g_t1_l[(size_t)NS * 2 * HD];

// fp16 hi/lo split buffers (weights)
__device__ __align__(16) __half g_wqkv_h[(size_t)3 * DE * DE], g_wqkv_l[(size_t)3 * DE * DE];
__device__ __align__(16) __half g_wbott_h[(size_t)HD * (XFD + DE)], g_wbott_l[(size_t)HD * (XFD + DE)];
__device__ __align__(16) __half g_wo_h[(size_t)NLAY * HD * HD],  g_wo_l[(size_t)NLAY * HD * HD];
__device__ __align__(16) __half g_wf1_h[(size_t)NLAY * 2 * HD * HD], g_wf1_l[(size_t)NLAY * 2 * HD * HD];
__device__ __align__(16) __half g_wf2_h[(size_t)NLAY * HD * 2 * HD], g_wf2_l[(size_t)NLAY * HD * 2 * HD];
__device__ __align__(16) __half g_wvt_h[(size_t)NLAY * HD * HD],  g_wvt_l[(size_t)NLAY * HD * HD];
__device__ __align__(16) __half g_woutt_h[(size_t)DE * DE],       g_woutt_l[(size_t)DE * DE];
__device__ __align__(16) __half g_wc_h[(size_t)NLAY * HD * HD],   g_wc_l[(size_t)NLAY * HD * HD];
__device__ __align__(16) __half g_wao_h[(size_t)HD * DE],         g_wao_l[(size_t)HD * DE];

// ================= helpers =================
__device__ __forceinline__ uint32_t smem_u32(const void* p) {
    uint32_t a;
    asm("{ .reg .u64 t; cvta.to.shared.u64 t, %1; cvt.u32.u64 %0, t; }" : "=r"(a) : "l"(p));
    return a;
}
__device__ __forceinline__ uint32_t sw128(uint32_t o) { return o ^ ((o >> 3) & 0x70); }

#define LDSM4(r, addr) \
    asm volatile("ldmatrix.sync.aligned.m8n8.x4.shared.b16 {%0,%1,%2,%3}, [%4];" \
        : "=r"((r)[0]), "=r"((r)[1]), "=r"((r)[2]), "=r"((r)[3]) : "r"(addr))

__device__ __forceinline__ void mma16816(float* c, const uint32_t* a, uint32_t b0, uint32_t b1) {
    asm volatile("mma.sync.aligned.m16n8k16.row.col.f32.f16.f16.f32 "
        "{%0,%1,%2,%3},{%4,%5,%6,%7},{%8,%9},{%0,%1,%2,%3};"
        : "+f"(c[0]), "+f"(c[1]), "+f"(c[2]), "+f"(c[3])
        : "r"(a[0]), "r"(a[1]), "r"(a[2]), "r"(a[3]), "r"(b0), "r"(b1));
}

#define CP_ASYNC16(dst, src) \
    asm volatile("cp.async.cg.shared.global [%0], [%1], 16;" :: "r"(dst), "l"(src))
#define CP_COMMIT() asm volatile("cp.async.commit_group;" ::: "memory")
#define CP_WAIT(n)  asm volatile("cp.async.wait_group %0;" :: "n"(n) : "memory")

// split fp32 pair -> packed fp16 hi (p) and lo residual (q). p = {lo16=h(x), hi16=h(y)}
__device__ __forceinline__ void split2(float x, float y, uint32_t& p, uint32_t& q) {
    const __half hx = __float2half_rn(x), hy = __float2half_rn(y);
    __half2 hp = __halves2half2(hx, hy);
    p = *reinterpret_cast<uint32_t*>(&hp);
    const float r0 = x - __half2float(hx), r1 = y - __half2float(hy);
    __half2 hq = __halves2half2(__float2half_rn(r0), __float2half_rn(r1));
    q = *reinterpret_cast<uint32_t*>(&hq);
}

// reconstruct fp32 pair from packed hi/lo fp16
__device__ __forceinline__ float2 recon2(uint32_t uh, uint32_t ul) {
    const float2 a = __half22float2(*reinterpret_cast<__half2*>(&uh));
    const float2 b = __half22float2(*reinterpret_cast<__half2*>(&ul));
    return make_float2(a.x + b.x, a.y + b.y);
}

// ---------------- fp32 -> fp16 hi/lo split ----------------
__global__ __launch_bounds__(256) void split_kernel(
    const float* __restrict__ src,
    __half* __restrict__ hi, __half* __restrict__ lo, int n2)
{
    const int i = blockIdx.x * blockDim.x + threadIdx.x;
    if (i < n2) {
        const float2 v = reinterpret_cast<const float2*>(src)[i];
        uint32_t p, q;
        split2(v.x, v.y, p, q);
        reinterpret_cast<uint32_t*>(hi)[i] = p;
        reinterpret_cast<uint32_t*>(lo)[i] = q;
    }
}

// ---------------- batched fp32 [R x C] -> transposed fp16 hi/lo [C x R] ----------------
__global__ __launch_bounds__(256) void transpose_split_kernel(
    const float* __restrict__ src, int ld, int R,
    __half* __restrict__ dh, __half* __restrict__ dl,
    size_t srcStride, size_t dstStride)
{
    __shared__ float tile[32][33];
    const int z = blockIdx.z;
    src += (size_t)z * srcStride;
    dh  += (size_t)z * dstStride;
    dl  += (size_t)z * dstStride;
    const int c0 = blockIdx.x * 32, r0 = blockIdx.y * 32;
    const int tx = threadIdx.x, ty = threadIdx.y;   // (32, 8)
#pragma unroll
    for (int i = ty; i < 32; i += 8)
        tile[i][tx] = src[(size_t)(r0 + i) * ld + c0 + tx];
    __syncthreads();
    if (tx < 16) {
#pragma unroll
        for (int i = ty; i < 32; i += 8) {
            uint32_t p, q;
            split2(tile[2 * tx][i], tile[2 * tx + 1][i], p, q);
            const size_t id2 = ((size_t)(c0 + i) * R + r0) / 2 + tx;
            reinterpret_cast<uint32_t*>(dh)[id2] = p;
            reinterpret_cast<uint32_t*>(dl)[id2] = q;
        }
    }
}

// ---------------- batched bias fold: out[row] = W[row,:]·v + base[row] ----------------
__global__ __launch_bounds__(128) void bias_fold_kernel(
    const float* __restrict__ W, int ldw, int coff,
    const float* __restrict__ v, const float* __restrict__ base,
    float* __restrict__ out, int K,
    size_t wStride, size_t vStride, size_t baseStride, size_t outStride)
{
    __shared__ float red[4];
    const int z = blockIdx.y;
    W += (size_t)z * wStride;
    v += (size_t)z * vStride;
    if (base) base += (size_t)z * baseStride;
    out += (size_t)z * outStride;
    const int row = blockIdx.x;
    const int t = threadIdx.x, lane = t & 31, warp = t >> 5;
    const float* wr = W + (size_t)row * ldw + coff;
    float s = 0.f;
    for (int k = t; k < K; k += 128) s += wr[k] * v[k];
#pragma unroll
    for (int o = 16; o; o >>= 1) s += __shfl_down_sync(0xffffffffu, s, o);
    if (lane == 0) red[warp] = s;
    __syncthreads();
    if (t == 0) out[row] = red[0] + red[1] + red[2] + red[3] + (base ? base[row] : 0.f);
}

// ---------------- compaction scan ----------------
__global__ __launch_bounds__(1024) void scan_kernel(
    const int* __restrict__ lens, int* __restrict__ off, int* __restrict__ total)
{
    __shared__ int wsum[32];
    const int tid = threadIdx.x, lane = tid & 31, warp = tid >> 5;
    int v[4], s = 0;
#pragma unroll
    for (int i = 0; i < 4; i++) { v[i] = lens[tid * 4 + i]; s += v[i]; }
    int ws = s;
#pragma unroll
    for (int o = 1; o < 32; o <<= 1) { int t = __shfl_up_sync(0xffffffffu, ws, o); if (lane >= o) ws += t; }
    if (lane == 31) wsum[warp] = ws;
    __syncthreads();
    if (warp == 0) {
        int t = wsum[lane];
#pragma unroll
        for (int o = 1; o < 32; o <<= 1) { int u = __shfl_up_sync(0xffffffffu, t, o); if (lane >= o) t += u; }
        wsum[lane] = t;
    }
    __syncthreads();
    int run = ws - s + (warp ? wsum[warp - 1] : 0);
#pragma unroll
    for (int i = 0; i < 4; i++) { off[tid * 4 + i] = run; run += v[i]; }
    if (tid == 1023) { off[NS] = run; total[0] = run; }
}

__global__ __launch_bounds__(32) void fill_rows_kernel(
    const int* __restrict__ lens, const int* __restrict__ off,
    const int* __restrict__ toks, int* __restrict__ rowtok)
{
    const int b = blockIdx.x;
    const int len = lens[b], o = off[b];
    for (int s = threadIdx.x; s < len; s += 32) rowtok[o + s] = toks[b * LS + s];
}

__global__ __launch_bounds__(128) void gather_split_kernel(
    const float* __restrict__ wte, const int* __restrict__ rowtok,
    const int* __restrict__ total,
    __half* __restrict__ Ah, __half* __restrict__ Al)
{
    const int r = blockIdx.x;
    if (r >= total[0]) return;
    const float2* src = reinterpret_cast<const float2*>(wte + (size_t)rowtok[r] * DE);
    uint32_t* dh = reinterpret_cast<uint32_t*>(Ah) + (size_t)r * (DE / 2);
    uint32_t* dl = reinterpret_cast<uint32_t*>(Al) + (size_t)r * (DE / 2);
#pragma unroll
    for (int i = 0; i < 3; i++) {
        const int j = threadIdx.x + 128 * i;
        const float2 v = src[j];
        uint32_t p, q;
        split2(v.x, v.y, p, q);
        dh[j] = p; dl[j] = q;
    }
}

// ================= HMMA GEMM: C[M,N] = A[M,K] @ B[N,K]^T + bias (+rs*bias2) (+RES) =================
// fp16 2-term: C = (Ah + Al) @ Bh^T.  A split hi/lo fp16; B hi only.
#define CHUNK  64
#define STG_BYTES (80 * 1024)
#define OFF_AH 0
#define OFF_AL 32768
#define OFF_BH 65536
#define TG_SMEM  (2 * STG_BYTES + 256)

template<int AMODE, int BMODE, bool RELU, bool WF32, bool WSPLIT, bool MDYN, bool HASB2, bool NDYN, bool RESID>
__global__ __launch_bounds__(256, 1) void tgemm_kernel(
    int M, int N, int K, int K1,
    const __half* __restrict__ Ah, const __half* __restrict__ Al, int lda,
    const __half* __restrict__ A2h, const __half* __restrict__ A2l, int lda2,
    const int* __restrict__ Mlim,
    const __half* __restrict__ Bh, const __half* __restrict__ Bl, int ldb,
    const __half* __restrict__ B2h, const __half* __restrict__ B2l, int ldb2,
    const float* __restrict__ bias, const float* __restrict__ bias2,
    const int* __restrict__ rowscale,
    float* __restrict__ C,
    __half* __restrict__ Ch, __half* __restrict__ Cl,
    size_t strideA, size_t strideB, size_t strideC,
    int ldc, int Nlim, size_t strideB2,
    const float* __restrict__ RES)
{
    extern __shared__ char smem[];
    const uint32_t sb = smem_u32(smem);

    const int z = blockIdx.z;
    if (strideA) { Ah += (size_t)z * strideA; Al += (size_t)z * strideA; }
    if (strideB) { Bh += (size_t)z * strideB; }
    if (strideC) { Ch += (size_t)z * strideC; Cl += (size_t)z * strideC; }
    if (HASB2 && strideB2) bias2 += (size_t)z * strideB2;

    const int tid  = threadIdx.x;
    const int lane = tid & 31;
    const int wid  = tid >> 5;
    const int bm = blockIdx.y * 256, bn = blockIdx.x * 128;

    int Mtot = M;
    if (MDYN) {
        Mtot = Mlim[0];
        if (bm >= Mtot) return;
    }

    const int nch = K / CHUNK;

    auto issue_stage = [&](int c) {
        const int k0 = c * CHUNK;
        const uint32_t st = sb + (c & 1) * STG_BYTES;
#pragma unroll
        for (int i = 0; i < 8; i++) {
            const int idx = tid + 256 * i;
            const int row = idx >> 3;
            const int seg = idx & 7;
            const uint32_t sw = sw128(row * 128 + seg * 16);
            int ar = bm + row;
            if (MDYN && ar >= Mtot) ar = Mtot - 1;
            const __half *pah, *pal;
            if (AMODE == 2 && k0 >= K1) {
                const size_t off = (size_t)ar * lda2 + (k0 - K1) + seg * 8;
                pah = A2h + off; pal = A2l + off;
            } else {
                const size_t off = (size_t)ar * lda + k0 + seg * 8;
                pah = Ah + off; pal = Al + off;
            }
            CP_ASYNC16(st + OFF_AH + sw, pah);
            CP_ASYNC16(st + OFF_AL + sw, pal);
        }
#pragma unroll
        for (int i = 0; i < 4; i++) {
            const int idx = tid + 256 * i;
            const int row = idx >> 3;
            const int seg = idx & 7;
            const uint32_t sw = sw128(row * 128 + seg * 16);
            int br = bn + row;
            if (NDYN && br >= Nlim) br = Nlim - 1;
            const __half* pbh;
            if (BMODE == 2 && k0 >= K1) {
                pbh = B2h + (size_t)br * ldb2 + (k0 - K1) + seg * 8;
            } else {
                pbh = Bh + (size_t)br * ldb + k0 + seg * 8;
            }
            CP_ASYNC16(st + OFF_BH + sw, pbh);
        }
        CP_COMMIT();
    };

    issue_stage(0);

    const int wm = (wid >> 1) * 64;
    const int wn = (wid & 1) * 64;

    float acc[4][8][4];
#pragma unroll
    for (int i = 0; i < 4; i++)
#pragma unroll
        for (int j = 0; j < 8; j++)
#pragma unroll
            for (int t = 0; t < 4; t++) acc[i][j][t] = 0.f;

    const int a_row  = (lane & 15);
    const int a_kb   = (lane >> 4) * 16;
    const int b_row  = (lane & 7) + ((lane >> 4) << 3);
    const int b_kb   = ((lane >> 3) & 1) * 16;

    for (int c = 0; c < nch; c++) {
        CP_WAIT(0);
        __syncthreads();
        if (c + 1 < nch) issue_stage(c + 1);

        const uint32_t st = sb + (c & 1) * STG_BYTES;

#pragma unroll
        for (int ks = 0; ks < 4; ks++) {
            const int kb = ks * 32;
            uint32_t ah[4][4], al[4][4];
#pragma unroll
            for (int i = 0; i < 4; i++) {
                const uint32_t oa = sw128((wm + i * 16 + a_row) * 128 + kb + a_kb);
                LDSM4(ah[i], st + OFF_AH + oa);
                LDSM4(al[i], st + OFF_AL + oa);
            }
            uint32_t bf[4][4];
#pragma unroll
            for (int j2 = 0; j2 < 4; j2++) {
                const uint32_t ob = sw128((wn + j2 * 16 + b_row) * 128 + kb + b_kb);
                LDSM4(bf[j2], st + OFF_BH + ob);
            }
            // (Ah + Al) * Bh
#pragma unroll
            for (int i = 0; i < 4; i++)
#pragma unroll
                for (int j2 = 0; j2 < 4; j2++) {
                    mma16816(acc[i][2 * j2 + 0], ah[i], bf[j2][0], bf[j2][1]);
                    mma16816(acc[i][2 * j2 + 1], ah[i], bf[j2][2], bf[j2][3]);
                    mma16816(acc[i][2 * j2 + 0], al[i], bf[j2][0], bf[j2][1]);
                    mma16816(acc[i][2 * j2 + 1], al[i], bf[j2][2], bf[j2][3]);
                }
        }
    }

    // ---- epilogue ----
#pragma unroll
    for (int i = 0; i < 4; i++) {
        const int r0 = bm + wm + i * 16 + (lane >> 2);
        const int r1 = r0 + 8;
        const bool ok0 = !MDYN || (r0 < Mtot);
        const bool ok1 = !MDYN || (r1 < Mtot);
        const float rs0 = HASB2 ? (float)rowscale[r0] : 0.f;
        const float rs1 = HASB2 ? (float)rowscale[r1] : 0.f;
#pragma unroll
        for (int j = 0; j < 8; j++) {
            const int col = bn + wn + j * 8 + (lane & 3) * 2;
            const bool okc = !NDYN || (col < Nlim);
            float b00 = bias[col], b01 = bias[col + 1];
            float b10 = b00, b11 = b01;
            if (HASB2) {
                b00 += rs0 * bias2[col]; b01 += rs0 * bias2[col + 1];
                b10 += rs1 * bias2[col]; b11 += rs1 * bias2[col + 1];
            }
            float2 v0 = make_float2(acc[i][j][0] + b00, acc[i][j][1] + b01);
            float2 v1 = make_float2(acc[i][j][2] + b10, acc[i][j][3] + b11);
            if (RESID) {
                const float2 h0 = *reinterpret_cast<const float2*>(RES + (size_t)r0 * ldc + col);
                const float2 h1 = *reinterpret_cast<const float2*>(RES + (size_t)r1 * ldc + col);
                v0.x += h0.x; v0.y += h0.y;
                v1.x += h1.x; v1.y += h1.y;
            }
            if (RELU) {
                v0.x = fmaxf(v0.x, 0.f); v0.y = fmaxf(v0.y, 0.f);
                v1.x = fmaxf(v1.x, 0.f); v1.y = fmaxf(v1.y, 0.f);
            }
            if (WF32) {
                if (ok0 && okc) *reinterpret_cast<float2*>(C + (size_t)r0 * ldc + col) = v0;
                if (ok1 && okc) *reinterpret_cast<float2*>(C + (size_t)r1 * ldc + col) = v1;
            }
            if (WSPLIT) {
                uint32_t p, q;
                if (ok0 && okc) {
                    split2(v0.x, v0.y, p, q);
                    reinterpret_cast<uint32_t*>(Ch)[((size_t)r0 * ldc + col) >> 1] = p;
                    reinterpret_cast<uint32_t*>(Cl)[((size_t)r0 * ldc + col) >> 1] = q;
                }
                if (ok1 && okc) {
                    split2(v1.x, v1.y, p, q);
                    reinterpret_cast<uint32_t*>(Ch)[((size_t)r1 * ldc + col) >> 1] = p;
                    reinterpret_cast<uint32_t*>(Cl)[((size_t)r1 * ldc + col) >> 1] = q;
                }
            }
        }
    }
}

// ---------------- name attention: block per (head, sample); emits CE ----------------
__global__ __launch_bounds__(192) void name_attn_kernel(
    const float* __restrict__ qk, const int* __restrict__ off,
    const __half* __restrict__ eh, const __half* __restrict__ el,
    __half* __restrict__ CEh, __half* __restrict__ CEl)
{
    __shared__ float Qs[LS][DHN];
    __shared__ float Ks[LS][DHN];
    __shared__ float sc[LS][LS + 1];
    __shared__ float cw[LS];

    const int h = blockIdx.x;
    const int b = blockIdx.y;
    const int d = threadIdx.x;

    const int o   = off[b];
    const int len = off[b + 1] - o;

    const float* base = qk + (size_t)o * (2 * DE) + h * DHN + d;
    for (int s = 0; s < len; s++) {
        Qs[s][d] = base[s * (2 * DE)];
        Ks[s][d] = base[s * (2 * DE) + DE];
    }
    if (d < LS) cw[d] = 0.f;
    __syncthreads();

    const int warp = d >> 5, lane = d & 31;
    const float scale = 1.0f / sqrtf((float)DHN);
    const int np = len * len;
    for (int p = warp; p < np; p += 6) {
        const int q = p / len, j = p - q * len;
        float s = 0.f;
#pragma unroll
        for (int i = 0; i < 6; i++) s += Qs[q][lane + 32 * i] * Ks[j][lane + 32 * i];
#pragma unroll
        for (int ofs = 16; ofs; ofs >>= 1) s += __shfl_down_sync(0xffffffffu, s, ofs);
        if (lane == 0) sc[q][j] = s * scale;
    }
    __syncthreads();

    if (d < len) {
        float mx = -1e30f;
        for (int j = 0; j < len; j++) mx = fmaxf(mx, sc[d][j]);
        float sum = 0.f;
        float row[LS];
        for (int j = 0; j < len; j++) { row[j] = expf(sc[d][j] - mx); sum += row[j]; }
        const float inv = 1.f / sum;
        for (int j = 0; j < len; j++) sc[d][j] = row[j] * inv;
    }
    __syncthreads();

    if (d < len) {
        float c = 0.f;
        for (int s = 0; s < len; s++) c += sc[s][d];
        cw[d] = c;
    }
    __syncthreads();

    const uint32_t* ehp = reinterpret_cast<const uint32_t*>(eh);
    const uint32_t* elp = reinterpret_cast<const uint32_t*>(el);
    for (int p = d; p < DE / 2; p += 192) {
        float ce0 = 0.f, ce1 = 0.f;
        for (int j = 0; j < len; j++) {
            const size_t idx = (size_t)(o + j) * (DE / 2) + p;
            const float2 e = recon2(ehp[idx], elp[idx]);
            ce0 += cw[j] * e.x;
            ce1 += cw[j] * e.y;
        }
        uint32_t P, Q;
        split2(ce0, ce1, P, Q);
        const size_t id2 = (size_t)b * (NHN * DE / 2) + h * (DE / 2) + p;
        reinterpret_cast<uint32_t*>(CEh)[id2] = P;
        reinterpret_cast<uint32_t*>(CEl)[id2] = Q;
    }
}

// ---------------- LayerNorm of ta (residual already added in GEMM epilogue) ----------------
__device__ __forceinline__ float block_reduce_sum(float v) {
    __shared__ float red[8];
    const int lane = threadIdx.x & 31, warp = threadIdx.x >> 5;
#pragma unroll
    for (int o = 16; o; o >>= 1) v += __shfl_down_sync(0xffffffffu, v, o);
    if (lane == 0) red[warp] = v;
    __syncthreads();
    v = (threadIdx.x < 8) ? red[threadIdx.x] : 0.f;
    if (warp == 0)
#pragma unroll
        for (int o = 4; o; o >>= 1) v += __shfl_down_sync(0xffffffffu, v, o);
    return v;
}

template<bool WRITEH, bool DOCLS>
__global__ __launch_bounds__(256) void ln_kernel(
    const float* __restrict__ ta,
    const float* __restrict__ g, const float* __restrict__ b,
    float* __restrict__ h,
    __half* __restrict__ hh, __half* __restrict__ hl,
    const float* __restrict__ clsw, const float* __restrict__ clsb,
    float* __restrict__ out)
{
    const int row = blockIdx.x;
    const int t = threadIdx.x;
    float v[4];
    float s = 0.f;
#pragma unroll
    for (int i = 0; i < 4; i++) {
        const int c = t + 256 * i;
        v[i] = ta[(size_t)row * HD + c];
        s += v[i];
    }
    s = block_reduce_sum(s);
    __shared__ float mean_s, rstd_s;
    if (t == 0) mean_s = s * (1.f / HD);
    __syncthreads();
    const float m = mean_s;
    float s2 = 0.f;
#pragma unroll
    for (int i = 0; i < 4; i++) { const float dd = v[i] - m; s2 += dd * dd; }
    s2 = block_reduce_sum(s2);
    if (t == 0) rstd_s = rsqrtf(s2 * (1.f / HD) + 1e-5f);
    __syncthreads();
    const float r = rstd_s;

    __shared__ float ys[HD];
#pragma unroll
    for (int i = 0; i < 4; i++) {
        const int c = t + 256 * i;
        const float y = (v[i] - m) * r * g[c] + b[c];
        if (WRITEH) {
            h[(size_t)row * HD + c] = y;
            const float y1 = __shfl_down_sync(0xffffffffu, y, 1);
            if (!(t & 1)) {
                uint32_t p, q;
                split2(y, y1, p, q);
                const size_t id2 = ((size_t)row * HD + c) >> 1;
                reinterpret_cast<uint32_t*>(hh)[id2] = p;
                reinterpret_cast<uint32_t*>(hl)[id2] = q;
            }
        }
        if (DOCLS) ys[c] = y;
    }
    if (DOCLS) {
        __syncthreads();
        const int warp = t >> 5, lane = t & 31;
        for (int cc = warp; cc < NCLS; cc += 8) {
            const float* wr = clsw + (size_t)cc * HD;
            float sum = 0.f;
#pragma unroll
            for (int i = lane; i < HD; i += 32) sum += ys[i] * wr[i];
#pragma unroll
            for (int o = 16; o; o >>= 1) sum += __shfl_down_sync(0xffffffffu, sum, o);
            if (lane == 0) out[(size_t)row * NCLS + cc] = sum + clsb[cc];
        }
    }
}

// ---------------- orchestration ----------------
static inline void launch_split_s(cudaStream_t st, const float* src,
                                  __half* hi, __half* lo, size_t n) {
    const int n2 = (int)(n / 2);
    split_kernel<<<(n2 + 255) / 256, 256, 0, st>>>(src, hi, lo, n2);
}

extern "C" void kernel_launch(void* const* d_in, const int* in_sizes, int n_in,
                              void* d_out, int out_size)
{
    const int*   name_tokens = (const int*)d_in[0];
    const int*   name_lens   = (const int*)d_in[1];
    const float* x_feats     = (const float*)d_in[2];
    const float* wte         = (const float*)d_in[3];
    const float* mha_in_w    = (const float*)d_in[4];
    const float* mha_in_b    = (const float*)d_in[5];
    const float* mha_out_w   = (const float*)d_in[6];
    const float* mha_out_b   = (const float*)d_in[7];
    const float* bott_w      = (const float*)d_in[8];
    const float* bott_b      = (const float*)d_in[9];
    const float* enc_in_w    = (const float*)d_in[10];
    const float* enc_in_b    = (const float*)d_in[11];
    const float* enc_out_w   = (const float*)d_in[12];
    const float* enc_out_b   = (const float*)d_in[13];
    const float* enc_ln1_g   = (const float*)d_in[14];
    const float* enc_ln1_b   = (const float*)d_in[15];
    const float* enc_ln2_g   = (const float*)d_in[16];
    const float* enc_ln2_b   = (const float*)d_in[17];
    const float* enc_ff1_w   = (const float*)d_in[18];
    const float* enc_ff1_b   = (const float*)d_in[19];
    const float* enc_ff2_w   = (const float*)d_in[20];
    const float* enc_ff2_b   = (const float*)d_in[21];
    const float* cls_w       = (const float*)d_in[22];
    const float* cls_b       = (const float*)d_in[23];
    float* out = (float*)d_out;

    float *qkv, *h, *ta, *zero, *bc, *bao;
    int *off, *total, *rowtok;
    cudaGetSymbolAddress((void**)&qkv,    g_qkv);
    cudaGetSymbolAddress((void**)&h,      g_h);
    cudaGetSymbolAddress((void**)&ta,     g_ta);
    cudaGetSymbolAddress((void**)&zero,   g_zero);
    cudaGetSymbolAddress((void**)&bc,     g_bc);
    cudaGetSymbolAddress((void**)&bao,    g_bao);
    cudaGetSymbolAddress((void**)&off,    g_off);
    cudaGetSymbolAddress((void**)&total,  g_total);
    cudaGetSymbolAddress((void**)&rowtok, g_rowtok);

    __half *gah, *gal, *ce_h, *ce_l, *attn_h, *attn_l, *xf_h, *xf_l, *hh, *hl, *t1_h, *t1_l;
    __half *wqkv_h, *wqkv_l, *wbott_h, *wbott_l, *wo_h, *wo_l, *wf1_h, *wf1_l, *wf2_h, *wf2_l;
    __half *wvt_h, *wvt_l, *woutt_h, *woutt_l, *wc_h, *wc_l, *wao_h, *wao_l;
    cudaGetSymbolAddress((void**)&gah,    g_gah);     cudaGetSymbolAddress((void**)&gal,    g_gal);
    cudaGetSymbolAddress((void**)&ce_h,   g_ce_h);    cudaGetSymbolAddress((void**)&ce_l,   g_ce_l);
    cudaGetSymbolAddress((void**)&attn_h, g_attn_h);  cudaGetSymbolAddress((void**)&attn_l, g_attn_l);
    cudaGetSymbolAddress((void**)&xf_h,   g_xf_h);    cudaGetSymbolAddress((void**)&xf_l,   g_xf_l);
    cudaGetSymbolAddress((void**)&hh,     g_hh);      cudaGetSymbolAddress((void**)&hl,     g_hl);
    cudaGetSymbolAddress((void**)&t1_h,   g_t1_h);    cudaGetSymbolAddress((void**)&t1_l,   g_t1_l);
    cudaGetSymbolAddress((void**)&wqkv_h, g_wqkv_h);  cudaGetSymbolAddress((void**)&wqkv_l, g_wqkv_l);
    cudaGetSymbolAddress((void**)&wbott_h,g_wbott_h); cudaGetSymbolAddress((void**)&wbott_l,g_wbott_l);
    cudaGetSymbolAddress((void**)&wo_h,   g_wo_h);    cudaGetSymbolAddress((void**)&wo_l,   g_wo_l);
    cudaGetSymbolAddress((void**)&wf1_h,  g_wf1_h);   cudaGetSymbolAddress((void**)&wf1_l,  g_wf1_l);
    cudaGetSymbolAddress((void**)&wf2_h,  g_wf2_h);   cudaGetSymbolAddress((void**)&wf2_l,  g_wf2_l);
    cudaGetSymbolAddress((void**)&wvt_h,  g_wvt_h);   cudaGetSymbolAddress((void**)&wvt_l,  g_wvt_l);
    cudaGetSymbolAddress((void**)&woutt_h,g_woutt_h); cudaGetSymbolAddress((void**)&woutt_l,g_woutt_l);
    cudaGetSymbolAddress((void**)&wc_h,   g_wc_h);    cudaGetSymbolAddress((void**)&wc_l,   g_wc_l);
    cudaGetSymbolAddress((void**)&wao_h,  g_wao_h);   cudaGetSymbolAddress((void**)&wao_l,  g_wao_l);

    auto k_qk    = tgemm_kernel<0, 0, false, true,  false, true,  false, false, false>;
    auto k_csum  = tgemm_kernel<0, 0, false, false, true,  false, true,  true,  false>;
    auto k_bott  = tgemm_kernel<2, 2, false, true,  true,  false, true,  false, false>;
    auto k_resid = tgemm_kernel<0, 0, false, true,  false, false, false, false, true >;
    auto k_ff1   = tgemm_kernel<0, 0, true,  false, true,  false, false, false, false>;
    auto k_pre   = tgemm_kernel<0, 0, false, false, true,  false, false, false, false>;
    cudaFuncSetAttribute(k_qk,    cudaFuncAttributeMaxDynamicSharedMemorySize, TG_SMEM);
    cudaFuncSetAttribute(k_csum,  cudaFuncAttributeMaxDynamicSharedMemorySize, TG_SMEM);
    cudaFuncSetAttribute(k_bott,  cudaFuncAttributeMaxDynamicSharedMemorySize, TG_SMEM);
    cudaFuncSetAttribute(k_resid, cudaFuncAttributeMaxDynamicSharedMemorySize, TG_SMEM);
    cudaFuncSetAttribute(k_ff1,   cudaFuncAttributeMaxDynamicSharedMemorySize, TG_SMEM);
    cudaFuncSetAttribute(k_pre,   cudaFuncAttributeMaxDynamicSharedMemorySize, TG_SMEM);

    cudaStream_t side = 0;
    cudaEvent_t evFork = 0, evJoin = 0;
    bool use_side = (cudaStreamCreateWithFlags(&side, cudaStreamNonBlocking) == cudaSuccess)
                 && (cudaEventCreateWithFlags(&evFork, cudaEventDisableTiming) == cudaSuccess)
                 && (cudaEventCreateWithFlags(&evJoin, cudaEventDisableTiming) == cudaSuccess);
    cudaStream_t prepSt = use_side ? side : (cudaStream_t)0;

    // ---- main-path prep ----
    scan_kernel<<<1, 1024>>>(name_lens, off, total);
    fill_rows_kernel<<<NS, 32>>>(name_lens, off, name_tokens, rowtok);
    gather_split_kernel<<<NS * LS, 128>>>(wte, rowtok, total, gah, gal);
    launch_split_s(0, mha_in_w, wqkv_h, wqkv_l, (size_t)3 * DE * DE);
    launch_split_s(0, bott_w,   wbott_h, wbott_l, (size_t)HD * (XFD + DE));
    launch_split_s(0, x_feats,  xf_h, xf_l, (size_t)NS * XFD);
    transpose_split_kernel<<<dim3(DE / 32, DE / 32, 1), dim3(32, 8)>>>(
        mha_out_w, DE, DE, woutt_h, woutt_l, 0, 0);
    bias_fold_kernel<<<dim3(HD, 1), 128>>>(
        bott_w, XFD + DE, XFD, mha_out_b, nullptr, bao, DE, 0, 0, 0, 0);

    // ---- fork: encoder-weight prep on side stream ----
    if (use_side) {
        cudaEventRecord(evFork, 0);
        cudaStreamWaitEvent(side, evFork, 0);
    }
    launch_split_s(prepSt, enc_out_w, wo_h,  wo_l,  (size_t)NLAY * HD * HD);
    launch_split_s(prepSt, enc_ff1_w, wf1_h, wf1_l, (size_t)NLAY * 2 * HD * HD);
    launch_split_s(prepSt, enc_ff2_w, wf2_h, wf2_l, (size_t)NLAY * HD * 2 * HD);
    transpose_split_kernel<<<dim3(HD / 32, HD / 32, NLAY), dim3(32, 8), 0, prepSt>>>(
        enc_in_w + (size_t)2 * HD * HD, HD, HD, wvt_h, wvt_l,
        (size_t)3 * HD * HD, (size_t)HD * HD);
    bias_fold_kernel<<<dim3(HD, NLAY), 128, 0, prepSt>>>(
        enc_out_w, HD, 0, enc_in_b + 2 * HD, enc_out_b, bc, HD,
        (size_t)HD * HD, (size_t)3 * HD, (size_t)HD, (size_t)HD);
    k_pre<<<dim3(HD / 128, HD / 256, NLAY), 256, TG_SMEM, prepSt>>>(
        HD, HD, HD, 0,
        wo_h, wo_l, HD, nullptr, nullptr, 0, nullptr,
        wvt_h, wvt_l, HD, nullptr, nullptr, 0,
        zero, nullptr, nullptr,
        nullptr, wc_h, wc_l,
        (size_t)HD * HD, (size_t)HD * HD, (size_t)HD * HD, HD, HD, 0, nullptr);
    k_pre<<<dim3(DE / 128, HD / 256, 1), 256, TG_SMEM, prepSt>>>(
        HD, DE, DE, 0,
        wbott_h + XFD, wbott_l + XFD, XFD + DE, nullptr, nullptr, 0, nullptr,
        woutt_h, woutt_l, DE, nullptr, nullptr, 0,
        zero, nullptr, nullptr,
        nullptr, wao_h, wao_l, 0, 0, 0, DE, DE, 0, nullptr);
    if (use_side) cudaEventRecord(evJoin, side);

    const int MQ = NS * LS;
    const int KQ = DE;
    const int NQ = 2 * DE;       // Q,K only

    // 1. qk(compact) = gathered_emb @ [Wq;Wk]^T + bias
    k_qk<<<dim3(NQ / 128, MQ / 256, 1), 256, TG_SMEM>>>(
        MQ, NQ, KQ, 0,
        gah, gal, KQ, nullptr, nullptr, 0, total,
        wqkv_h, wqkv_l, KQ, nullptr, nullptr, 0,
        mha_in_b, nullptr, nullptr, qkv, nullptr, nullptr, 0, 0, 0, NQ, NQ, 0, nullptr);

    // 2. attention weights -> per-head mixed embeddings CE [4096 x 4 x 768]
    name_attn_kernel<<<dim3(NHN, NS), 192>>>(qkv, off, gah, gal, ce_h, ce_l);

    // 2b. attnsum_h = CE_h @ Wv_h^T + len*bv_h
    k_csum<<<dim3(2, NS / 256, NHN), 256, TG_SMEM>>>(
        NS, DHN, DE, 0,
        ce_h, ce_l, NHN * DE, nullptr, nullptr, 0, nullptr,
        wqkv_h + (size_t)2 * DE * DE, wqkv_l + (size_t)2 * DE * DE, DE, nullptr, nullptr, 0,
        zero, mha_in_b + 2 * DE, name_lens,
        nullptr, attn_h, attn_l,
        (size_t)DE, (size_t)DHN * DE, (size_t)DHN,
        DE, DHN, (size_t)DHN, nullptr);

    // ---- join ----
    if (use_side) cudaStreamWaitEvent(0, evJoin, 0);

    // 3. x = xf@Wb1^T + attnsum@Wao^T + bbott + len*bao -> h fp32 + split
    k_bott<<<dim3(HD / 128, NS / 256, 1), 256, TG_SMEM>>>(
        NS, HD, XFD + DE, XFD,
        xf_h, xf_l, XFD, attn_h, attn_l, DE, nullptr,
        wbott_h, wbott_l, XFD + DE, wao_h, wao_l, DE,
        bott_b, bao, name_lens, h, hh, hl, 0, 0, 0, HD, HD, 0, nullptr);

    // 4. encoder layers (residual fused into GEMM epilogue; LN reads only ta)
    for (int l = 0; l < NLAY; l++) {
        k_resid<<<dim3(HD / 128, NS / 256, 1), 256, TG_SMEM>>>(
            NS, HD, HD, 0,
            hh, hl, HD, nullptr, nullptr, 0, nullptr,
            wc_h + (size_t)l * HD * HD, wc_l + (size_t)l * HD * HD, HD,
            nullptr, nullptr, 0,
            bc + (size_t)l * HD, nullptr, nullptr, ta, nullptr, nullptr, 0, 0, 0, HD, HD, 0, h);
        ln_kernel<true, false><<<NS, 256>>>(
            ta, enc_ln1_g + (size_t)l * HD, enc_ln1_b + (size_t)l * HD,
            h, hh, hl, nullptr, nullptr, nullptr);

        k_ff1<<<dim3(2 * HD / 128, NS / 256, 1), 256, TG_SMEM>>>(
            NS, 2 * HD, HD, 0,
            hh, hl, HD, nullptr, nullptr, 0, nullptr,
            wf1_h + (size_t)l * 2 * HD * HD, wf1_l + (size_t)l * 2 * HD * HD, HD,
            nullptr, nullptr, 0,
            enc_ff1_b + (size_t)l * 2 * HD, nullptr, nullptr, nullptr, t1_h, t1_l,
            0, 0, 0, 2 * HD, 2 * HD, 0, nullptr);
        k_resid<<<dim3(HD / 128, NS / 256, 1), 256, TG_SMEM>>>(
            NS, HD, 2 * HD, 0,
            t1_h, t1_l, 2 * HD, nullptr, nullptr, 0, nullptr,
            wf2_h + (size_t)l * HD * 2 * HD, wf2_l + (size_t)l * HD * 2 * HD, 2 * HD,
            nullptr, nullptr, 0,
            enc_ff2_b + (size_t)l * HD, nullptr, nullptr, ta, nullptr, nullptr, 0, 0, 0, HD, HD, 0, h);
        if (l < NLAY - 1) {
            ln_kernel<true, false><<<NS, 256>>>(
                ta, enc_ln2_g + (size_t)l * HD, enc_ln2_b + (size_t)l * HD,
                h, hh, hl, nullptr, nullptr, nullptr);
        } else {
            // final LN fused with classifier head -> out [4096 x 16]
            ln_kernel<false, true><<<NS, 256>>>(
                ta, enc_ln2_g + (size_t)l * HD, enc_ln2_b + (size_t)l * HD,
                nullptr, nullptr, nullptr, cls_w, cls_b, out);
        }
    }
}

// round 14
// speedup vs baseline: 1.4134x; 1.0003x over previous
#include <cuda_runtime.h>
#include <cuda_fp16.h>
#include <cstdint>
#include <math.h>

// ---------------- problem constants ----------------
#define NS    4096          // N samples
#define LS    16            // L tokens
#define DE    768           // D embedding
#define NHN   4             // heads (name attn)
#define DHN   192           // head dim (name attn)
#define HD    1024          // H
#define NLAY  4             // NL
#define NCLS  16            // C
#define XFD   256           // XF

// ---------------- scratch (device globals; no cudaMalloc allowed) ----------------
__device__ float g_qkv[(size_t)NS * LS * 2 * DE];   // compacted Q,K rows, fp32
__device__ float g_ta[(size_t)NS * HD];             // fp32 (pre-LN sum)

__device__ int g_off[NS + 1];
__device__ int g_total[1];
__device__ int g_rowtok[NS * LS];

__device__ float g_zero[4096];
__device__ float g_bc[NLAY * HD];
__device__ float g_bao[HD];

// fp16 hi/lo split buffers (activations)
__device__ __align__(16) __half g_gah[(size_t)NS * LS * DE],   g_gal[(size_t)NS * LS * DE];
__device__ __align__(16) __half g_ce_h[(size_t)NS * NHN * DE], g_ce_l[(size_t)NS * NHN * DE];
__device__ __align__(16) __half g_attn_h[(size_t)NS * DE],     g_attn_l[(size_t)NS * DE];
__device__ __align__(16) __half g_xf_h[(size_t)NS * XFD],      g_xf_l[(size_t)NS * XFD];
__device__ __align__(16) __half g_hh[(size_t)NS * HD],         g_hl[(size_t)NS * HD];
__device__ __align__(16) __half g_t1_h[(size_t)NS * 2 * HD],   g_t1_l[(size_t)NS * 2 * HD];

// fp16 split buffers (weights; lo only where read as A operand)
__device__ __align__(16) __half g_wqkv_h[(size_t)3 * DE * DE];                                   // B only
__device__ __align__(16) __half g_wbott_h[(size_t)HD * (XFD + DE)], g_wbott_l[(size_t)HD * (XFD + DE)];  // A+B
__device__ __align__(16) __half g_wo_h[(size_t)NLAY * HD * HD],  g_wo_l[(size_t)NLAY * HD * HD];  // A in fold
__device__ __align__(16) __half g_wf1_h[(size_t)NLAY * 2 * HD * HD];                             // B only
__device__ __align__(16) __half g_wf2_h[(size_t)NLAY * HD * 2 * HD];                             // B only
__device__ __align__(16) __half g_wvt_h[(size_t)NLAY * HD * HD];                                 // B only
__device__ __align__(16) __half g_woutt_h[(size_t)DE * DE];                                      // B only
__device__ __align__(16) __half g_wc_h[(size_t)NLAY * HD * HD];                                  // B only
__device__ __align__(16) __half g_wao_h[(size_t)HD * DE];                                        // B only

// ================= helpers =================
__device__ __forceinline__ uint32_t smem_u32(const void* p) {
    uint32_t a;
    asm("{ .reg .u64 t; cvta.to.shared.u64 t, %1; cvt.u32.u64 %0, t; }" : "=r"(a) : "l"(p));
    return a;
}
__device__ __forceinline__ uint32_t sw128(uint32_t o) { return o ^ ((o >> 3) & 0x70); }

#define LDSM4(r, addr) \
    asm volatile("ldmatrix.sync.aligned.m8n8.x4.shared.b16 {%0,%1,%2,%3}, [%4];" \
        : "=r"((r)[0]), "=r"((r)[1]), "=r"((r)[2]), "=r"((r)[3]) : "r"(addr))

__device__ __forceinline__ void mma16816(float* c, const uint32_t* a, uint32_t b0, uint32_t b1) {
    asm volatile("mma.sync.aligned.m16n8k16.row.col.f32.f16.f16.f32 "
        "{%0,%1,%2,%3},{%4,%5,%6,%7},{%8,%9},{%0,%1,%2,%3};"
        : "+f"(c[0]), "+f"(c[1]), "+f"(c[2]), "+f"(c[3])
        : "r"(a[0]), "r"(a[1]), "r"(a[2]), "r"(a[3]), "r"(b0), "r"(b1));
}

#define CP_ASYNC16(dst, src) \
    asm volatile("cp.async.cg.shared.global [%0], [%1], 16;" :: "r"(dst), "l"(src))
#define CP_COMMIT() asm volatile("cp.async.commit_group;" ::: "memory")
#define CP_WAIT(n)  asm volatile("cp.async.wait_group %0;" :: "n"(n) : "memory")

// split fp32 pair -> packed fp16 hi (p) and lo residual (q)
__device__ __forceinline__ void split2(float x, float y, uint32_t& p, uint32_t& q) {
    const __half hx = __float2half_rn(x), hy = __float2half_rn(y);
    __half2 hp = __halves2half2(hx, hy);
    p = *reinterpret_cast<uint32_t*>(&hp);
    const float r0 = x - __half2float(hx), r1 = y - __half2float(hy);
    __half2 hq = __halves2half2(__float2half_rn(r0), __float2half_rn(r1));
    q = *reinterpret_cast<uint32_t*>(&hq);
}

// reconstruct fp32 pair from packed hi/lo fp16
__device__ __forceinline__ float2 recon2(uint32_t uh, uint32_t ul) {
    const float2 a = __half22float2(*reinterpret_cast<__half2*>(&uh));
    const float2 b = __half22float2(*reinterpret_cast<__half2*>(&ul));
    return make_float2(a.x + b.x, a.y + b.y);
}

// ---------------- fp32 -> fp16 hi(/lo) split (lo nullable) ----------------
__global__ __launch_bounds__(256) void split_kernel(
    const float* __restrict__ src,
    __half* __restrict__ hi, __half* __restrict__ lo, int n2)
{
    const int i = blockIdx.x * blockDim.x + threadIdx.x;
    if (i < n2) {
        const float2 v = reinterpret_cast<const float2*>(src)[i];
        uint32_t p, q;
        split2(v.x, v.y, p, q);
        reinterpret_cast<uint32_t*>(hi)[i] = p;
        if (lo) reinterpret_cast<uint32_t*>(lo)[i] = q;
    }
}

// ---------------- batched fp32 [R x C] -> transposed fp16 hi(/lo) [C x R] ----------------
__global__ __launch_bounds__(256) void transpose_split_kernel(
    const float* __restrict__ src, int ld, int R,
    __half* __restrict__ dh, __half* __restrict__ dl,
    size_t srcStride, size_t dstStride)
{
    __shared__ float tile[32][33];
    const int z = blockIdx.z;
    src += (size_t)z * srcStride;
    dh  += (size_t)z * dstStride;
    if (dl) dl += (size_t)z * dstStride;
    const int c0 = blockIdx.x * 32, r0 = blockIdx.y * 32;
    const int tx = threadIdx.x, ty = threadIdx.y;   // (32, 8)
#pragma unroll
    for (int i = ty; i < 32; i += 8)
        tile[i][tx] = src[(size_t)(r0 + i) * ld + c0 + tx];
    __syncthreads();
    if (tx < 16) {
#pragma unroll
        for (int i = ty; i < 32; i += 8) {
            uint32_t p, q;
            split2(tile[2 * tx][i], tile[2 * tx + 1][i], p, q);
            const size_t id2 = ((size_t)(c0 + i) * R + r0) / 2 + tx;
            reinterpret_cast<uint32_t*>(dh)[id2] = p;
            if (dl) reinterpret_cast<uint32_t*>(dl)[id2] = q;
        }
    }
}

// ---------------- batched bias fold: out[row] = W[row,:]·v + base[row] ----------------
__global__ __launch_bounds__(128) void bias_fold_kernel(
    const float* __restrict__ W, int ldw, int coff,
    const float* __restrict__ v, const float* __restrict__ base,
    float* __restrict__ out, int K,
    size_t wStride, size_t vStride, size_t baseStride, size_t outStride)
{
    __shared__ float red[4];
    const int z = blockIdx.y;
    W += (size_t)z * wStride;
    v += (size_t)z * vStride;
    if (base) base += (size_t)z * baseStride;
    out += (size_t)z * outStride;
    const int row = blockIdx.x;
    const int t = threadIdx.x, lane = t & 31, warp = t >> 5;
    const float* wr = W + (size_t)row * ldw + coff;
    float s = 0.f;
    for (int k = t; k < K; k += 128) s += wr[k] * v[k];
#pragma unroll
    for (int o = 16; o; o >>= 1) s += __shfl_down_sync(0xffffffffu, s, o);
    if (lane == 0) red[warp] = s;
    __syncthreads();
    if (t == 0) out[row] = red[0] + red[1] + red[2] + red[3] + (base ? base[row] : 0.f);
}

// ---------------- compaction scan ----------------
__global__ __launch_bounds__(1024) void scan_kernel(
    const int* __restrict__ lens, int* __restrict__ off, int* __restrict__ total)
{
    __shared__ int wsum[32];
    const int tid = threadIdx.x, lane = tid & 31, warp = tid >> 5;
    int v[4], s = 0;
#pragma unroll
    for (int i = 0; i < 4; i++) { v[i] = lens[tid * 4 + i]; s += v[i]; }
    int ws = s;
#pragma unroll
    for (int o = 1; o < 32; o <<= 1) { int t = __shfl_up_sync(0xffffffffu, ws, o); if (lane >= o) ws += t; }
    if (lane == 31) wsum[warp] = ws;
    __syncthreads();
    if (warp == 0) {
        int t = wsum[lane];
#pragma unroll
        for (int o = 1; o < 32; o <<= 1) { int u = __shfl_up_sync(0xffffffffu, t, o); if (lane >= o) t += u; }
        wsum[lane] = t;
    }
    __syncthreads();
    int run = ws - s + (warp ? wsum[warp - 1] : 0);
#pragma unroll
    for (int i = 0; i < 4; i++) { off[tid * 4 + i] = run; run += v[i]; }
    if (tid == 1023) { off[NS] = run; total[0] = run; }
}

__global__ __launch_bounds__(32) void fill_rows_kernel(
    const int* __restrict__ lens, const int* __restrict__ off,
    const int* __restrict__ toks, int* __restrict__ rowtok)
{
    const int b = blockIdx.x;
    const int len = lens[b], o = off[b];
    for (int s = threadIdx.x; s < len; s += 32) rowtok[o + s] = toks[b * LS + s];
}

__global__ __launch_bounds__(128) void gather_split_kernel(
    const float* __restrict__ wte, const int* __restrict__ rowtok,
    const int* __restrict__ total,
    __half* __restrict__ Ah, __half* __restrict__ Al)
{
    const int r = blockIdx.x;
    if (r >= total[0]) return;
    const float2* src = reinterpret_cast<const float2*>(wte + (size_t)rowtok[r] * DE);
    uint32_t* dh = reinterpret_cast<uint32_t*>(Ah) + (size_t)r * (DE / 2);
    uint32_t* dl = reinterpret_cast<uint32_t*>(Al) + (size_t)r * (DE / 2);
#pragma unroll
    for (int i = 0; i < 3; i++) {
        const int j = threadIdx.x + 128 * i;
        const float2 v = src[j];
        uint32_t p, q;
        split2(v.x, v.y, p, q);
        dh[j] = p; dl[j] = q;
    }
}

// ================= HMMA GEMM: C[M,N] = A[M,K] @ B[N,K]^T + bias (+rs*bias2) (+RES) =================
// fp16 2-term: C = (Ah + Al) @ Bh^T.  RESID: residual read as fp16 hi/lo pair.
#define CHUNK  64
#define STG_BYTES (80 * 1024)
#define OFF_AH 0
#define OFF_AL 32768
#define OFF_BH 65536
#define TG_SMEM  (2 * STG_BYTES + 256)

template<int AMODE, int BMODE, bool RELU, bool WF32, bool WSPLIT, bool MDYN, bool HASB2, bool NDYN, bool RESID>
__global__ __launch_bounds__(256, 1) void tgemm_kernel(
    int M, int N, int K, int K1,
    const __half* __restrict__ Ah, const __half* __restrict__ Al, int lda,
    const __half* __restrict__ A2h, const __half* __restrict__ A2l, int lda2,
    const int* __restrict__ Mlim,
    const __half* __restrict__ Bh, int ldb,
    const __half* __restrict__ B2h, int ldb2,
    const float* __restrict__ bias, const float* __restrict__ bias2,
    const int* __restrict__ rowscale,
    float* __restrict__ C,
    __half* __restrict__ Ch, __half* __restrict__ Cl,
    size_t strideA, size_t strideB, size_t strideC,
    int ldc, int Nlim, size_t strideB2,
    const __half* __restrict__ RESh, const __half* __restrict__ RESl)
{
    extern __shared__ char smem[];
    const uint32_t sb = smem_u32(smem);

    const int z = blockIdx.z;
    if (strideA) { Ah += (size_t)z * strideA; Al += (size_t)z * strideA; }
    if (strideB) { Bh += (size_t)z * strideB; }
    if (strideC) { Ch += (size_t)z * strideC; if (Cl) Cl += (size_t)z * strideC; }
    if (HASB2 && strideB2) bias2 += (size_t)z * strideB2;

    const int tid  = threadIdx.x;
    const int lane = tid & 31;
    const int wid  = tid >> 5;
    const int bm = blockIdx.y * 256, bn = blockIdx.x * 128;

    int Mtot = M;
    if (MDYN) {
        Mtot = Mlim[0];
        if (bm >= Mtot) return;
    }

    const int nch = K / CHUNK;

    auto issue_stage = [&](int c) {
        const int k0 = c * CHUNK;
        const uint32_t st = sb + (c & 1) * STG_BYTES;
#pragma unroll
        for (int i = 0; i < 8; i++) {
            const int idx = tid + 256 * i;
            const int row = idx >> 3;
            const int seg = idx & 7;
            const uint32_t sw = sw128(row * 128 + seg * 16);
            int ar = bm + row;
            if (MDYN && ar >= Mtot) ar = Mtot - 1;
            const __half *pah, *pal;
            if (AMODE == 2 && k0 >= K1) {
                const size_t off = (size_t)ar * lda2 + (k0 - K1) + seg * 8;
                pah = A2h + off; pal = A2l + off;
            } else {
                const size_t off = (size_t)ar * lda + k0 + seg * 8;
                pah = Ah + off; pal = Al + off;
            }
            CP_ASYNC16(st + OFF_AH + sw, pah);
            CP_ASYNC16(st + OFF_AL + sw, pal);
        }
#pragma unroll
        for (int i = 0; i < 4; i++) {
            const int idx = tid + 256 * i;
            const int row = idx >> 3;
            const int seg = idx & 7;
            const uint32_t sw = sw128(row * 128 + seg * 16);
            int br = bn + row;
            if (NDYN && br >= Nlim) br = Nlim - 1;
            const __half* pbh;
            if (BMODE == 2 && k0 >= K1) {
                pbh = B2h + (size_t)br * ldb2 + (k0 - K1) + seg * 8;
            } else {
                pbh = Bh + (size_t)br * ldb + k0 + seg * 8;
            }
            CP_ASYNC16(st + OFF_BH + sw, pbh);
        }
        CP_COMMIT();
    };

    issue_stage(0);

    const int wm = (wid >> 1) * 64;
    const int wn = (wid & 1) * 64;

    float acc[4][8][4];
#pragma unroll
    for (int i = 0; i < 4; i++)
#pragma unroll
        for (int j = 0; j < 8; j++)
#pragma unroll
            for (int t = 0; t < 4; t++) acc[i][j][t] = 0.f;

    const int a_row  = (lane & 15);
    const int a_kb   = (lane >> 4) * 16;
    const int b_row  = (lane & 7) + ((lane >> 4) << 3);
    const int b_kb   = ((lane >> 3) & 1) * 16;

    for (int c = 0; c < nch; c++) {
        CP_WAIT(0);
        __syncthreads();
        if (c + 1 < nch) issue_stage(c + 1);

        const uint32_t st = sb + (c & 1) * STG_BYTES;

#pragma unroll
        for (int ks = 0; ks < 4; ks++) {
            const int kb = ks * 32;
            uint32_t ah[4][4], al[4][4];
#pragma unroll
            for (int i = 0; i < 4; i++) {
                const uint32_t oa = sw128((wm + i * 16 + a_row) * 128 + kb + a_kb);
                LDSM4(ah[i], st + OFF_AH + oa);
                LDSM4(al[i], st + OFF_AL + oa);
            }
            uint32_t bf[4][4];
#pragma unroll
            for (int j2 = 0; j2 < 4; j2++) {
                const uint32_t ob = sw128((wn + j2 * 16 + b_row) * 128 + kb + b_kb);
                LDSM4(bf[j2], st + OFF_BH + ob);
            }
            // (Ah + Al) * Bh
#pragma unroll
            for (int i = 0; i < 4; i++)
#pragma unroll
                for (int j2 = 0; j2 < 4; j2++) {
                    mma16816(acc[i][2 * j2 + 0], ah[i], bf[j2][0], bf[j2][1]);
                    mma16816(acc[i][2 * j2 + 1], ah[i], bf[j2][2], bf[j2][3]);
                    mma16816(acc[i][2 * j2 + 0], al[i], bf[j2][0], bf[j2][1]);
                    mma16816(acc[i][2 * j2 + 1], al[i], bf[j2][2], bf[j2][3]);
                }
        }
    }

    // ---- epilogue ----
#pragma unroll
    for (int i = 0; i < 4; i++) {
        const int r0 = bm + wm + i * 16 + (lane >> 2);
        const int r1 = r0 + 8;
        const bool ok0 = !MDYN || (r0 < Mtot);
        const bool ok1 = !MDYN || (r1 < Mtot);
        const float rs0 = HASB2 ? (float)rowscale[r0] : 0.f;
        const float rs1 = HASB2 ? (float)rowscale[r1] : 0.f;
#pragma unroll
        for (int j = 0; j < 8; j++) {
            const int col = bn + wn + j * 8 + (lane & 3) * 2;
            const bool okc = !NDYN || (col < Nlim);
            float b00 = bias[col], b01 = bias[col + 1];
            float b10 = b00, b11 = b01;
            if (HASB2) {
                b00 += rs0 * bias2[col]; b01 += rs0 * bias2[col + 1];
                b10 += rs1 * bias2[col]; b11 += rs1 * bias2[col + 1];
            }
            float2 v0 = make_float2(acc[i][j][0] + b00, acc[i][j][1] + b01);
            float2 v1 = make_float2(acc[i][j][2] + b10, acc[i][j][3] + b11);
            if (RESID) {
                const uint32_t uh0 = *reinterpret_cast<const uint32_t*>(RESh + (size_t)r0 * ldc + col);
                const uint32_t ul0 = *reinterpret_cast<const uint32_t*>(RESl + (size_t)r0 * ldc + col);
                const uint32_t uh1 = *reinterpret_cast<const uint32_t*>(RESh + (size_t)r1 * ldc + col);
                const uint32_t ul1 = *reinterpret_cast<const uint32_t*>(RESl + (size_t)r1 * ldc + col);
                const float2 e0 = recon2(uh0, ul0);
                const float2 e1 = recon2(uh1, ul1);
                v0.x += e0.x; v0.y += e0.y;
                v1.x += e1.x; v1.y += e1.y;
            }
            if (RELU) {
                v0.x = fmaxf(v0.x, 0.f); v0.y = fmaxf(v0.y, 0.f);
                v1.x = fmaxf(v1.x, 0.f); v1.y = fmaxf(v1.y, 0.f);
            }
            if (WF32) {
                if (ok0 && okc) *reinterpret_cast<float2*>(C + (size_t)r0 * ldc + col) = v0;
                if (ok1 && okc) *reinterpret_cast<float2*>(C + (size_t)r1 * ldc + col) = v1;
            }
            if (WSPLIT) {
                uint32_t p, q;
                if (ok0 && okc) {
                    split2(v0.x, v0.y, p, q);
                    reinterpret_cast<uint32_t*>(Ch)[((size_t)r0 * ldc + col) >> 1] = p;
                    if (Cl) reinterpret_cast<uint32_t*>(Cl)[((size_t)r0 * ldc + col) >> 1] = q;
                }
                if (ok1 && okc) {
                    split2(v1.x, v1.y, p, q);
                    reinterpret_cast<uint32_t*>(Ch)[((size_t)r1 * ldc + col) >> 1] = p;
                    if (Cl) reinterpret_cast<uint32_t*>(Cl)[((size_t)r1 * ldc + col) >> 1] = q;
                }
            }
        }
    }
}

// ---------------- name attention: block per (head, sample); emits CE ----------------
__global__ __launch_bounds__(192) void name_attn_kernel(
    const float* __restrict__ qk, const int* __restrict__ off,
    const __half* __restrict__ eh, const __half* __restrict__ el,
    __half* __restrict__ CEh, __half* __restrict__ CEl)
{
    __shared__ float Qs[LS][DHN];
    __shared__ float Ks[LS][DHN];
    __shared__ float sc[LS][LS + 1];
    __shared__ float cw[LS];

    const int h = blockIdx.x;
    const int b = blockIdx.y;
    const int d = threadIdx.x;

    const int o   = off[b];
    const int len = off[b + 1] - o;

    const float* base = qk + (size_t)o * (2 * DE) + h * DHN + d;
    for (int s = 0; s < len; s++) {
        Qs[s][d] = base[s * (2 * DE)];
        Ks[s][d] = base[s * (2 * DE) + DE];
    }
    if (d < LS) cw[d] = 0.f;
    __syncthreads();

    const int warp = d >> 5, lane = d & 31;
    const float scale = 1.0f / sqrtf((float)DHN);
    const int np = len * len;
    for (int p = warp; p < np; p += 6) {
        const int q = p / len, j = p - q * len;
        float s = 0.f;
#pragma unroll
        for (int i = 0; i < 6; i++) s += Qs[q][lane + 32 * i] * Ks[j][lane + 32 * i];
#pragma unroll
        for (int ofs = 16; ofs; ofs >>= 1) s += __shfl_down_sync(0xffffffffu, s, ofs);
        if (lane == 0) sc[q][j] = s * scale;
    }
    __syncthreads();

    if (d < len) {
        float mx = -1e30f;
        for (int j = 0; j < len; j++) mx = fmaxf(mx, sc[d][j]);
        float sum = 0.f;
        float row[LS];
        for (int j = 0; j < len; j++) { row[j] = expf(sc[d][j] - mx); sum += row[j]; }
        const float inv = 1.f / sum;
        for (int j = 0; j < len; j++) sc[d][j] = row[j] * inv;
    }
    __syncthreads();

    if (d < len) {
        float c = 0.f;
        for (int s = 0; s < len; s++) c += sc[s][d];
        cw[d] = c;
    }
    __syncthreads();

    const uint32_t* ehp = reinterpret_cast<const uint32_t*>(eh);
    const uint32_t* elp = reinterpret_cast<const uint32_t*>(el);
    for (int p = d; p < DE / 2; p += 192) {
        float ce0 = 0.f, ce1 = 0.f;
        for (int j = 0; j < len; j++) {
            const size_t idx = (size_t)(o + j) * (DE / 2) + p;
            const float2 e = recon2(ehp[idx], elp[idx]);
            ce0 += cw[j] * e.x;
            ce1 += cw[j] * e.y;
        }
        uint32_t P, Q;
        split2(ce0, ce1, P, Q);
        const size_t id2 = (size_t)b * (NHN * DE / 2) + h * (DE / 2) + p;
        reinterpret_cast<uint32_t*>(CEh)[id2] = P;
        reinterpret_cast<uint32_t*>(CEl)[id2] = Q;
    }
}

// ---------------- LayerNorm of ta (residual pre-added); writes fp16 hi/lo only ----------------
__device__ __forceinline__ float block_reduce_sum(float v) {
    __shared__ float red[8];
    const int lane = threadIdx.x & 31, warp = threadIdx.x >> 5;
#pragma unroll
    for (int o = 16; o; o >>= 1) v += __shfl_down_sync(0xffffffffu, v, o);
    if (lane == 0) red[warp] = v;
    __syncthreads();
    v = (threadIdx.x < 8) ? red[threadIdx.x] : 0.f;
    if (warp == 0)
#pragma unroll
        for (int o = 4; o; o >>= 1) v += __shfl_down_sync(0xffffffffu, v, o);
    return v;
}

template<bool WRITEH, bool DOCLS>
__global__ __launch_bounds__(256) void ln_kernel(
    const float* __restrict__ ta,
    const float* __restrict__ g, const float* __restrict__ b,
    __half* __restrict__ hh, __half* __restrict__ hl,
    const float* __restrict__ clsw, const float* __restrict__ clsb,
    float* __restrict__ out)
{
    const int row = blockIdx.x;
    const int t = threadIdx.x;
    float v[4];
    float s = 0.f;
#pragma unroll
    for (int i = 0; i < 4; i++) {
        const int c = t + 256 * i;
        v[i] = ta[(size_t)row * HD + c];
        s += v[i];
    }
    s = block_reduce_sum(s);
    __shared__ float mean_s, rstd_s;
    if (t == 0) mean_s = s * (1.f / HD);
    __syncthreads();
    const float m = mean_s;
    float s2 = 0.f;
#pragma unroll
    for (int i = 0; i < 4; i++) { const float dd = v[i] - m; s2 += dd * dd; }
    s2 = block_reduce_sum(s2);
    if (t == 0) rstd_s = rsqrtf(s2 * (1.f / HD) + 1e-5f);
    __syncthreads();
    const float r = rstd_s;

    __shared__ float ys[HD];
#pragma unroll
    for (int i = 0; i < 4; i++) {
        const int c = t + 256 * i;
        const float y = (v[i] - m) * r * g[c] + b[c];
        if (WRITEH) {
            const float y1 = __shfl_down_sync(0xffffffffu, y, 1);
            if (!(t & 1)) {
                uint32_t p, q;
                split2(y, y1, p, q);
                const size_t id2 = ((size_t)row * HD + c) >> 1;
                reinterpret_cast<uint32_t*>(hh)[id2] = p;
                reinterpret_cast<uint32_t*>(hl)[id2] = q;
            }
        }
        if (DOCLS) ys[c] = y;
    }
    if (DOCLS) {
        __syncthreads();
        const int warp = t >> 5, lane = t & 31;
        for (int cc = warp; cc < NCLS; cc += 8) {
            const float* wr = clsw + (size_t)cc * HD;
            float sum = 0.f;
#pragma unroll
            for (int i = lane; i < HD; i += 32) sum += ys[i] * wr[i];
#pragma unroll
            for (int o = 16; o; o >>= 1) sum += __shfl_down_sync(0xffffffffu, sum, o);
            if (lane == 0) out[(size_t)row * NCLS + cc] = sum + clsb[cc];
        }
    }
}

// ---------------- orchestration ----------------
static inline void launch_split_s(cudaStream_t st, const float* src,
                                  __half* hi, __half* lo, size_t n) {
    const int n2 = (int)(n / 2);
    split_kernel<<<(n2 + 255) / 256, 256, 0, st>>>(src, hi, lo, n2);
}

extern "C" void kernel_launch(void* const* d_in, const int* in_sizes, int n_in,
                              void* d_out, int out_size)
{
    const int*   name_tokens = (const int*)d_in[0];
    const int*   name_lens   = (const int*)d_in[1];
    const float* x_feats     = (const float*)d_in[2];
    const float* wte         = (const float*)d_in[3];
    const float* mha_in_w    = (const float*)d_in[4];
    const float* mha_in_b    = (const float*)d_in[5];
    const float* mha_out_w   = (const float*)d_in[6];
    const float* mha_out_b   = (const float*)d_in[7];
    const float* bott_w      = (const float*)d_in[8];
    const float* bott_b      = (const float*)d_in[9];
    const float* enc_in_w    = (const float*)d_in[10];
    const float* enc_in_b    = (const float*)d_in[11];
    const float* enc_out_w   = (const float*)d_in[12];
    const float* enc_out_b   = (const float*)d_in[13];
    const float* enc_ln1_g   = (const float*)d_in[14];
    const float* enc_ln1_b   = (const float*)d_in[15];
    const float* enc_ln2_g   = (const float*)d_in[16];
    const float* enc_ln2_b   = (const float*)d_in[17];
    const float* enc_ff1_w   = (const float*)d_in[18];
    const float* enc_ff1_b   = (const float*)d_in[19];
    const float* enc_ff2_w   = (const float*)d_in[20];
    const float* enc_ff2_b   = (const float*)d_in[21];
    const float* cls_w       = (const float*)d_in[22];
    const float* cls_b       = (const float*)d_in[23];
    float* out = (float*)d_out;

    float *qkv, *ta, *zero, *bc, *bao;
    int *off, *total, *rowtok;
    cudaGetSymbolAddress((void**)&qkv,    g_qkv);
    cudaGetSymbolAddress((void**)&ta,     g_ta);
    cudaGetSymbolAddress((void**)&zero,   g_zero);
    cudaGetSymbolAddress((void**)&bc,     g_bc);
    cudaGetSymbolAddress((void**)&bao,    g_bao);
    cudaGetSymbolAddress((void**)&off,    g_off);
    cudaGetSymbolAddress((void**)&total,  g_total);
    cudaGetSymbolAddress((void**)&rowtok, g_rowtok);

    __half *gah, *gal, *ce_h, *ce_l, *attn_h, *attn_l, *xf_h, *xf_l, *hh, *hl, *t1_h, *t1_l;
    __half *wqkv_h, *wbott_h, *wbott_l, *wo_h, *wo_l, *wf1_h, *wf2_h;
    __half *wvt_h, *woutt_h, *wc_h, *wao_h;
    cudaGetSymbolAddress((void**)&gah,    g_gah);     cudaGetSymbolAddress((void**)&gal,    g_gal);
    cudaGetSymbolAddress((void**)&ce_h,   g_ce_h);    cudaGetSymbolAddress((void**)&ce_l,   g_ce_l);
    cudaGetSymbolAddress((void**)&attn_h, g_attn_h);  cudaGetSymbolAddress((void**)&attn_l, g_attn_l);
    cudaGetSymbolAddress((void**)&xf_h,   g_xf_h);    cudaGetSymbolAddress((void**)&xf_l,   g_xf_l);
    cudaGetSymbolAddress((void**)&hh,     g_hh);      cudaGetSymbolAddress((void**)&hl,     g_hl);
    cudaGetSymbolAddress((void**)&t1_h,   g_t1_h);    cudaGetSymbolAddress((void**)&t1_l,   g_t1_l);
    cudaGetSymbolAddress((void**)&wqkv_h, g_wqkv_h);
    cudaGetSymbolAddress((void**)&wbott_h,g_wbott_h); cudaGetSymbolAddress((void**)&wbott_l,g_wbott_l);
    cudaGetSymbolAddress((void**)&wo_h,   g_wo_h);    cudaGetSymbolAddress((void**)&wo_l,   g_wo_l);
    cudaGetSymbolAddress((void**)&wf1_h,  g_wf1_h);
    cudaGetSymbolAddress((void**)&wf2_h,  g_wf2_h);
    cudaGetSymbolAddress((void**)&wvt_h,  g_wvt_h);
    cudaGetSymbolAddress((void**)&woutt_h,g_woutt_h);
    cudaGetSymbolAddress((void**)&wc_h,   g_wc_h);
    cudaGetSymbolAddress((void**)&wao_h,  g_wao_h);

    auto k_qk    = tgemm_kernel<0, 0, false, true,  false, true,  false, false, false>;
    auto k_csum  = tgemm_kernel<0, 0, false, false, true,  false, true,  true,  false>;
    auto k_bott  = tgemm_kernel<2, 2, false, false, true,  false, true,  false, false>;
    auto k_resid = tgemm_kernel<0, 0, false, true,  false, false, false, false, true >;
    auto k_ff1   = tgemm_kernel<0, 0, true,  false, true,  false, false, false, false>;
    auto k_pre   = tgemm_kernel<0, 0, false, false, true,  false, false, false, false>;
    cudaFuncSetAttribute(k_qk,    cudaFuncAttributeMaxDynamicSharedMemorySize, TG_SMEM);
    cudaFuncSetAttribute(k_csum,  cudaFuncAttributeMaxDynamicSharedMemorySize, TG_SMEM);
    cudaFuncSetAttribute(k_bott,  cudaFuncAttributeMaxDynamicSharedMemorySize, TG_SMEM);
    cudaFuncSetAttribute(k_resid, cudaFuncAttributeMaxDynamicSharedMemorySize, TG_SMEM);
    cudaFuncSetAttribute(k_ff1,   cudaFuncAttributeMaxDynamicSharedMemorySize, TG_SMEM);
    cudaFuncSetAttribute(k_pre,   cudaFuncAttributeMaxDynamicSharedMemorySize, TG_SMEM);

    cudaStream_t side = 0;
    cudaEvent_t evFork = 0, evJoin = 0;
    bool use_side = (cudaStreamCreateWithFlags(&side, cudaStreamNonBlocking) == cudaSuccess)
                 && (cudaEventCreateWithFlags(&evFork, cudaEventDisableTiming) == cudaSuccess)
                 && (cudaEventCreateWithFlags(&evJoin, cudaEventDisableTiming) == cudaSuccess);
    cudaStream_t prepSt = use_side ? side : (cudaStream_t)0;

    // ---- main-path prep ----
    scan_kernel<<<1, 1024>>>(name_lens, off, total);
    fill_rows_kernel<<<NS, 32>>>(name_lens, off, name_tokens, rowtok);
    gather_split_kernel<<<NS * LS, 128>>>(wte, rowtok, total, gah, gal);
    launch_split_s(0, mha_in_w, wqkv_h, nullptr, (size_t)3 * DE * DE);
    launch_split_s(0, bott_w,   wbott_h, wbott_l, (size_t)HD * (XFD + DE));
    launch_split_s(0, x_feats,  xf_h, xf_l, (size_t)NS * XFD);
    transpose_split_kernel<<<dim3(DE / 32, DE / 32, 1), dim3(32, 8)>>>(
        mha_out_w, DE, DE, woutt_h, nullptr, 0, 0);
    bias_fold_kernel<<<dim3(HD, 1), 128>>>(
        bott_w, XFD + DE, XFD, mha_out_b, nullptr, bao, DE, 0, 0, 0, 0);

    // ---- fork: encoder-weight prep on side stream ----
    if (use_side) {
        cudaEventRecord(evFork, 0);
        cudaStreamWaitEvent(side, evFork, 0);
    }
    launch_split_s(prepSt, enc_out_w, wo_h,  wo_l,  (size_t)NLAY * HD * HD);
    launch_split_s(prepSt, enc_ff1_w, wf1_h, nullptr, (size_t)NLAY * 2 * HD * HD);
    launch_split_s(prepSt, enc_ff2_w, wf2_h, nullptr, (size_t)NLAY * HD * 2 * HD);
    transpose_split_kernel<<<dim3(HD / 32, HD / 32, NLAY), dim3(32, 8), 0, prepSt>>>(
        enc_in_w + (size_t)2 * HD * HD, HD, HD, wvt_h, nullptr,
        (size_t)3 * HD * HD, (size_t)HD * HD);
    bias_fold_kernel<<<dim3(HD, NLAY), 128, 0, prepSt>>>(
        enc_out_w, HD, 0, enc_in_b + 2 * HD, enc_out_b, bc, HD,
        (size_t)HD * HD, (size_t)3 * HD, (size_t)HD, (size_t)HD);
    k_pre<<<dim3(HD / 128, HD / 256, NLAY), 256, TG_SMEM, prepSt>>>(
        HD, HD, HD, 0,
        wo_h, wo_l, HD, nullptr, nullptr, 0, nullptr,
        wvt_h, HD, nullptr, 0,
        zero, nullptr, nullptr,
        nullptr, wc_h, nullptr,
        (size_t)HD * HD, (size_t)HD * HD, (size_t)HD * HD, HD, HD, 0, nullptr, nullptr);
    k_pre<<<dim3(DE / 128, HD / 256, 1), 256, TG_SMEM, prepSt>>>(
        HD, DE, DE, 0,
        wbott_h + XFD, wbott_l + XFD, XFD + DE, nullptr, nullptr, 0, nullptr,
        woutt_h, DE, nullptr, 0,
        zero, nullptr, nullptr,
        nullptr, wao_h, nullptr, 0, 0, 0, DE, DE, 0, nullptr, nullptr);
    if (use_side) cudaEventRecord(evJoin, side);

    const int MQ = NS * LS;
    const int KQ = DE;
    const int NQ = 2 * DE;       // Q,K only

    // 1. qk(compact) = gathered_emb @ [Wq;Wk]^T + bias
    k_qk<<<dim3(NQ / 128, MQ / 256, 1), 256, TG_SMEM>>>(
        MQ, NQ, KQ, 0,
        gah, gal, KQ, nullptr, nullptr, 0, total,
        wqkv_h, KQ, nullptr, 0,
        mha_in_b, nullptr, nullptr, qkv, nullptr, nullptr, 0, 0, 0, NQ, NQ, 0, nullptr, nullptr);

    // 2. attention weights -> per-head mixed embeddings CE [4096 x 4 x 768]
    name_attn_kernel<<<dim3(NHN, NS), 192>>>(qkv, off, gah, gal, ce_h, ce_l);

    // 2b. attnsum_h = CE_h @ Wv_h^T + len*bv_h
    k_csum<<<dim3(2, NS / 256, NHN), 256, TG_SMEM>>>(
        NS, DHN, DE, 0,
        ce_h, ce_l, NHN * DE, nullptr, nullptr, 0, nullptr,
        wqkv_h + (size_t)2 * DE * DE, DE, nullptr, 0,
        zero, mha_in_b + 2 * DE, name_lens,
        nullptr, attn_h, attn_l,
        (size_t)DE, (size_t)DHN * DE, (size_t)DHN,
        DE, DHN, (size_t)DHN, nullptr, nullptr);

    // ---- join ----
    if (use_side) cudaStreamWaitEvent(0, evJoin, 0);

    // 3. x = xf@Wb1^T + attnsum@Wao^T + bbott + len*bao -> hh/hl split only
    k_bott<<<dim3(HD / 128, NS / 256, 1), 256, TG_SMEM>>>(
        NS, HD, XFD + DE, XFD,
        xf_h, xf_l, XFD, attn_h, attn_l, DE, nullptr,
        wbott_h, XFD + DE, wao_h, DE,
        bott_b, bao, name_lens, nullptr, hh, hl, 0, 0, 0, HD, HD, 0, nullptr, nullptr);

    // 4. encoder layers (residual read from hi/lo; LN writes hi/lo only)
    for (int l = 0; l < NLAY; l++) {
        k_resid<<<dim3(HD / 128, NS / 256, 1), 256, TG_SMEM>>>(
            NS, HD, HD, 0,
            hh, hl, HD, nullptr, nullptr, 0, nullptr,
            wc_h + (size_t)l * HD * HD, HD, nullptr, 0,
            bc + (size_t)l * HD, nullptr, nullptr, ta, nullptr, nullptr, 0, 0, 0, HD, HD, 0, hh, hl);
        ln_kernel<true, false><<<NS, 256>>>(
            ta, enc_ln1_g + (size_t)l * HD, enc_ln1_b + (size_t)l * HD,
            hh, hl, nullptr, nullptr, nullptr);

        k_ff1<<<dim3(2 * HD / 128, NS / 256, 1), 256, TG_SMEM>>>(
            NS, 2 * HD, HD, 0,
            hh, hl, HD, nullptr, nullptr, 0, nullptr,
            wf1_h + (size_t)l * 2 * HD * HD, HD, nullptr, 0,
            enc_ff1_b + (size_t)l * 2 * HD, nullptr, nullptr, nullptr, t1_h, t1_l,
            0, 0, 0, 2 * HD, 2 * HD, 0, nullptr, nullptr);
        k_resid<<<dim3(HD / 128, NS / 256, 1), 256, TG_SMEM>>>(
            NS, HD, 2 * HD, 0,
            t1_h, t1_l, 2 * HD, nullptr, nullptr, 0, nullptr,
            wf2_h + (size_t)l * HD * 2 * HD, 2 * HD, nullptr, 0,
            enc_ff2_b + (size_t)l * HD, nullptr, nullptr, ta, nullptr, nullptr, 0, 0, 0, HD, HD, 0, hh, hl);
        if (l < NLAY - 1) {
            ln_kernel<true, false><<<NS, 256>>>(
                ta, enc_ln2_g + (size_t)l * HD, enc_ln2_b + (size_t)l * HD,
                hh, hl, nullptr, nullptr, nullptr);
        } else {
            // final LN fused with classifier head -> out [4096 x 16]
            ln_kernel<false, true><<<NS, 256>>>(
                ta, enc_ln2_g + (size_t)l * HD, enc_ln2_b + (size_t)l * HD,
                nullptr, nullptr, cls_w, cls_b, out);
        }
    }
}

// round 15
// speedup vs baseline: 1.4395x; 1.0184x over previous
#include <cuda_runtime.h>
#include <cuda_fp16.h>
#include <cstdint>
#include <math.h>

// ---------------- problem constants ----------------
#define NS    4096          // N samples
#define LS    16            // L tokens
#define DE    768           // D embedding
#define NHN   4             // heads (name attn)
#define DHN   192           // head dim (name attn)
#define HD    1024          // H
#define NLAY  4             // NL
#define NCLS  16            // C
#define XFD   256           // XF

// ---------------- scratch (device globals; no cudaMalloc allowed) ----------------
__device__ float g_qkv[(size_t)NS * LS * 2 * DE];   // compacted Q,K rows, fp32
__device__ float g_ta[(size_t)NS * HD];             // fp32 (pre-LN sum)

__device__ int g_off[NS + 1];
__device__ int g_total[1];
__device__ int g_rowtok[NS * LS];

__device__ float g_zero[4096];
__device__ float g_bc[NLAY * HD];
__device__ float g_bao[HD];

// fp16 hi/lo split buffers (activations)
__device__ __align__(16) __half g_gah[(size_t)NS * LS * DE],   g_gal[(size_t)NS * LS * DE];
__device__ __align__(16) __half g_ce_h[(size_t)NS * NHN * DE], g_ce_l[(size_t)NS * NHN * DE];
__device__ __align__(16) __half g_attn_h[(size_t)NS * DE],     g_attn_l[(size_t)NS * DE];
__device__ __align__(16) __half g_xf_h[(size_t)NS * XFD],      g_xf_l[(size_t)NS * XFD];
__device__ __align__(16) __half g_hh[(size_t)NS * HD],         g_hl[(size_t)NS * HD];
__device__ __align__(16) __half g_t1_h[(size_t)NS * 2 * HD],   g_t1_l[(size_t)NS * 2 * HD];

// fp16 split buffers (weights; lo only where read as A operand)
__device__ __align__(16) __half g_wqkv_h[(size_t)3 * DE * DE];                                   // B only
__device__ __align__(16) __half g_wbott_h[(size_t)HD * (XFD + DE)], g_wbott_l[(size_t)HD * (XFD + DE)];  // A+B
__device__ __align__(16) __half g_wo_h[(size_t)NLAY * HD * HD],  g_wo_l[(size_t)NLAY * HD * HD];  // A in fold
__device__ __align__(16) __half g_wf1_h[(size_t)NLAY * 2 * HD * HD];                             // B only
__device__ __align__(16) __half g_wf2_h[(size_t)NLAY * HD * 2 * HD];                             // B only
__device__ __align__(16) __half g_wvt_h[(size_t)NLAY * HD * HD];                                 // B only
__device__ __align__(16) __half g_woutt_h[(size_t)DE * DE];                                      // B only
__device__ __align__(16) __half g_wc_h[(size_t)NLAY * HD * HD];                                  // B only
__device__ __align__(16) __half g_wao_h[(size_t)HD * DE];                                        // B only

// ================= helpers =================
__device__ __forceinline__ uint32_t smem_u32(const void* p) {
    uint32_t a;
    asm("{ .reg .u64 t; cvta.to.shared.u64 t, %1; cvt.u32.u64 %0, t; }" : "=r"(a) : "l"(p));
    return a;
}
__device__ __forceinline__ uint32_t sw128(uint32_t o) { return o ^ ((o >> 3) & 0x70); }

#define LDSM4(r, addr) \
    asm volatile("ldmatrix.sync.aligned.m8n8.x4.shared.b16 {%0,%1,%2,%3}, [%4];" \
        : "=r"((r)[0]), "=r"((r)[1]), "=r"((r)[2]), "=r"((r)[3]) : "r"(addr))

__device__ __forceinline__ void mma16816(float* c, const uint32_t* a, uint32_t b0, uint32_t b1) {
    asm volatile("mma.sync.aligned.m16n8k16.row.col.f32.f16.f16.f32 "
        "{%0,%1,%2,%3},{%4,%5,%6,%7},{%8,%9},{%0,%1,%2,%3};"
        : "+f"(c[0]), "+f"(c[1]), "+f"(c[2]), "+f"(c[3])
        : "r"(a[0]), "r"(a[1]), "r"(a[2]), "r"(a[3]), "r"(b0), "r"(b1));
}

#define CP_ASYNC16(dst, src) \
    asm volatile("cp.async.cg.shared.global [%0], [%1], 16;" :: "r"(dst), "l"(src))
#define CP_COMMIT() asm volatile("cp.async.commit_group;" ::: "memory")
#define CP_WAIT(n)  asm volatile("cp.async.wait_group %0;" :: "n"(n) : "memory")

// split fp32 pair -> packed fp16 hi (p) and lo residual (q)
__device__ __forceinline__ void split2(float x, float y, uint32_t& p, uint32_t& q) {
    const __half hx = __float2half_rn(x), hy = __float2half_rn(y);
    __half2 hp = __halves2half2(hx, hy);
    p = *reinterpret_cast<uint32_t*>(&hp);
    const float r0 = x - __half2float(hx), r1 = y - __half2float(hy);
    __half2 hq = __halves2half2(__float2half_rn(r0), __float2half_rn(r1));
    q = *reinterpret_cast<uint32_t*>(&hq);
}

// reconstruct fp32 pair from packed hi/lo fp16
__device__ __forceinline__ float2 recon2(uint32_t uh, uint32_t ul) {
    const float2 a = __half22float2(*reinterpret_cast<__half2*>(&uh));
    const float2 b = __half22float2(*reinterpret_cast<__half2*>(&ul));
    return make_float2(a.x + b.x, a.y + b.y);
}

// ---------------- fp32 -> fp16 hi(/lo) split (lo nullable) ----------------
__global__ __launch_bounds__(256) void split_kernel(
    const float* __restrict__ src,
    __half* __restrict__ hi, __half* __restrict__ lo, int n2)
{
    const int i = blockIdx.x * blockDim.x + threadIdx.x;
    if (i < n2) {
        const float2 v = reinterpret_cast<const float2*>(src)[i];
        uint32_t p, q;
        split2(v.x, v.y, p, q);
        reinterpret_cast<uint32_t*>(hi)[i] = p;
        if (lo) reinterpret_cast<uint32_t*>(lo)[i] = q;
    }
}

// ---------------- batched fp32 [R x C] -> transposed fp16 hi(/lo) [C x R] ----------------
__global__ __launch_bounds__(256) void transpose_split_kernel(
    const float* __restrict__ src, int ld, int R,
    __half* __restrict__ dh, __half* __restrict__ dl,
    size_t srcStride, size_t dstStride)
{
    __shared__ float tile[32][33];
    const int z = blockIdx.z;
    src += (size_t)z * srcStride;
    dh  += (size_t)z * dstStride;
    if (dl) dl += (size_t)z * dstStride;
    const int c0 = blockIdx.x * 32, r0 = blockIdx.y * 32;
    const int tx = threadIdx.x, ty = threadIdx.y;   // (32, 8)
#pragma unroll
    for (int i = ty; i < 32; i += 8)
        tile[i][tx] = src[(size_t)(r0 + i) * ld + c0 + tx];
    __syncthreads();
    if (tx < 16) {
#pragma unroll
        for (int i = ty; i < 32; i += 8) {
            uint32_t p, q;
            split2(tile[2 * tx][i], tile[2 * tx + 1][i], p, q);
            const size_t id2 = ((size_t)(c0 + i) * R + r0) / 2 + tx;
            reinterpret_cast<uint32_t*>(dh)[id2] = p;
            if (dl) reinterpret_cast<uint32_t*>(dl)[id2] = q;
        }
    }
}

// ---------------- batched bias fold: out[row] = W[row,:]·v + base[row] ----------------
__global__ __launch_bounds__(128) void bias_fold_kernel(
    const float* __restrict__ W, int ldw, int coff,
    const float* __restrict__ v, const float* __restrict__ base,
    float* __restrict__ out, int K,
    size_t wStride, size_t vStride, size_t baseStride, size_t outStride)
{
    __shared__ float red[4];
    const int z = blockIdx.y;
    W += (size_t)z * wStride;
    v += (size_t)z * vStride;
    if (base) base += (size_t)z * baseStride;
    out += (size_t)z * outStride;
    const int row = blockIdx.x;
    const int t = threadIdx.x, lane = t & 31, warp = t >> 5;
    const float* wr = W + (size_t)row * ldw + coff;
    float s = 0.f;
    for (int k = t; k < K; k += 128) s += wr[k] * v[k];
#pragma unroll
    for (int o = 16; o; o >>= 1) s += __shfl_down_sync(0xffffffffu, s, o);
    if (lane == 0) red[warp] = s;
    __syncthreads();
    if (t == 0) out[row] = red[0] + red[1] + red[2] + red[3] + (base ? base[row] : 0.f);
}

// ---------------- compaction scan ----------------
__global__ __launch_bounds__(1024) void scan_kernel(
    const int* __restrict__ lens, int* __restrict__ off, int* __restrict__ total)
{
    __shared__ int wsum[32];
    const int tid = threadIdx.x, lane = tid & 31, warp = tid >> 5;
    int v[4], s = 0;
#pragma unroll
    for (int i = 0; i < 4; i++) { v[i] = lens[tid * 4 + i]; s += v[i]; }
    int ws = s;
#pragma unroll
    for (int o = 1; o < 32; o <<= 1) { int t = __shfl_up_sync(0xffffffffu, ws, o); if (lane >= o) ws += t; }
    if (lane == 31) wsum[warp] = ws;
    __syncthreads();
    if (warp == 0) {
        int t = wsum[lane];
#pragma unroll
        for (int o = 1; o < 32; o <<= 1) { int u = __shfl_up_sync(0xffffffffu, t, o); if (lane >= o) t += u; }
        wsum[lane] = t;
    }
    __syncthreads();
    int run = ws - s + (warp ? wsum[warp - 1] : 0);
#pragma unroll
    for (int i = 0; i < 4; i++) { off[tid * 4 + i] = run; run += v[i]; }
    if (tid == 1023) { off[NS] = run; total[0] = run; }
}

__global__ __launch_bounds__(32) void fill_rows_kernel(
    const int* __restrict__ lens, const int* __restrict__ off,
    const int* __restrict__ toks, int* __restrict__ rowtok)
{
    const int b = blockIdx.x;
    const int len = lens[b], o = off[b];
    for (int s = threadIdx.x; s < len; s += 32) rowtok[o + s] = toks[b * LS + s];
}

__global__ __launch_bounds__(128) void gather_split_kernel(
    const float* __restrict__ wte, const int* __restrict__ rowtok,
    const int* __restrict__ total,
    __half* __restrict__ Ah, __half* __restrict__ Al)
{
    const int r = blockIdx.x;
    if (r >= total[0]) return;
    const float2* src = reinterpret_cast<const float2*>(wte + (size_t)rowtok[r] * DE);
    uint32_t* dh = reinterpret_cast<uint32_t*>(Ah) + (size_t)r * (DE / 2);
    uint32_t* dl = reinterpret_cast<uint32_t*>(Al) + (size_t)r * (DE / 2);
#pragma unroll
    for (int i = 0; i < 3; i++) {
        const int j = threadIdx.x + 128 * i;
        const float2 v = src[j];
        uint32_t p, q;
        split2(v.x, v.y, p, q);
        dh[j] = p; dl[j] = q;
    }
}

// ================= HMMA GEMM: C[M,N] = A[M,K] @ B[N,K]^T + bias (+rs*bias2) (+RES) =================
// fp16 2-term: C = (Ah + Al) @ Bh^T.  CTA tile 128x128, warp 32x64, 2 CTAs/SM.
#define CHUNK  64
#define STG_BYTES (48 * 1024)
#define OFF_AH 0
#define OFF_AL 16384
#define OFF_BH 32768
#define TG_SMEM  (2 * STG_BYTES + 256)

template<int AMODE, int BMODE, bool RELU, bool WF32, bool WSPLIT, bool MDYN, bool HASB2, bool NDYN, bool RESID>
__global__ __launch_bounds__(256, 2) void tgemm_kernel(
    int M, int N, int K, int K1,
    const __half* __restrict__ Ah, const __half* __restrict__ Al, int lda,
    const __half* __restrict__ A2h, const __half* __restrict__ A2l, int lda2,
    const int* __restrict__ Mlim,
    const __half* __restrict__ Bh, int ldb,
    const __half* __restrict__ B2h, int ldb2,
    const float* __restrict__ bias, const float* __restrict__ bias2,
    const int* __restrict__ rowscale,
    float* __restrict__ C,
    __half* __restrict__ Ch, __half* __restrict__ Cl,
    size_t strideA, size_t strideB, size_t strideC,
    int ldc, int Nlim, size_t strideB2,
    const __half* __restrict__ RESh, const __half* __restrict__ RESl)
{
    extern __shared__ char smem[];
    const uint32_t sb = smem_u32(smem);

    const int z = blockIdx.z;
    if (strideA) { Ah += (size_t)z * strideA; Al += (size_t)z * strideA; }
    if (strideB) { Bh += (size_t)z * strideB; }
    if (strideC) { Ch += (size_t)z * strideC; if (Cl) Cl += (size_t)z * strideC; }
    if (HASB2 && strideB2) bias2 += (size_t)z * strideB2;

    const int tid  = threadIdx.x;
    const int lane = tid & 31;
    const int wid  = tid >> 5;
    const int bm = blockIdx.y * 128, bn = blockIdx.x * 128;

    int Mtot = M;
    if (MDYN) {
        Mtot = Mlim[0];
        if (bm >= Mtot) return;
    }

    const int nch = K / CHUNK;

    auto issue_stage = [&](int c) {
        const int k0 = c * CHUNK;
        const uint32_t st = sb + (c & 1) * STG_BYTES;
#pragma unroll
        for (int i = 0; i < 4; i++) {
            const int idx = tid + 256 * i;
            const int row = idx >> 3;          // 0..127
            const int seg = idx & 7;
            const uint32_t sw = sw128(row * 128 + seg * 16);
            int ar = bm + row;
            if (MDYN && ar >= Mtot) ar = Mtot - 1;
            const __half *pah, *pal;
            if (AMODE == 2 && k0 >= K1) {
                const size_t off = (size_t)ar * lda2 + (k0 - K1) + seg * 8;
                pah = A2h + off; pal = A2l + off;
            } else {
                const size_t off = (size_t)ar * lda + k0 + seg * 8;
                pah = Ah + off; pal = Al + off;
            }
            CP_ASYNC16(st + OFF_AH + sw, pah);
            CP_ASYNC16(st + OFF_AL + sw, pal);
        }
#pragma unroll
        for (int i = 0; i < 4; i++) {
            const int idx = tid + 256 * i;
            const int row = idx >> 3;
            const int seg = idx & 7;
            const uint32_t sw = sw128(row * 128 + seg * 16);
            int br = bn + row;
            if (NDYN && br >= Nlim) br = Nlim - 1;
            const __half* pbh;
            if (BMODE == 2 && k0 >= K1) {
                pbh = B2h + (size_t)br * ldb2 + (k0 - K1) + seg * 8;
            } else {
                pbh = Bh + (size_t)br * ldb + k0 + seg * 8;
            }
            CP_ASYNC16(st + OFF_BH + sw, pbh);
        }
        CP_COMMIT();
    };

    issue_stage(0);

    // warp tile 32 (M) x 64 (N); warps 4 (M) x 2 (N)
    const int wm = (wid >> 1) * 32;
    const int wn = (wid & 1) * 64;

    float acc[2][8][4];
#pragma unroll
    for (int i = 0; i < 2; i++)
#pragma unroll
        for (int j = 0; j < 8; j++)
#pragma unroll
            for (int t = 0; t < 4; t++) acc[i][j][t] = 0.f;

    const int a_row  = (lane & 15);
    const int a_kb   = (lane >> 4) * 16;
    const int b_row  = (lane & 7) + ((lane >> 4) << 3);
    const int b_kb   = ((lane >> 3) & 1) * 16;

    for (int c = 0; c < nch; c++) {
        CP_WAIT(0);
        __syncthreads();
        if (c + 1 < nch) issue_stage(c + 1);

        const uint32_t st = sb + (c & 1) * STG_BYTES;

#pragma unroll
        for (int ks = 0; ks < 4; ks++) {
            const int kb = ks * 32;
            uint32_t ah[2][4], al[2][4];
#pragma unroll
            for (int i = 0; i < 2; i++) {
                const uint32_t oa = sw128((wm + i * 16 + a_row) * 128 + kb + a_kb);
                LDSM4(ah[i], st + OFF_AH + oa);
                LDSM4(al[i], st + OFF_AL + oa);
            }
            uint32_t bf[4][4];
#pragma unroll
            for (int j2 = 0; j2 < 4; j2++) {
                const uint32_t ob = sw128((wn + j2 * 16 + b_row) * 128 + kb + b_kb);
                LDSM4(bf[j2], st + OFF_BH + ob);
            }
            // (Ah + Al) * Bh
#pragma unroll
            for (int i = 0; i < 2; i++)
#pragma unroll
                for (int j2 = 0; j2 < 4; j2++) {
                    mma16816(acc[i][2 * j2 + 0], ah[i], bf[j2][0], bf[j2][1]);
                    mma16816(acc[i][2 * j2 + 1], ah[i], bf[j2][2], bf[j2][3]);
                    mma16816(acc[i][2 * j2 + 0], al[i], bf[j2][0], bf[j2][1]);
                    mma16816(acc[i][2 * j2 + 1], al[i], bf[j2][2], bf[j2][3]);
                }
        }
    }

    // ---- epilogue ----
#pragma unroll
    for (int i = 0; i < 2; i++) {
        const int r0 = bm + wm + i * 16 + (lane >> 2);
        const int r1 = r0 + 8;
        const bool ok0 = !MDYN || (r0 < Mtot);
        const bool ok1 = !MDYN || (r1 < Mtot);
        const float rs0 = HASB2 ? (float)rowscale[r0] : 0.f;
        const float rs1 = HASB2 ? (float)rowscale[r1] : 0.f;
#pragma unroll
        for (int j = 0; j < 8; j++) {
            const int col = bn + wn + j * 8 + (lane & 3) * 2;
            const bool okc = !NDYN || (col < Nlim);
            float b00 = bias[col], b01 = bias[col + 1];
            float b10 = b00, b11 = b01;
            if (HASB2) {
                b00 += rs0 * bias2[col]; b01 += rs0 * bias2[col + 1];
                b10 += rs1 * bias2[col]; b11 += rs1 * bias2[col + 1];
            }
            float2 v0 = make_float2(acc[i][j][0] + b00, acc[i][j][1] + b01);
            float2 v1 = make_float2(acc[i][j][2] + b10, acc[i][j][3] + b11);
            if (RESID) {
                const uint32_t uh0 = *reinterpret_cast<const uint32_t*>(RESh + (size_t)r0 * ldc + col);
                const uint32_t ul0 = *reinterpret_cast<const uint32_t*>(RESl + (size_t)r0 * ldc + col);
                const uint32_t uh1 = *reinterpret_cast<const uint32_t*>(RESh + (size_t)r1 * ldc + col);
                const uint32_t ul1 = *reinterpret_cast<const uint32_t*>(RESl + (size_t)r1 * ldc + col);
                const float2 e0 = recon2(uh0, ul0);
                const float2 e1 = recon2(uh1, ul1);
                v0.x += e0.x; v0.y += e0.y;
                v1.x += e1.x; v1.y += e1.y;
            }
            if (RELU) {
                v0.x = fmaxf(v0.x, 0.f); v0.y = fmaxf(v0.y, 0.f);
                v1.x = fmaxf(v1.x, 0.f); v1.y = fmaxf(v1.y, 0.f);
            }
            if (WF32) {
                if (ok0 && okc) *reinterpret_cast<float2*>(C + (size_t)r0 * ldc + col) = v0;
                if (ok1 && okc) *reinterpret_cast<float2*>(C + (size_t)r1 * ldc + col) = v1;
            }
            if (WSPLIT) {
                uint32_t p, q;
                if (ok0 && okc) {
                    split2(v0.x, v0.y, p, q);
                    reinterpret_cast<uint32_t*>(Ch)[((size_t)r0 * ldc + col) >> 1] = p;
                    if (Cl) reinterpret_cast<uint32_t*>(Cl)[((size_t)r0 * ldc + col) >> 1] = q;
                }
                if (ok1 && okc) {
                    split2(v1.x, v1.y, p, q);
                    reinterpret_cast<uint32_t*>(Ch)[((size_t)r1 * ldc + col) >> 1] = p;
                    if (Cl) reinterpret_cast<uint32_t*>(Cl)[((size_t)r1 * ldc + col) >> 1] = q;
                }
            }
        }
    }
}

// ---------------- name attention: block per (head, sample); emits CE ----------------
__global__ __launch_bounds__(192) void name_attn_kernel(
    const float* __restrict__ qk, const int* __restrict__ off,
    const __half* __restrict__ eh, const __half* __restrict__ el,
    __half* __restrict__ CEh, __half* __restrict__ CEl)
{
    __shared__ float Qs[LS][DHN];
    __shared__ float Ks[LS][DHN];
    __shared__ float sc[LS][LS + 1];
    __shared__ float cw[LS];

    const int h = blockIdx.x;
    const int b = blockIdx.y;
    const int d = threadIdx.x;

    const int o   = off[b];
    const int len = off[b + 1] - o;

    const float* base = qk + (size_t)o * (2 * DE) + h * DHN + d;
    for (int s = 0; s < len; s++) {
        Qs[s][d] = base[s * (2 * DE)];
        Ks[s][d] = base[s * (2 * DE) + DE];
    }
    if (d < LS) cw[d] = 0.f;
    __syncthreads();

    const int warp = d >> 5, lane = d & 31;
    const float scale = 1.0f / sqrtf((float)DHN);
    const int np = len * len;
    for (int p = warp; p < np; p += 6) {
        const int q = p / len, j = p - q * len;
        float s = 0.f;
#pragma unroll
        for (int i = 0; i < 6; i++) s += Qs[q][lane + 32 * i] * Ks[j][lane + 32 * i];
#pragma unroll
        for (int ofs = 16; ofs; ofs >>= 1) s += __shfl_down_sync(0xffffffffu, s, ofs);
        if (lane == 0) sc[q][j] = s * scale;
    }
    __syncthreads();

    if (d < len) {
        float mx = -1e30f;
        for (int j = 0; j < len; j++) mx = fmaxf(mx, sc[d][j]);
        float sum = 0.f;
        float row[LS];
        for (int j = 0; j < len; j++) { row[j] = expf(sc[d][j] - mx); sum += row[j]; }
        const float inv = 1.f / sum;
        for (int j = 0; j < len; j++) sc[d][j] = row[j] * inv;
    }
    __syncthreads();

    if (d < len) {
        float c = 0.f;
        for (int s = 0; s < len; s++) c += sc[s][d];
        cw[d] = c;
    }
    __syncthreads();

    const uint32_t* ehp = reinterpret_cast<const uint32_t*>(eh);
    const uint32_t* elp = reinterpret_cast<const uint32_t*>(el);
    for (int p = d; p < DE / 2; p += 192) {
        float ce0 = 0.f, ce1 = 0.f;
        for (int j = 0; j < len; j++) {
            const size_t idx = (size_t)(o + j) * (DE / 2) + p;
            const float2 e = recon2(ehp[idx], elp[idx]);
            ce0 += cw[j] * e.x;
            ce1 += cw[j] * e.y;
        }
        uint32_t P, Q;
        split2(ce0, ce1, P, Q);
        const size_t id2 = (size_t)b * (NHN * DE / 2) + h * (DE / 2) + p;
        reinterpret_cast<uint32_t*>(CEh)[id2] = P;
        reinterpret_cast<uint32_t*>(CEl)[id2] = Q;
    }
}

// ---------------- LayerNorm of ta (residual pre-added); writes fp16 hi/lo only ----------------
__device__ __forceinline__ float block_reduce_sum(float v) {
    __shared__ float red[8];
    const int lane = threadIdx.x & 31, warp = threadIdx.x >> 5;
#pragma unroll
    for (int o = 16; o; o >>= 1) v += __shfl_down_sync(0xffffffffu, v, o);
    if (lane == 0) red[warp] = v;
    __syncthreads();
    v = (threadIdx.x < 8) ? red[threadIdx.x] : 0.f;
    if (warp == 0)
#pragma unroll
        for (int o = 4; o; o >>= 1) v += __shfl_down_sync(0xffffffffu, v, o);
    return v;
}

template<bool WRITEH, bool DOCLS>
__global__ __launch_bounds__(256) void ln_kernel(
    const float* __restrict__ ta,
    const float* __restrict__ g, const float* __restrict__ b,
    __half* __restrict__ hh, __half* __restrict__ hl,
    const float* __restrict__ clsw, const float* __restrict__ clsb,
    float* __restrict__ out)
{
    const int row = blockIdx.x;
    const int t = threadIdx.x;
    float v[4];
    float s = 0.f;
#pragma unroll
    for (int i = 0; i < 4; i++) {
        const int c = t + 256 * i;
        v[i] = ta[(size_t)row * HD + c];
        s += v[i];
    }
    s = block_reduce_sum(s);
    __shared__ float mean_s, rstd_s;
    if (t == 0) mean_s = s * (1.f / HD);
    __syncthreads();
    const float m = mean_s;
    float s2 = 0.f;
#pragma unroll
    for (int i = 0; i < 4; i++) { const float dd = v[i] - m; s2 += dd * dd; }
    s2 = block_reduce_sum(s2);
    if (t == 0) rstd_s = rsqrtf(s2 * (1.f / HD) + 1e-5f);
    __syncthreads();
    const float r = rstd_s;

    __shared__ float ys[HD];
#pragma unroll
    for (int i = 0; i < 4; i++) {
        const int c = t + 256 * i;
        const float y = (v[i] - m) * r * g[c] + b[c];
        if (WRITEH) {
            const float y1 = __shfl_down_sync(0xffffffffu, y, 1);
            if (!(t & 1)) {
                uint32_t p, q;
                split2(y, y1, p, q);
                const size_t id2 = ((size_t)row * HD + c) >> 1;
                reinterpret_cast<uint32_t*>(hh)[id2] = p;
                reinterpret_cast<uint32_t*>(hl)[id2] = q;
            }
        }
        if (DOCLS) ys[c] = y;
    }
    if (DOCLS) {
        __syncthreads();
        const int warp = t >> 5, lane = t & 31;
        for (int cc = warp; cc < NCLS; cc += 8) {
            const float* wr = clsw + (size_t)cc * HD;
            float sum = 0.f;
#pragma unroll
            for (int i = lane; i < HD; i += 32) sum += ys[i] * wr[i];
#pragma unroll
            for (int o = 16; o; o >>= 1) sum += __shfl_down_sync(0xffffffffu, sum, o);
            if (lane == 0) out[(size_t)row * NCLS + cc] = sum + clsb[cc];
        }
    }
}

// ---------------- orchestration ----------------
static inline void launch_split_s(cudaStream_t st, const float* src,
                                  __half* hi, __half* lo, size_t n) {
    const int n2 = (int)(n / 2);
    split_kernel<<<(n2 + 255) / 256, 256, 0, st>>>(src, hi, lo, n2);
}

extern "C" void kernel_launch(void* const* d_in, const int* in_sizes, int n_in,
                              void* d_out, int out_size)
{
    const int*   name_tokens = (const int*)d_in[0];
    const int*   name_lens   = (const int*)d_in[1];
    const float* x_feats     = (const float*)d_in[2];
    const float* wte         = (const float*)d_in[3];
    const float* mha_in_w    = (const float*)d_in[4];
    const float* mha_in_b    = (const float*)d_in[5];
    const float* mha_out_w   = (const float*)d_in[6];
    const float* mha_out_b   = (const float*)d_in[7];
    const float* bott_w      = (const float*)d_in[8];
    const float* bott_b      = (const float*)d_in[9];
    const float* enc_in_w    = (const float*)d_in[10];
    const float* enc_in_b    = (const float*)d_in[11];
    const float* enc_out_w   = (const float*)d_in[12];
    const float* enc_out_b   = (const float*)d_in[13];
    const float* enc_ln1_g   = (const float*)d_in[14];
    const float* enc_ln1_b   = (const float*)d_in[15];
    const float* enc_ln2_g   = (const float*)d_in[16];
    const float* enc_ln2_b   = (const float*)d_in[17];
    const float* enc_ff1_w   = (const float*)d_in[18];
    const float* enc_ff1_b   = (const float*)d_in[19];
    const float* enc_ff2_w   = (const float*)d_in[20];
    const float* enc_ff2_b   = (const float*)d_in[21];
    const float* cls_w       = (const float*)d_in[22];
    const float* cls_b       = (const float*)d_in[23];
    float* out = (float*)d_out;

    float *qkv, *ta, *zero, *bc, *bao;
    int *off, *total, *rowtok;
    cudaGetSymbolAddress((void**)&qkv,    g_qkv);
    cudaGetSymbolAddress((void**)&ta,     g_ta);
    cudaGetSymbolAddress((void**)&zero,   g_zero);
    cudaGetSymbolAddress((void**)&bc,     g_bc);
    cudaGetSymbolAddress((void**)&bao,    g_bao);
    cudaGetSymbolAddress((void**)&off,    g_off);
    cudaGetSymbolAddress((void**)&total,  g_total);
    cudaGetSymbolAddress((void**)&rowtok, g_rowtok);

    __half *gah, *gal, *ce_h, *ce_l, *attn_h, *attn_l, *xf_h, *xf_l, *hh, *hl, *t1_h, *t1_l;
    __half *wqkv_h, *wbott_h, *wbott_l, *wo_h, *wo_l, *wf1_h, *wf2_h;
    __half *wvt_h, *woutt_h, *wc_h, *wao_h;
    cudaGetSymbolAddress((void**)&gah,    g_gah);     cudaGetSymbolAddress((void**)&gal,    g_gal);
    cudaGetSymbolAddress((void**)&ce_h,   g_ce_h);    cudaGetSymbolAddress((void**)&ce_l,   g_ce_l);
    cudaGetSymbolAddress((void**)&attn_h, g_attn_h);  cudaGetSymbolAddress((void**)&attn_l, g_attn_l);
    cudaGetSymbolAddress((void**)&xf_h,   g_xf_h);    cudaGetSymbolAddress((void**)&xf_l,   g_xf_l);
    cudaGetSymbolAddress((void**)&hh,     g_hh);      cudaGetSymbolAddress((void**)&hl,     g_hl);
    cudaGetSymbolAddress((void**)&t1_h,   g_t1_h);    cudaGetSymbolAddress((void**)&t1_l,   g_t1_l);
    cudaGetSymbolAddress((void**)&wqkv_h, g_wqkv_h);
    cudaGetSymbolAddress((void**)&wbott_h,g_wbott_h); cudaGetSymbolAddress((void**)&wbott_l,g_wbott_l);
    cudaGetSymbolAddress((void**)&wo_h,   g_wo_h);    cudaGetSymbolAddress((void**)&wo_l,   g_wo_l);
    cudaGetSymbolAddress((void**)&wf1_h,  g_wf1_h);
    cudaGetSymbolAddress((void**)&wf2_h,  g_wf2_h);
    cudaGetSymbolAddress((void**)&wvt_h,  g_wvt_h);
    cudaGetSymbolAddress((void**)&woutt_h,g_woutt_h);
    cudaGetSymbolAddress((void**)&wc_h,   g_wc_h);
    cudaGetSymbolAddress((void**)&wao_h,  g_wao_h);

    auto k_qk    = tgemm_kernel<0, 0, false, true,  false, true,  false, false, false>;
    auto k_csum  = tgemm_kernel<0, 0, false, false, true,  false, true,  true,  false>;
    auto k_bott  = tgemm_kernel<2, 2, false, false, true,  false, true,  false, false>;
    auto k_resid = tgemm_kernel<0, 0, false, true,  false, false, false, false, true >;
    auto k_ff1   = tgemm_kernel<0, 0, true,  false, true,  false, false, false, false>;
    auto k_pre   = tgemm_kernel<0, 0, false, false, true,  false, false, false, false>;
    cudaFuncSetAttribute(k_qk,    cudaFuncAttributeMaxDynamicSharedMemorySize, TG_SMEM);
    cudaFuncSetAttribute(k_csum,  cudaFuncAttributeMaxDynamicSharedMemorySize, TG_SMEM);
    cudaFuncSetAttribute(k_bott,  cudaFuncAttributeMaxDynamicSharedMemorySize, TG_SMEM);
    cudaFuncSetAttribute(k_resid, cudaFuncAttributeMaxDynamicSharedMemorySize, TG_SMEM);
    cudaFuncSetAttribute(k_ff1,   cudaFuncAttributeMaxDynamicSharedMemorySize, TG_SMEM);
    cudaFuncSetAttribute(k_pre,   cudaFuncAttributeMaxDynamicSharedMemorySize, TG_SMEM);

    cudaStream_t side = 0;
    cudaEvent_t evFork = 0, evJoin = 0;
    bool use_side = (cudaStreamCreateWithFlags(&side, cudaStreamNonBlocking) == cudaSuccess)
                 && (cudaEventCreateWithFlags(&evFork, cudaEventDisableTiming) == cudaSuccess)
                 && (cudaEventCreateWithFlags(&evJoin, cudaEventDisableTiming) == cudaSuccess);
    cudaStream_t prepSt = use_side ? side : (cudaStream_t)0;

    // ---- main-path prep ----
    scan_kernel<<<1, 1024>>>(name_lens, off, total);
    fill_rows_kernel<<<NS, 32>>>(name_lens, off, name_tokens, rowtok);
    gather_split_kernel<<<NS * LS, 128>>>(wte, rowtok, total, gah, gal);
    launch_split_s(0, mha_in_w, wqkv_h, nullptr, (size_t)3 * DE * DE);
    launch_split_s(0, bott_w,   wbott_h, wbott_l, (size_t)HD * (XFD + DE));
    launch_split_s(0, x_feats,  xf_h, xf_l, (size_t)NS * XFD);
    transpose_split_kernel<<<dim3(DE / 32, DE / 32, 1), dim3(32, 8)>>>(
        mha_out_w, DE, DE, woutt_h, nullptr, 0, 0);
    bias_fold_kernel<<<dim3(HD, 1), 128>>>(
        bott_w, XFD + DE, XFD, mha_out_b, nullptr, bao, DE, 0, 0, 0, 0);

    // ---- fork: encoder-weight prep on side stream ----
    if (use_side) {
        cudaEventRecord(evFork, 0);
        cudaStreamWaitEvent(side, evFork, 0);
    }
    launch_split_s(prepSt, enc_out_w, wo_h,  wo_l,  (size_t)NLAY * HD * HD);
    launch_split_s(prepSt, enc_ff1_w, wf1_h, nullptr, (size_t)NLAY * 2 * HD * HD);
    launch_split_s(prepSt, enc_ff2_w, wf2_h, nullptr, (size_t)NLAY * HD * 2 * HD);
    transpose_split_kernel<<<dim3(HD / 32, HD / 32, NLAY), dim3(32, 8), 0, prepSt>>>(
        enc_in_w + (size_t)2 * HD * HD, HD, HD, wvt_h, nullptr,
        (size_t)3 * HD * HD, (size_t)HD * HD);
    bias_fold_kernel<<<dim3(HD, NLAY), 128, 0, prepSt>>>(
        enc_out_w, HD, 0, enc_in_b + 2 * HD, enc_out_b, bc, HD,
        (size_t)HD * HD, (size_t)3 * HD, (size_t)HD, (size_t)HD);
    k_pre<<<dim3(HD / 128, HD / 128, NLAY), 256, TG_SMEM, prepSt>>>(
        HD, HD, HD, 0,
        wo_h, wo_l, HD, nullptr, nullptr, 0, nullptr,
        wvt_h, HD, nullptr, 0,
        zero, nullptr, nullptr,
        nullptr, wc_h, nullptr,
        (size_t)HD * HD, (size_t)HD * HD, (size_t)HD * HD, HD, HD, 0, nullptr, nullptr);
    k_pre<<<dim3(DE / 128, HD / 128, 1), 256, TG_SMEM, prepSt>>>(
        HD, DE, DE, 0,
        wbott_h + XFD, wbott_l + XFD, XFD + DE, nullptr, nullptr, 0, nullptr,
        woutt_h, DE, nullptr, 0,
        zero, nullptr, nullptr,
        nullptr, wao_h, nullptr, 0, 0, 0, DE, DE, 0, nullptr, nullptr);
    if (use_side) cudaEventRecord(evJoin, side);

    const int MQ = NS * LS;
    const int KQ = DE;
    const int NQ = 2 * DE;       // Q,K only

    // 1. qk(compact) = gathered_emb @ [Wq;Wk]^T + bias
    k_qk<<<dim3(NQ / 128, MQ / 128, 1), 256, TG_SMEM>>>(
        MQ, NQ, KQ, 0,
        gah, gal, KQ, nullptr, nullptr, 0, total,
        wqkv_h, KQ, nullptr, 0,
        mha_in_b, nullptr, nullptr, qkv, nullptr, nullptr, 0, 0, 0, NQ, NQ, 0, nullptr, nullptr);

    // 2. attention weights -> per-head mixed embeddings CE [4096 x 4 x 768]
    name_attn_kernel<<<dim3(NHN, NS), 192>>>(qkv, off, gah, gal, ce_h, ce_l);

    // 2b. attnsum_h = CE_h @ Wv_h^T + len*bv_h
    k_csum<<<dim3(2, NS / 128, NHN), 256, TG_SMEM>>>(
        NS, DHN, DE, 0,
        ce_h, ce_l, NHN * DE, nullptr, nullptr, 0, nullptr,
        wqkv_h + (size_t)2 * DE * DE, DE, nullptr, 0,
        zero, mha_in_b + 2 * DE, name_lens,
        nullptr, attn_h, attn_l,
        (size_t)DE, (size_t)DHN * DE, (size_t)DHN,
        DE, DHN, (size_t)DHN, nullptr, nullptr);

    // ---- join ----
    if (use_side) cudaStreamWaitEvent(0, evJoin, 0);

    // 3. x = xf@Wb1^T + attnsum@Wao^T + bbott + len*bao -> hh/hl split only
    k_bott<<<dim3(HD / 128, NS / 128, 1), 256, TG_SMEM>>>(
        NS, HD, XFD + DE, XFD,
        xf_h, xf_l, XFD, attn_h, attn_l, DE, nullptr,
        wbott_h, XFD + DE, wao_h, DE,
        bott_b, bao, name_lens, nullptr, hh, hl, 0, 0, 0, HD, HD, 0, nullptr, nullptr);

    // 4. encoder layers (residual read from hi/lo; LN writes hi/lo only)
    for (int l = 0; l < NLAY; l++) {
        k_resid<<<dim3(HD / 128, NS / 128, 1), 256, TG_SMEM>>>(
            NS, HD, HD, 0,
            hh, hl, HD, nullptr, nullptr, 0, nullptr,
            wc_h + (size_t)l * HD * HD, HD, nullptr, 0,
            bc + (size_t)l * HD, nullptr, nullptr, ta, nullptr, nullptr, 0, 0, 0, HD, HD, 0, hh, hl);
        ln_kernel<true, false><<<NS, 256>>>(
            ta, enc_ln1_g + (size_t)l * HD, enc_ln1_b + (size_t)l * HD,
            hh, hl, nullptr, nullptr, nullptr);

        k_ff1<<<dim3(2 * HD / 128, NS / 128, 1), 256, TG_SMEM>>>(
            NS, 2 * HD, HD, 0,
            hh, hl, HD, nullptr, nullptr, 0, nullptr,
            wf1_h + (size_t)l * 2 * HD * HD, HD, nullptr, 0,
            enc_ff1_b + (size_t)l * 2 * HD, nullptr, nullptr, nullptr, t1_h, t1_l,
            0, 0, 0, 2 * HD, 2 * HD, 0, nullptr, nullptr);
        k_resid<<<dim3(HD / 128, NS / 128, 1), 256, TG_SMEM>>>(
            NS, HD, 2 * HD, 0,
            t1_h, t1_l, 2 * HD, nullptr, nullptr, 0, nullptr,
            wf2_h + (size_t)l * HD * 2 * HD, 2 * HD, nullptr, 0,
            enc_ff2_b + (size_t)l * HD, nullptr, nullptr, ta, nullptr, nullptr, 0, 0, 0, HD, HD, 0, hh, hl);
        if (l < NLAY - 1) {
            ln_kernel<true, false><<<NS, 256>>>(
                ta, enc_ln2_g + (size_t)l * HD, enc_ln2_b + (size_t)l * HD,
                hh, hl, nullptr, nullptr, nullptr);
        } else {
            // final LN fused with classifier head -> out [4096 x 16]
            ln_kernel<false, true><<<NS, 256>>>(
                ta, enc_ln2_g + (size_t)l * HD, enc_ln2_b + (size_t)l * HD,
                nullptr, nullptr, cls_w, cls_b, out);
        }
    }
}

// round 16
// speedup vs baseline: 1.8330x; 1.2734x over previous
#include <cuda_runtime.h>
#include <cuda_fp16.h>
#include <cstdint>
#include <math.h>

// ---------------- problem constants ----------------
#define NS    4096          // N samples
#define LS    16            // L tokens
#define DE    768           // D embedding
#define NHN   4             // heads (name attn)
#define DHN   192           // head dim (name attn)
#define HD    1024          // H
#define NLAY  4             // NL
#define NCLS  16            // C
#define XFD   256           // XF

// ---------------- scratch (device globals; no cudaMalloc allowed) ----------------
__device__ float g_qkv[(size_t)NS * LS * 2 * DE];   // compacted Q,K rows, fp32
__device__ float g_ta[(size_t)NS * HD];             // fp32 (pre-LN sum)

__device__ int g_off[NS + 1];
__device__ int g_total[1];
__device__ int g_rowtok[NS * LS];

__device__ float g_zero[4096];
__device__ float g_bc[NLAY * HD];
__device__ float g_bao[HD];

// fp16 hi/lo split buffers (activations)
__device__ __align__(16) __half g_gah[(size_t)NS * LS * DE],   g_gal[(size_t)NS * LS * DE];
__device__ __align__(16) __half g_ce_h[(size_t)NS * NHN * DE], g_ce_l[(size_t)NS * NHN * DE];
__device__ __align__(16) __half g_attn_h[(size_t)NS * DE],     g_attn_l[(size_t)NS * DE];
__device__ __align__(16) __half g_xf_h[(size_t)NS * XFD],      g_xf_l[(size_t)NS * XFD];
__device__ __align__(16) __half g_hh[(size_t)NS * HD],         g_hl[(size_t)NS * HD];
__device__ __align__(16) __half g_t1_h[(size_t)NS * 2 * HD];
// fp16 split buffers (weights; lo only where read as 2-term A operand)
__device__ __align__(16) __half g_wqkv_h[(size_t)3 * DE * DE];
__device__ __align__(16) __half g_wbott_h[(size_t)HD * (XFD + DE)], g_wbott_l[(size_t)HD * (XFD + DE)];
__device__ __align__(16) __half g_wo_h[(size_t)NLAY * HD * HD],  g_wo_l[(size_t)NLAY * HD * HD];
__device__ __align__(16) __half g_wf1_h[(size_t)NLAY * 2 * HD * HD];
__device__ __align__(16) __half g_wf2_h[(size_t)NLAY * HD * 2 * HD];
__device__ __align__(16) __half g_wvt_h[(size_t)NLAY * HD * HD];
__device__ __align__(16) __half g_woutt_h[(size_t)DE * DE];
__device__ __align__(16) __half g_wc_h[(size_t)NLAY * HD * HD];
__device__ __align__(16) __half g_wao_h[(size_t)HD * DE];

// ================= helpers =================
__device__ __forceinline__ uint32_t smem_u32(const void* p) {
    uint32_t a;
    asm("{ .reg .u64 t; cvta.to.shared.u64 t, %1; cvt.u32.u64 %0, t; }" : "=r"(a) : "l"(p));
    return a;
}
__device__ __forceinline__ uint32_t sw128(uint32_t o) { return o ^ ((o >> 3) & 0x70); }

#define LDSM4(r, addr) \
    asm volatile("ldmatrix.sync.aligned.m8n8.x4.shared.b16 {%0,%1,%2,%3}, [%4];" \
        : "=r"((r)[0]), "=r"((r)[1]), "=r"((r)[2]), "=r"((r)[3]) : "r"(addr))

__device__ __forceinline__ void mma16816(float* c, const uint32_t* a, uint32_t b0, uint32_t b1) {
    asm volatile("mma.sync.aligned.m16n8k16.row.col.f32.f16.f16.f32 "
        "{%0,%1,%2,%3},{%4,%5,%6,%7},{%8,%9},{%0,%1,%2,%3};"
        : "+f"(c[0]), "+f"(c[1]), "+f"(c[2]), "+f"(c[3])
        : "r"(a[0]), "r"(a[1]), "r"(a[2]), "r"(a[3]), "r"(b0), "r"(b1));
}

#define CP_ASYNC16(dst, src) \
    asm volatile("cp.async.cg.shared.global [%0], [%1], 16;" :: "r"(dst), "l"(src))
#define CP_COMMIT() asm volatile("cp.async.commit_group;" ::: "memory")
#define CP_WAIT(n)  asm volatile("cp.async.wait_group %0;" :: "n"(n) : "memory")

// split fp32 pair -> packed fp16 hi (p) and lo residual (q)
__device__ __forceinline__ void split2(float x, float y, uint32_t& p, uint32_t& q) {
    const __half hx = __float2half_rn(x), hy = __float2half_rn(y);
    __half2 hp = __halves2half2(hx, hy);
    p = *reinterpret_cast<uint32_t*>(&hp);
    const float r0 = x - __half2float(hx), r1 = y - __half2float(hy);
    __half2 hq = __halves2half2(__float2half_rn(r0), __float2half_rn(r1));
    q = *reinterpret_cast<uint32_t*>(&hq);
}

// reconstruct fp32 pair from packed hi/lo fp16
__device__ __forceinline__ float2 recon2(uint32_t uh, uint32_t ul) {
    const float2 a = __half22float2(*reinterpret_cast<__half2*>(&uh));
    const float2 b = __half22float2(*reinterpret_cast<__half2*>(&ul));
    return make_float2(a.x + b.x, a.y + b.y);
}

// ---------------- fp32 -> fp16 hi(/lo) split (lo nullable) ----------------
__global__ __launch_bounds__(256) void split_kernel(
    const float* __restrict__ src,
    __half* __restrict__ hi, __half* __restrict__ lo, int n2)
{
    const int i = blockIdx.x * blockDim.x + threadIdx.x;
    if (i < n2) {
        const float2 v = reinterpret_cast<const float2*>(src)[i];
        uint32_t p, q;
        split2(v.x, v.y, p, q);
        reinterpret_cast<uint32_t*>(hi)[i] = p;
        if (lo) reinterpret_cast<uint32_t*>(lo)[i] = q;
    }
}

// ---------------- batched fp32 [R x C] -> transposed fp16 hi(/lo) [C x R] ----------------
__global__ __launch_bounds__(256) void transpose_split_kernel(
    const float* __restrict__ src, int ld, int R,
    __half* __restrict__ dh, __half* __restrict__ dl,
    size_t srcStride, size_t dstStride)
{
    __shared__ float tile[32][33];
    const int z = blockIdx.z;
    src += (size_t)z * srcStride;
    dh  += (size_t)z * dstStride;
    if (dl) dl += (size_t)z * dstStride;
    const int c0 = blockIdx.x * 32, r0 = blockIdx.y * 32;
    const int tx = threadIdx.x, ty = threadIdx.y;   // (32, 8)
#pragma unroll
    for (int i = ty; i < 32; i += 8)
        tile[i][tx] = src[(size_t)(r0 + i) * ld + c0 + tx];
    __syncthreads();
    if (tx < 16) {
#pragma unroll
        for (int i = ty; i < 32; i += 8) {
            uint32_t p, q;
            split2(tile[2 * tx][i], tile[2 * tx + 1][i], p, q);
            const size_t id2 = ((size_t)(c0 + i) * R + r0) / 2 + tx;
            reinterpret_cast<uint32_t*>(dh)[id2] = p;
            if (dl) reinterpret_cast<uint32_t*>(dl)[id2] = q;
        }
    }
}

// ---------------- batched bias fold: out[row] = W[row,:]·v + base[row] ----------------
__global__ __launch_bounds__(128) void bias_fold_kernel(
    const float* __restrict__ W, int ldw, int coff,
    const float* __restrict__ v, const float* __restrict__ base,
    float* __restrict__ out, int K,
    size_t wStride, size_t vStride, size_t baseStride, size_t outStride)
{
    __shared__ float red[4];
    const int z = blockIdx.y;
    W += (size_t)z * wStride;
    v += (size_t)z * vStride;
    if (base) base += (size_t)z * baseStride;
    out += (size_t)z * outStride;
    const int row = blockIdx.x;
    const int t = threadIdx.x, lane = t & 31, warp = t >> 5;
    const float* wr = W + (size_t)row * ldw + coff;
    float s = 0.f;
    for (int k = t; k < K; k += 128) s += wr[k] * v[k];
#pragma unroll
    for (int o = 16; o; o >>= 1) s += __shfl_down_sync(0xffffffffu, s, o);
    if (lane == 0) red[warp] = s;
    __syncthreads();
    if (t == 0) out[row] = red[0] + red[1] + red[2] + red[3] + (base ? base[row] : 0.f);
}

// ---------------- compaction scan ----------------
__global__ __launch_bounds__(1024) void scan_kernel(
    const int* __restrict__ lens, int* __restrict__ off, int* __restrict__ total)
{
    __shared__ int wsum[32];
    const int tid = threadIdx.x, lane = tid & 31, warp = tid >> 5;
    int v[4], s = 0;
#pragma unroll
    for (int i = 0; i < 4; i++) { v[i] = lens[tid * 4 + i]; s += v[i]; }
    int ws = s;
#pragma unroll
    for (int o = 1; o < 32; o <<= 1) { int t = __shfl_up_sync(0xffffffffu, ws, o); if (lane >= o) ws += t; }
    if (lane == 31) wsum[warp] = ws;
    __syncthreads();
    if (warp == 0) {
        int t = wsum[lane];
#pragma unroll
        for (int o = 1; o < 32; o <<= 1) { int u = __shfl_up_sync(0xffffffffu, t, o); if (lane >= o) t += u; }
        wsum[lane] = t;
    }
    __syncthreads();
    int run = ws - s + (warp ? wsum[warp - 1] : 0);
#pragma unroll
    for (int i = 0; i < 4; i++) { off[tid * 4 + i] = run; run += v[i]; }
    if (tid == 1023) { off[NS] = run; total[0] = run; }
}

__global__ __launch_bounds__(32) void fill_rows_kernel(
    const int* __restrict__ lens, const int* __restrict__ off,
    const int* __restrict__ toks, int* __restrict__ rowtok)
{
    const int b = blockIdx.x;
    const int len = lens[b], o = off[b];
    for (int s = threadIdx.x; s < len; s += 32) rowtok[o + s] = toks[b * LS + s];
}

__global__ __launch_bounds__(128) void gather_split_kernel(
    const float* __restrict__ wte, const int* __restrict__ rowtok,
    const int* __restrict__ total,
    __half* __restrict__ Ah, __half* __restrict__ Al)
{
    const int r = blockIdx.x;
    if (r >= total[0]) return;
    const float2* src = reinterpret_cast<const float2*>(wte + (size_t)rowtok[r] * DE);
    uint32_t* dh = reinterpret_cast<uint32_t*>(Ah) + (size_t)r * (DE / 2);
    uint32_t* dl = reinterpret_cast<uint32_t*>(Al) + (size_t)r * (DE / 2);
#pragma unroll
    for (int i = 0; i < 3; i++) {
        const int j = threadIdx.x + 128 * i;
        const float2 v = src[j];
        uint32_t p, q;
        split2(v.x, v.y, p, q);
        dh[j] = p; dl[j] = q;
    }
}

// ================= HMMA GEMM: C[M,N] = A[M,K] @ B[N,K]^T + bias (+rs*bias2) (+RES) =================
// ALO=true: 2-term C = (Ah+Al) @ Bh^T. ALO=false: 1-term C = Ah @ Bh^T.
// CTA tile 128x128, warp 32x64, 2 CTAs/SM.
#define CHUNK  64
#define STG_BYTES (48 * 1024)
#define OFF_AH 0
#define OFF_AL 16384
#define OFF_BH 32768
#define TG_SMEM  (2 * STG_BYTES + 256)

template<int AMODE, int BMODE, bool RELU, bool WF32, bool WSPLIT, bool MDYN, bool HASB2, bool NDYN, bool RESID, bool ALO>
__global__ __launch_bounds__(256, 2) void tgemm_kernel(
    int M, int N, int K, int K1,
    const __half* __restrict__ Ah, const __half* __restrict__ Al, int lda,
    const __half* __restrict__ A2h, const __half* __restrict__ A2l, int lda2,
    const int* __restrict__ Mlim,
    const __half* __restrict__ Bh, int ldb,
    const __half* __restrict__ B2h, int ldb2,
    const float* __restrict__ bias, const float* __restrict__ bias2,
    const int* __restrict__ rowscale,
    float* __restrict__ C,
    __half* __restrict__ Ch, __half* __restrict__ Cl,
    size_t strideA, size_t strideB, size_t strideC,
    int ldc, int Nlim, size_t strideB2,
    const __half* __restrict__ RESh, const __half* __restrict__ RESl)
{
    extern __shared__ char smem[];
    const uint32_t sb = smem_u32(smem);

    const int z = blockIdx.z;
    if (strideA) { Ah += (size_t)z * strideA; if (ALO) Al += (size_t)z * strideA; }
    if (strideB) { Bh += (size_t)z * strideB; }
    if (strideC) { Ch += (size_t)z * strideC; if (Cl) Cl += (size_t)z * strideC; }
    if (HASB2 && strideB2) bias2 += (size_t)z * strideB2;

    const int tid  = threadIdx.x;
    const int lane = tid & 31;
    const int wid  = tid >> 5;
    const int bm = blockIdx.y * 128, bn = blockIdx.x * 128;

    int Mtot = M;
    if (MDYN) {
        Mtot = Mlim[0];
        if (bm >= Mtot) return;
    }

    const int nch = K / CHUNK;

    auto issue_stage = [&](int c) {
        const int k0 = c * CHUNK;
        const uint32_t st = sb + (c & 1) * STG_BYTES;
#pragma unroll
        for (int i = 0; i < 4; i++) {
            const int idx = tid + 256 * i;
            const int row = idx >> 3;          // 0..127
            const int seg = idx & 7;
            const uint32_t sw = sw128(row * 128 + seg * 16);
            int ar = bm + row;
            if (MDYN && ar >= Mtot) ar = Mtot - 1;
            const __half *pah, *pal;
            if (AMODE == 2 && k0 >= K1) {
                const size_t off = (size_t)ar * lda2 + (k0 - K1) + seg * 8;
                pah = A2h + off; pal = A2l + off;
            } else {
                const size_t off = (size_t)ar * lda + k0 + seg * 8;
                pah = Ah + off; pal = Al + off;
            }
            CP_ASYNC16(st + OFF_AH + sw, pah);
            if (ALO) CP_ASYNC16(st + OFF_AL + sw, pal);
        }
#pragma unroll
        for (int i = 0; i < 4; i++) {
            const int idx = tid + 256 * i;
            const int row = idx >> 3;
            const int seg = idx & 7;
            const uint32_t sw = sw128(row * 128 + seg * 16);
            int br = bn + row;
            if (NDYN && br >= Nlim) br = Nlim - 1;
            const __half* pbh;
            if (BMODE == 2 && k0 >= K1) {
                pbh = B2h + (size_t)br * ldb2 + (k0 - K1) + seg * 8;
            } else {
                pbh = Bh + (size_t)br * ldb + k0 + seg * 8;
            }
            CP_ASYNC16(st + OFF_BH + sw, pbh);
        }
        CP_COMMIT();
    };

    issue_stage(0);

    // warp tile 32 (M) x 64 (N); warps 4 (M) x 2 (N)
    const int wm = (wid >> 1) * 32;
    const int wn = (wid & 1) * 64;

    float acc[2][8][4];
#pragma unroll
    for (int i = 0; i < 2; i++)
#pragma unroll
        for (int j = 0; j < 8; j++)
#pragma unroll
            for (int t = 0; t < 4; t++) acc[i][j][t] = 0.f;

    const int a_row  = (lane & 15);
    const int a_kb   = (lane >> 4) * 16;
    const int b_row  = (lane & 7) + ((lane >> 4) << 3);
    const int b_kb   = ((lane >> 3) & 1) * 16;

    for (int c = 0; c < nch; c++) {
        CP_WAIT(0);
        __syncthreads();
        if (c + 1 < nch) issue_stage(c + 1);

        const uint32_t st = sb + (c & 1) * STG_BYTES;

#pragma unroll
        for (int ks = 0; ks < 4; ks++) {
            const int kb = ks * 32;
            uint32_t ah[2][4], al[2][4];
#pragma unroll
            for (int i = 0; i < 2; i++) {
                const uint32_t oa = sw128((wm + i * 16 + a_row) * 128 + kb + a_kb);
                LDSM4(ah[i], st + OFF_AH + oa);
                if (ALO) LDSM4(al[i], st + OFF_AL + oa);
            }
            uint32_t bf[4][4];
#pragma unroll
            for (int j2 = 0; j2 < 4; j2++) {
                const uint32_t ob = sw128((wn + j2 * 16 + b_row) * 128 + kb + b_kb);
                LDSM4(bf[j2], st + OFF_BH + ob);
            }
#pragma unroll
            for (int i = 0; i < 2; i++)
#pragma unroll
                for (int j2 = 0; j2 < 4; j2++) {
                    mma16816(acc[i][2 * j2 + 0], ah[i], bf[j2][0], bf[j2][1]);
                    mma16816(acc[i][2 * j2 + 1], ah[i], bf[j2][2], bf[j2][3]);
                    if (ALO) {
                        mma16816(acc[i][2 * j2 + 0], al[i], bf[j2][0], bf[j2][1]);
                        mma16816(acc[i][2 * j2 + 1], al[i], bf[j2][2], bf[j2][3]);
                    }
                }
        }
    }

    // ---- epilogue ----
#pragma unroll
    for (int i = 0; i < 2; i++) {
        const int r0 = bm + wm + i * 16 + (lane >> 2);
        const int r1 = r0 + 8;
        const bool ok0 = !MDYN || (r0 < Mtot);
        const bool ok1 = !MDYN || (r1 < Mtot);
        const float rs0 = HASB2 ? (float)rowscale[r0] : 0.f;
        const float rs1 = HASB2 ? (float)rowscale[r1] : 0.f;
#pragma unroll
        for (int j = 0; j < 8; j++) {
            const int col = bn + wn + j * 8 + (lane & 3) * 2;
            const bool okc = !NDYN || (col < Nlim);
            float b00 = bias[col], b01 = bias[col + 1];
            float b10 = b00, b11 = b01;
            if (HASB2) {
                b00 += rs0 * bias2[col]; b01 += rs0 * bias2[col + 1];
                b10 += rs1 * bias2[col]; b11 += rs1 * bias2[col + 1];
            }
            float2 v0 = make_float2(acc[i][j][0] + b00, acc[i][j][1] + b01);
            float2 v1 = make_float2(acc[i][j][2] + b10, acc[i][j][3] + b11);
            if (RESID) {
                const uint32_t uh0 = *reinterpret_cast<const uint32_t*>(RESh + (size_t)r0 * ldc + col);
                const uint32_t ul0 = *reinterpret_cast<const uint32_t*>(RESl + (size_t)r0 * ldc + col);
                const uint32_t uh1 = *reinterpret_cast<const uint32_t*>(RESh + (size_t)r1 * ldc + col);
                const uint32_t ul1 = *reinterpret_cast<const uint32_t*>(RESl + (size_t)r1 * ldc + col);
                const float2 e0 = recon2(uh0, ul0);
                const float2 e1 = recon2(uh1, ul1);
                v0.x += e0.x; v0.y += e0.y;
                v1.x += e1.x; v1.y += e1.y;
            }
            if (RELU) {
                v0.x = fmaxf(v0.x, 0.f); v0.y = fmaxf(v0.y, 0.f);
                v1.x = fmaxf(v1.x, 0.f); v1.y = fmaxf(v1.y, 0.f);
            }
            if (WF32) {
                if (ok0 && okc) *reinterpret_cast<float2*>(C + (size_t)r0 * ldc + col) = v0;
                if (ok1 && okc) *reinterpret_cast<float2*>(C + (size_t)r1 * ldc + col) = v1;
            }
            if (WSPLIT) {
                uint32_t p, q;
                if (ok0 && okc) {
                    split2(v0.x, v0.y, p, q);
                    reinterpret_cast<uint32_t*>(Ch)[((size_t)r0 * ldc + col) >> 1] = p;
                    if (Cl) reinterpret_cast<uint32_t*>(Cl)[((size_t)r0 * ldc + col) >> 1] = q;
                }
                if (ok1 && okc) {
                    split2(v1.x, v1.y, p, q);
                    reinterpret_cast<uint32_t*>(Ch)[((size_t)r1 * ldc + col) >> 1] = p;
                    if (Cl) reinterpret_cast<uint32_t*>(Cl)[((size_t)r1 * ldc + col) >> 1] = q;
                }
            }
        }
    }
}

// ---------------- name attention: block per (head, sample); emits CE ----------------
__global__ __launch_bounds__(192) void name_attn_kernel(
    const float* __restrict__ qk, const int* __restrict__ off,
    const __half* __restrict__ eh, const __half* __restrict__ el,
    __half* __restrict__ CEh, __half* __restrict__ CEl)
{
    __shared__ float Qs[LS][DHN];
    __shared__ float Ks[LS][DHN];
    __shared__ float sc[LS][LS + 1];
    __shared__ float cw[LS];

    const int h = blockIdx.x;
    const int b = blockIdx.y;
    const int d = threadIdx.x;

    const int o   = off[b];
    const int len = off[b + 1] - o;

    const float* base = qk + (size_t)o * (2 * DE) + h * DHN + d;
    for (int s = 0; s < len; s++) {
        Qs[s][d] = base[s * (2 * DE)];
        Ks[s][d] = base[s * (2 * DE) + DE];
    }
    if (d < LS) cw[d] = 0.f;
    __syncthreads();

    const int warp = d >> 5, lane = d & 31;
    const float scale = 1.0f / sqrtf((float)DHN);
    const int np = len * len;
    for (int p = warp; p < np; p += 6) {
        const int q = p / len, j = p - q * len;
        float s = 0.f;
#pragma unroll
        for (int i = 0; i < 6; i++) s += Qs[q][lane + 32 * i] * Ks[j][lane + 32 * i];
#pragma unroll
        for (int ofs = 16; ofs; ofs >>= 1) s += __shfl_down_sync(0xffffffffu, s, ofs);
        if (lane == 0) sc[q][j] = s * scale;
    }
    __syncthreads();

    if (d < len) {
        float mx = -1e30f;
        for (int j = 0; j < len; j++) mx = fmaxf(mx, sc[d][j]);
        float sum = 0.f;
        float row[LS];
        for (int j = 0; j < len; j++) { row[j] = expf(sc[d][j] - mx); sum += row[j]; }
        const float inv = 1.f / sum;
        for (int j = 0; j < len; j++) sc[d][j] = row[j] * inv;
    }
    __syncthreads();

    if (d < len) {
        float c = 0.f;
        for (int s = 0; s < len; s++) c += sc[s][d];
        cw[d] = c;
    }
    __syncthreads();

    const uint32_t* ehp = reinterpret_cast<const uint32_t*>(eh);
    const uint32_t* elp = reinterpret_cast<const uint32_t*>(el);
    for (int p = d; p < DE / 2; p += 192) {
        float ce0 = 0.f, ce1 = 0.f;
        for (int j = 0; j < len; j++) {
            const size_t idx = (size_t)(o + j) * (DE / 2) + p;
            const float2 e = recon2(ehp[idx], elp[idx]);
            ce0 += cw[j] * e.x;
            ce1 += cw[j] * e.y;
        }
        uint32_t P, Q;
        split2(ce0, ce1, P, Q);
        const size_t id2 = (size_t)b * (NHN * DE / 2) + h * (DE / 2) + p;
        reinterpret_cast<uint32_t*>(CEh)[id2] = P;
        reinterpret_cast<uint32_t*>(CEl)[id2] = Q;
    }
}

// ---------------- LayerNorm of ta (residual pre-added); writes fp16 hi/lo only ----------------
__device__ __forceinline__ float block_reduce_sum(float v) {
    __shared__ float red[8];
    const int lane = threadIdx.x & 31, warp = threadIdx.x >> 5;
#pragma unroll
    for (int o = 16; o; o >>= 1) v += __shfl_down_sync(0xffffffffu, v, o);
    if (lane == 0) red[warp] = v;
    __syncthreads();
    v = (threadIdx.x < 8) ? red[threadIdx.x] : 0.f;
    if (warp == 0)
#pragma unroll
        for (int o = 4; o; o >>= 1) v += __shfl_down_sync(0xffffffffu, v, o);
    return v;
}

template<bool WRITEH, bool DOCLS>
__global__ __launch_bounds__(256) void ln_kernel(
    const float* __restrict__ ta,
    const float* __restrict__ g, const float* __restrict__ b,
    __half* __restrict__ hh, __half* __restrict__ hl,
    const float* __restrict__ clsw, const float* __restrict__ clsb,
    float* __restrict__ out)
{
    const int row = blockIdx.x;
    const int t = threadIdx.x;
    float v[4];
    float s = 0.f;
#pragma unroll
    for (int i = 0; i < 4; i++) {
        const int c = t + 256 * i;
        v[i] = ta[(size_t)row * HD + c];
        s += v[i];
    }
    s = block_reduce_sum(s);
    __shared__ float mean_s, rstd_s;
    if (t == 0) mean_s = s * (1.f / HD);
    __syncthreads();
    const float m = mean_s;
    float s2 = 0.f;
#pragma unroll
    for (int i = 0; i < 4; i++) { const float dd = v[i] - m; s2 += dd * dd; }
    s2 = block_reduce_sum(s2);
    if (t == 0) rstd_s = rsqrtf(s2 * (1.f / HD) + 1e-5f);
    __syncthreads();
    const float r = rstd_s;

    __shared__ float ys[HD];
#pragma unroll
    for (int i = 0; i < 4; i++) {
        const int c = t + 256 * i;
        const float y = (v[i] - m) * r * g[c] + b[c];
        if (WRITEH) {
            const float y1 = __shfl_down_sync(0xffffffffu, y, 1);
            if (!(t & 1)) {
                uint32_t p, q;
                split2(y, y1, p, q);
                const size_t id2 = ((size_t)row * HD + c) >> 1;
                reinterpret_cast<uint32_t*>(hh)[id2] = p;
                reinterpret_cast<uint32_t*>(hl)[id2] = q;
            }
        }
        if (DOCLS) ys[c] = y;
    }
    if (DOCLS) {
        __syncthreads();
        const int warp = t >> 5, lane = t & 31;
        for (int cc = warp; cc < NCLS; cc += 8) {
            const float* wr = clsw + (size_t)cc * HD;
            float sum = 0.f;
#pragma unroll
            for (int i = lane; i < HD; i += 32) sum += ys[i] * wr[i];
#pragma unroll
            for (int o = 16; o; o >>= 1) sum += __shfl_down_sync(0xffffffffu, sum, o);
            if (lane == 0) out[(size_t)row * NCLS + cc] = sum + clsb[cc];
        }
    }
}

// ---------------- orchestration ----------------
static inline void launch_split_s(cudaStream_t st, const float* src,
                                  __half* hi, __half* lo, size_t n) {
    const int n2 = (int)(n / 2);
    split_kernel<<<(n2 + 255) / 256, 256, 0, st>>>(src, hi, lo, n2);
}

extern "C" void kernel_launch(void* const* d_in, const int* in_sizes, int n_in,
                              void* d_out, int out_size)
{
    const int*   name_tokens = (const int*)d_in[0];
    const int*   name_lens   = (const int*)d_in[1];
    const float* x_feats     = (const float*)d_in[2];
    const float* wte         = (const float*)d_in[3];
    const float* mha_in_w    = (const float*)d_in[4];
    const float* mha_in_b    = (const float*)d_in[5];
    const float* mha_out_w   = (const float*)d_in[6];
    const float* mha_out_b   = (const float*)d_in[7];
    const float* bott_w      = (const float*)d_in[8];
    const float* bott_b      = (const float*)d_in[9];
    const float* enc_in_w    = (const float*)d_in[10];
    const float* enc_in_b    = (const float*)d_in[11];
    const float* enc_out_w   = (const float*)d_in[12];
    const float* enc_out_b   = (const float*)d_in[13];
    const float* enc_ln1_g   = (const float*)d_in[14];
    const float* enc_ln1_b   = (const float*)d_in[15];
    const float* enc_ln2_g   = (const float*)d_in[16];
    const float* enc_ln2_b   = (const float*)d_in[17];
    const float* enc_ff1_w   = (const float*)d_in[18];
    const float* enc_ff1_b   = (const float*)d_in[19];
    const float* enc_ff2_w   = (const float*)d_in[20];
    const float* enc_ff2_b   = (const float*)d_in[21];
    const float* cls_w       = (const float*)d_in[22];
    const float* cls_b       = (const float*)d_in[23];
    float* out = (float*)d_out;

    float *qkv, *ta, *zero, *bc, *bao;
    int *off, *total, *rowtok;
    cudaGetSymbolAddress((void**)&qkv,    g_qkv);
    cudaGetSymbolAddress((void**)&ta,     g_ta);
    cudaGetSymbolAddress((void**)&zero,   g_zero);
    cudaGetSymbolAddress((void**)&bc,     g_bc);
    cudaGetSymbolAddress((void**)&bao,    g_bao);
    cudaGetSymbolAddress((void**)&off,    g_off);
    cudaGetSymbolAddress((void**)&total,  g_total);
    cudaGetSymbolAddress((void**)&rowtok, g_rowtok);

    __half *gah, *gal, *ce_h, *ce_l, *attn_h, *attn_l, *xf_h, *xf_l, *hh, *hl, *t1_h;
    __half *wqkv_h, *wbott_h, *wbott_l, *wo_h, *wo_l, *wf1_h, *wf2_h;
    __half *wvt_h, *woutt_h, *wc_h, *wao_h;
    cudaGetSymbolAddress((void**)&gah,    g_gah);     cudaGetSymbolAddress((void**)&gal,    g_gal);
    cudaGetSymbolAddress((void**)&ce_h,   g_ce_h);    cudaGetSymbolAddress((void**)&ce_l,   g_ce_l);
    cudaGetSymbolAddress((void**)&attn_h, g_attn_h);  cudaGetSymbolAddress((void**)&attn_l, g_attn_l);
    cudaGetSymbolAddress((void**)&xf_h,   g_xf_h);    cudaGetSymbolAddress((void**)&xf_l,   g_xf_l);
    cudaGetSymbolAddress((void**)&hh,     g_hh);      cudaGetSymbolAddress((void**)&hl,     g_hl);
    cudaGetSymbolAddress((void**)&t1_h,   g_t1_h);
    cudaGetSymbolAddress((void**)&wqkv_h, g_wqkv_h);
    cudaGetSymbolAddress((void**)&wbott_h,g_wbott_h); cudaGetSymbolAddress((void**)&wbott_l,g_wbott_l);
    cudaGetSymbolAddress((void**)&wo_h,   g_wo_h);    cudaGetSymbolAddress((void**)&wo_l,   g_wo_l);
    cudaGetSymbolAddress((void**)&wf1_h,  g_wf1_h);
    cudaGetSymbolAddress((void**)&wf2_h,  g_wf2_h);
    cudaGetSymbolAddress((void**)&wvt_h,  g_wvt_h);
    cudaGetSymbolAddress((void**)&woutt_h,g_woutt_h);
    cudaGetSymbolAddress((void**)&wc_h,   g_wc_h);
    cudaGetSymbolAddress((void**)&wao_h,  g_wao_h);

    // ALO (last param): 2-term for qk/csum/bott/pre, 1-term for encoder GEMMs
    auto k_qk    = tgemm_kernel<0, 0, false, true,  false, true,  false, false, false, true >;
    auto k_csum  = tgemm_kernel<0, 0, false, false, true,  false, true,  true,  false, true >;
    auto k_bott  = tgemm_kernel<2, 2, false, false, true,  false, true,  false, false, true >;
    auto k_resid = tgemm_kernel<0, 0, false, true,  false, false, false, false, true,  false>;
    auto k_ff1   = tgemm_kernel<0, 0, true,  false, true,  false, false, false, false, false>;
    auto k_pre   = tgemm_kernel<0, 0, false, false, true,  false, false, false, false, true >;
    cudaFuncSetAttribute(k_qk,    cudaFuncAttributeMaxDynamicSharedMemorySize, TG_SMEM);
    cudaFuncSetAttribute(k_csum,  cudaFuncAttributeMaxDynamicSharedMemorySize, TG_SMEM);
    cudaFuncSetAttribute(k_bott,  cudaFuncAttributeMaxDynamicSharedMemorySize, TG_SMEM);
    cudaFuncSetAttribute(k_resid, cudaFuncAttributeMaxDynamicSharedMemorySize, TG_SMEM);
    cudaFuncSetAttribute(k_ff1,   cudaFuncAttributeMaxDynamicSharedMemorySize, TG_SMEM);
    cudaFuncSetAttribute(k_pre,   cudaFuncAttributeMaxDynamicSharedMemorySize, TG_SMEM);

    cudaStream_t side = 0;
    cudaEvent_t evFork = 0, evJoin = 0;
    bool use_side = (cudaStreamCreateWithFlags(&side, cudaStreamNonBlocking) == cudaSuccess)
                 && (cudaEventCreateWithFlags(&evFork, cudaEventDisableTiming) == cudaSuccess)
                 && (cudaEventCreateWithFlags(&evJoin, cudaEventDisableTiming) == cudaSuccess);
    cudaStream_t prepSt = use_side ? side : (cudaStream_t)0;

    // ---- main-path prep ----
    scan_kernel<<<1, 1024>>>(name_lens, off, total);
    fill_rows_kernel<<<NS, 32>>>(name_lens, off, name_tokens, rowtok);
    gather_split_kernel<<<NS * LS, 128>>>(wte, rowtok, total, gah, gal);
    launch_split_s(0, mha_in_w, wqkv_h, nullptr, (size_t)3 * DE * DE);
    launch_split_s(0, bott_w,   wbott_h, wbott_l, (size_t)HD * (XFD + DE));
    launch_split_s(0, x_feats,  xf_h, xf_l, (size_t)NS * XFD);
    transpose_split_kernel<<<dim3(DE / 32, DE / 32, 1), dim3(32, 8)>>>(
        mha_out_w, DE, DE, woutt_h, nullptr, 0, 0);
    bias_fold_kernel<<<dim3(HD, 1), 128>>>(
        bott_w, XFD + DE, XFD, mha_out_b, nullptr, bao, DE, 0, 0, 0, 0);

    // ---- fork: encoder-weight prep on side stream ----
    if (use_side) {
        cudaEventRecord(evFork, 0);
        cudaStreamWaitEvent(side, evFork, 0);
    }
    launch_split_s(prepSt, enc_out_w, wo_h,  wo_l,  (size_t)NLAY * HD * HD);
    launch_split_s(prepSt, enc_ff1_w, wf1_h, nullptr, (size_t)NLAY * 2 * HD * HD);
    launch_split_s(prepSt, enc_ff2_w, wf2_h, nullptr, (size_t)NLAY * HD * 2 * HD);
    transpose_split_kernel<<<dim3(HD / 32, HD / 32, NLAY), dim3(32, 8), 0, prepSt>>>(
        enc_in_w + (size_t)2 * HD * HD, HD, HD, wvt_h, nullptr,
        (size_t)3 * HD * HD, (size_t)HD * HD);
    bias_fold_kernel<<<dim3(HD, NLAY), 128, 0, prepSt>>>(
        enc_out_w, HD, 0, enc_in_b + 2 * HD, enc_out_b, bc, HD,
        (size_t)HD * HD, (size_t)3 * HD, (size_t)HD, (size_t)HD);
    k_pre<<<dim3(HD / 128, HD / 128, NLAY), 256, TG_SMEM, prepSt>>>(
        HD, HD, HD, 0,
        wo_h, wo_l, HD, nullptr, nullptr, 0, nullptr,
        wvt_h, HD, nullptr, 0,
        zero, nullptr, nullptr,
        nullptr, wc_h, nullptr,
        (size_t)HD * HD, (size_t)HD * HD, (size_t)HD * HD, HD, HD, 0, nullptr, nullptr);
    k_pre<<<dim3(DE / 128, HD / 128, 1), 256, TG_SMEM, prepSt>>>(
        HD, DE, DE, 0,
        wbott_h + XFD, wbott_l + XFD, XFD + DE, nullptr, nullptr, 0, nullptr,
        woutt_h, DE, nullptr, 0,
        zero, nullptr, nullptr,
        nullptr, wao_h, nullptr, 0, 0, 0, DE, DE, 0, nullptr, nullptr);
    if (use_side) cudaEventRecord(evJoin, side);

    const int MQ = NS * LS;
    const int KQ = DE;
    const int NQ = 2 * DE;       // Q,K only

    // 1. qk(compact) = gathered_emb @ [Wq;Wk]^T + bias
    k_qk<<<dim3(NQ / 128, MQ / 128, 1), 256, TG_SMEM>>>(
        MQ, NQ, KQ, 0,
        gah, gal, KQ, nullptr, nullptr, 0, total,
        wqkv_h, KQ, nullptr, 0,
        mha_in_b, nullptr, nullptr, qkv, nullptr, nullptr, 0, 0, 0, NQ, NQ, 0, nullptr, nullptr);

    // 2. attention weights -> per-head mixed embeddings CE [4096 x 4 x 768]
    name_attn_kernel<<<dim3(NHN, NS), 192>>>(qkv, off, gah, gal, ce_h, ce_l);

    // 2b. attnsum_h = CE_h @ Wv_h^T + len*bv_h
    k_csum<<<dim3(2, NS / 128, NHN), 256, TG_SMEM>>>(
        NS, DHN, DE, 0,
        ce_h, ce_l, NHN * DE, nullptr, nullptr, 0, nullptr,
        wqkv_h + (size_t)2 * DE * DE, DE, nullptr, 0,
        zero, mha_in_b + 2 * DE, name_lens,
        nullptr, attn_h, attn_l,
        (size_t)DE, (size_t)DHN * DE, (size_t)DHN,
        DE, DHN, (size_t)DHN, nullptr, nullptr);

    // ---- join ----
    if (use_side) cudaStreamWaitEvent(0, evJoin, 0);

    // 3. x = xf@Wb1^T + attnsum@Wao^T + bbott + len*bao -> hh/hl split only
    k_bott<<<dim3(HD / 128, NS / 128, 1), 256, TG_SMEM>>>(
        NS, HD, XFD + DE, XFD,
        xf_h, xf_l, XFD, attn_h, attn_l, DE, nullptr,
        wbott_h, XFD + DE, wao_h, DE,
        bott_b, bao, name_lens, nullptr, hh, hl, 0, 0, 0, HD, HD, 0, nullptr, nullptr);

    // 4. encoder layers (1-term A; residual read from hi/lo; LN writes hi/lo)
    for (int l = 0; l < NLAY; l++) {
        k_resid<<<dim3(HD / 128, NS / 128, 1), 256, TG_SMEM>>>(
            NS, HD, HD, 0,
            hh, nullptr, HD, nullptr, nullptr, 0, nullptr,
            wc_h + (size_t)l * HD * HD, HD, nullptr, 0,
            bc + (size_t)l * HD, nullptr, nullptr, ta, nullptr, nullptr, 0, 0, 0, HD, HD, 0, hh, hl);
        ln_kernel<true, false><<<NS, 256>>>(
            ta, enc_ln1_g + (size_t)l * HD, enc_ln1_b + (size_t)l * HD,
            hh, hl, nullptr, nullptr, nullptr);

        k_ff1<<<dim3(2 * HD / 128, NS / 128, 1), 256, TG_SMEM>>>(
            NS, 2 * HD, HD, 0,
            hh, nullptr, HD, nullptr, nullptr, 0, nullptr,
            wf1_h + (size_t)l * 2 * HD * HD, HD, nullptr, 0,
            enc_ff1_b + (size_t)l * 2 * HD, nullptr, nullptr, nullptr, t1_h, nullptr,
            0, 0, 0, 2 * HD, 2 * HD, 0, nullptr, nullptr);
        k_resid<<<dim3(HD / 128, NS / 128, 1), 256, TG_SMEM>>>(
            NS, HD, 2 * HD, 0,
            t1_h, nullptr, 2 * HD, nullptr, nullptr, 0, nullptr,
            wf2_h + (size_t)l * HD * 2 * HD, 2 * HD, nullptr, 0,
            enc_ff2_b + (size_t)l * HD, nullptr, nullptr, ta, nullptr, nullptr, 0, 0, 0, HD, HD, 0, hh, hl);
        if (l < NLAY - 1) {
            ln_kernel<true, false><<<NS, 256>>>(
                ta, enc_ln2_g + (size_t)l * HD, enc_ln2_b + (size_t)l * HD,
                hh, hl, nullptr, nullptr, nullptr);
        } else {
            // final LN fused with classifier head -> out [4096 x 16]
            ln_kernel<false, true><<<NS, 256>>>(
                ta, enc_ln2_g + (size_t)l * HD, enc_ln2_b + (size_t)l * HD,
                nullptr, nullptr, cls_w, cls_b, out);
        }
    }
}

// round 17
// speedup vs baseline: 2.1169x; 1.1549x over previous
#include <cuda_runtime.h>
#include <cuda_fp16.h>
#include <cstdint>
#include <math.h>

// ---------------- problem constants ----------------
#define NS    4096          // N samples
#define LS    16            // L tokens
#define DE    768           // D embedding
#define NHN   4             // heads (name attn)
#define DHN   192           // head dim (name attn)
#define HD    1024          // H
#define NLAY  4             // NL
#define NCLS  16            // C
#define XFD   256           // XF

// ---------------- scratch (device globals; no cudaMalloc allowed) ----------------
__device__ float g_qkv[(size_t)NS * LS * 2 * DE];   // compacted Q,K rows, fp32
__device__ float g_ta[(size_t)NS * HD];             // fp32 (pre-LN sum)

__device__ int g_off[NS + 1];
__device__ int g_total[1];
__device__ int g_rowtok[NS * LS];

__device__ float g_zero[4096];
__device__ float g_bc[NLAY * HD];
__device__ float g_bao[HD];

// fp16 hi/lo split buffers (activations)
__device__ __align__(16) __half g_gah[(size_t)NS * LS * DE],   g_gal[(size_t)NS * LS * DE];
__device__ __align__(16) __half g_ce_h[(size_t)NS * NHN * DE];
__device__ __align__(16) __half g_attn_h[(size_t)NS * DE];
__device__ __align__(16) __half g_xf_h[(size_t)NS * XFD];
__device__ __align__(16) __half g_hh[(size_t)NS * HD],         g_hl[(size_t)NS * HD];
__device__ __align__(16) __half g_t1_h[(size_t)NS * 2 * HD];
// fp16 split buffers (weights; lo only where read as 2-term A operand)
__device__ __align__(16) __half g_wqkv_h[(size_t)3 * DE * DE];
__device__ __align__(16) __half g_wbott_h[(size_t)HD * (XFD + DE)], g_wbott_l[(size_t)HD * (XFD + DE)];
__device__ __align__(16) __half g_wo_h[(size_t)NLAY * HD * HD],  g_wo_l[(size_t)NLAY * HD * HD];
__device__ __align__(16) __half g_wf1_h[(size_t)NLAY * 2 * HD * HD];
__device__ __align__(16) __half g_wf2_h[(size_t)NLAY * HD * 2 * HD];
__device__ __align__(16) __half g_wvt_h[(size_t)NLAY * HD * HD];
__device__ __align__(16) __half g_woutt_h[(size_t)DE * DE];
__device__ __align__(16) __half g_wc_h[(size_t)NLAY * HD * HD];
__device__ __align__(16) __half g_wao_h[(size_t)HD * DE];

// ================= helpers =================
__device__ __forceinline__ uint32_t smem_u32(const void* p) {
    uint32_t a;
    asm("{ .reg .u64 t; cvta.to.shared.u64 t, %1; cvt.u32.u64 %0, t; }" : "=r"(a) : "l"(p));
    return a;
}
__device__ __forceinline__ uint32_t sw128(uint32_t o) { return o ^ ((o >> 3) & 0x70); }

#define LDSM4(r, addr) \
    asm volatile("ldmatrix.sync.aligned.m8n8.x4.shared.b16 {%0,%1,%2,%3}, [%4];" \
        : "=r"((r)[0]), "=r"((r)[1]), "=r"((r)[2]), "=r"((r)[3]) : "r"(addr))

__device__ __forceinline__ void mma16816(float* c, const uint32_t* a, uint32_t b0, uint32_t b1) {
    asm volatile("mma.sync.aligned.m16n8k16.row.col.f32.f16.f16.f32 "
        "{%0,%1,%2,%3},{%4,%5,%6,%7},{%8,%9},{%0,%1,%2,%3};"
        : "+f"(c[0]), "+f"(c[1]), "+f"(c[2]), "+f"(c[3])
        : "r"(a[0]), "r"(a[1]), "r"(a[2]), "r"(a[3]), "r"(b0), "r"(b1));
}

#define CP_ASYNC16(dst, src) \
    asm volatile("cp.async.cg.shared.global [%0], [%1], 16;" :: "r"(dst), "l"(src))
#define CP_COMMIT() asm volatile("cp.async.commit_group;" ::: "memory")
#define CP_WAIT(n)  asm volatile("cp.async.wait_group %0;" :: "n"(n) : "memory")

// split fp32 pair -> packed fp16 hi (p) and lo residual (q)
__device__ __forceinline__ void split2(float x, float y, uint32_t& p, uint32_t& q) {
    const __half hx = __float2half_rn(x), hy = __float2half_rn(y);
    __half2 hp = __halves2half2(hx, hy);
    p = *reinterpret_cast<uint32_t*>(&hp);
    const float r0 = x - __half2float(hx), r1 = y - __half2float(hy);
    __half2 hq = __halves2half2(__float2half_rn(r0), __float2half_rn(r1));
    q = *reinterpret_cast<uint32_t*>(&hq);
}

// reconstruct fp32 pair from packed hi/lo fp16
__device__ __forceinline__ float2 recon2(uint32_t uh, uint32_t ul) {
    const float2 a = __half22float2(*reinterpret_cast<__half2*>(&uh));
    const float2 b = __half22float2(*reinterpret_cast<__half2*>(&ul));
    return make_float2(a.x + b.x, a.y + b.y);
}

// ---------------- fp32 -> fp16 hi(/lo) split (lo nullable) ----------------
__global__ __launch_bounds__(256) void split_kernel(
    const float* __restrict__ src,
    __half* __restrict__ hi, __half* __restrict__ lo, int n2)
{
    const int i = blockIdx.x * blockDim.x + threadIdx.x;
    if (i < n2) {
        const float2 v = reinterpret_cast<const float2*>(src)[i];
        uint32_t p, q;
        split2(v.x, v.y, p, q);
        reinterpret_cast<uint32_t*>(hi)[i] = p;
        if (lo) reinterpret_cast<uint32_t*>(lo)[i] = q;
    }
}

// ---------------- batched fp32 [R x C] -> transposed fp16 hi(/lo) [C x R] ----------------
__global__ __launch_bounds__(256) void transpose_split_kernel(
    const float* __restrict__ src, int ld, int R,
    __half* __restrict__ dh, __half* __restrict__ dl,
    size_t srcStride, size_t dstStride)
{
    __shared__ float tile[32][33];
    const int z = blockIdx.z;
    src += (size_t)z * srcStride;
    dh  += (size_t)z * dstStride;
    if (dl) dl += (size_t)z * dstStride;
    const int c0 = blockIdx.x * 32, r0 = blockIdx.y * 32;
    const int tx = threadIdx.x, ty = threadIdx.y;   // (32, 8)
#pragma unroll
    for (int i = ty; i < 32; i += 8)
        tile[i][tx] = src[(size_t)(r0 + i) * ld + c0 + tx];
    __syncthreads();
    if (tx < 16) {
#pragma unroll
        for (int i = ty; i < 32; i += 8) {
            uint32_t p, q;
            split2(tile[2 * tx][i], tile[2 * tx + 1][i], p, q);
            const size_t id2 = ((size_t)(c0 + i) * R + r0) / 2 + tx;
            reinterpret_cast<uint32_t*>(dh)[id2] = p;
            if (dl) reinterpret_cast<uint32_t*>(dl)[id2] = q;
        }
    }
}

// ---------------- batched bias fold: out[row] = W[row,:]·v + base[row] ----------------
__global__ __launch_bounds__(128) void bias_fold_kernel(
    const float* __restrict__ W, int ldw, int coff,
    const float* __restrict__ v, const float* __restrict__ base,
    float* __restrict__ out, int K,
    size_t wStride, size_t vStride, size_t baseStride, size_t outStride)
{
    __shared__ float red[4];
    const int z = blockIdx.y;
    W += (size_t)z * wStride;
    v += (size_t)z * vStride;
    if (base) base += (size_t)z * baseStride;
    out += (size_t)z * outStride;
    const int row = blockIdx.x;
    const int t = threadIdx.x, lane = t & 31, warp = t >> 5;
    const float* wr = W + (size_t)row * ldw + coff;
    float s = 0.f;
    for (int k = t; k < K; k += 128) s += wr[k] * v[k];
#pragma unroll
    for (int o = 16; o; o >>= 1) s += __shfl_down_sync(0xffffffffu, s, o);
    if (lane == 0) red[warp] = s;
    __syncthreads();
    if (t == 0) out[row] = red[0] + red[1] + red[2] + red[3] + (base ? base[row] : 0.f);
}

// ---------------- compaction scan ----------------
__global__ __launch_bounds__(1024) void scan_kernel(
    const int* __restrict__ lens, int* __restrict__ off, int* __restrict__ total)
{
    __shared__ int wsum[32];
    const int tid = threadIdx.x, lane = tid & 31, warp = tid >> 5;
    int v[4], s = 0;
#pragma unroll
    for (int i = 0; i < 4; i++) { v[i] = lens[tid * 4 + i]; s += v[i]; }
    int ws = s;
#pragma unroll
    for (int o = 1; o < 32; o <<= 1) { int t = __shfl_up_sync(0xffffffffu, ws, o); if (lane >= o) ws += t; }
    if (lane == 31) wsum[warp] = ws;
    __syncthreads();
    if (warp == 0) {
        int t = wsum[lane];
#pragma unroll
        for (int o = 1; o < 32; o <<= 1) { int u = __shfl_up_sync(0xffffffffu, t, o); if (lane >= o) t += u; }
        wsum[lane] = t;
    }
    __syncthreads();
    int run = ws - s + (warp ? wsum[warp - 1] : 0);
#pragma unroll
    for (int i = 0; i < 4; i++) { off[tid * 4 + i] = run; run += v[i]; }
    if (tid == 1023) { off[NS] = run; total[0] = run; }
}

__global__ __launch_bounds__(32) void fill_rows_kernel(
    const int* __restrict__ lens, const int* __restrict__ off,
    const int* __restrict__ toks, int* __restrict__ rowtok)
{
    const int b = blockIdx.x;
    const int len = lens[b], o = off[b];
    for (int s = threadIdx.x; s < len; s += 32) rowtok[o + s] = toks[b * LS + s];
}

__global__ __launch_bounds__(128) void gather_split_kernel(
    const float* __restrict__ wte, const int* __restrict__ rowtok,
    const int* __restrict__ total,
    __half* __restrict__ Ah, __half* __restrict__ Al)
{
    const int r = blockIdx.x;
    if (r >= total[0]) return;
    const float2* src = reinterpret_cast<const float2*>(wte + (size_t)rowtok[r] * DE);
    uint32_t* dh = reinterpret_cast<uint32_t*>(Ah) + (size_t)r * (DE / 2);
    uint32_t* dl = reinterpret_cast<uint32_t*>(Al) + (size_t)r * (DE / 2);
#pragma unroll
    for (int i = 0; i < 3; i++) {
        const int j = threadIdx.x + 128 * i;
        const float2 v = src[j];
        uint32_t p, q;
        split2(v.x, v.y, p, q);
        dh[j] = p; dl[j] = q;
    }
}

// ================= HMMA GEMM: C[M,N] = A[M,K] @ B[N,K]^T + bias (+rs*bias2) (+RES) =================
// ALO=true: 2-term C = (Ah+Al) @ Bh^T. ALO=false: 1-term C = Ah @ Bh^T.
// CTA tile 128x128, warp 32x64, 2 CTAs/SM.
#define CHUNK  64
#define STG_BYTES (48 * 1024)
#define OFF_AH 0
#define OFF_AL 16384
#define OFF_BH 32768
#define TG_SMEM  (2 * STG_BYTES + 256)

template<int AMODE, int BMODE, bool RELU, bool WF32, bool WSPLIT, bool MDYN, bool HASB2, bool NDYN, bool RESID, bool ALO>
__global__ __launch_bounds__(256, 2) void tgemm_kernel(
    int M, int N, int K, int K1,
    const __half* __restrict__ Ah, const __half* __restrict__ Al, int lda,
    const __half* __restrict__ A2h, const __half* __restrict__ A2l, int lda2,
    const int* __restrict__ Mlim,
    const __half* __restrict__ Bh, int ldb,
    const __half* __restrict__ B2h, int ldb2,
    const float* __restrict__ bias, const float* __restrict__ bias2,
    const int* __restrict__ rowscale,
    float* __restrict__ C,
    __half* __restrict__ Ch, __half* __restrict__ Cl,
    size_t strideA, size_t strideB, size_t strideC,
    int ldc, int Nlim, size_t strideB2,
    const __half* __restrict__ RESh, const __half* __restrict__ RESl)
{
    extern __shared__ char smem[];
    const uint32_t sb = smem_u32(smem);

    const int z = blockIdx.z;
    if (strideA) { Ah += (size_t)z * strideA; if (ALO) Al += (size_t)z * strideA; }
    if (strideB) { Bh += (size_t)z * strideB; }
    if (strideC) { Ch += (size_t)z * strideC; if (Cl) Cl += (size_t)z * strideC; }
    if (HASB2 && strideB2) bias2 += (size_t)z * strideB2;

    const int tid  = threadIdx.x;
    const int lane = tid & 31;
    const int wid  = tid >> 5;
    const int bm = blockIdx.y * 128, bn = blockIdx.x * 128;

    int Mtot = M;
    if (MDYN) {
        Mtot = Mlim[0];
        if (bm >= Mtot) return;
    }

    const int nch = K / CHUNK;

    auto issue_stage = [&](int c) {
        const int k0 = c * CHUNK;
        const uint32_t st = sb + (c & 1) * STG_BYTES;
#pragma unroll
        for (int i = 0; i < 4; i++) {
            const int idx = tid + 256 * i;
            const int row = idx >> 3;          // 0..127
            const int seg = idx & 7;
            const uint32_t sw = sw128(row * 128 + seg * 16);
            int ar = bm + row;
            if (MDYN && ar >= Mtot) ar = Mtot - 1;
            const __half *pah, *pal;
            if (AMODE == 2 && k0 >= K1) {
                const size_t off = (size_t)ar * lda2 + (k0 - K1) + seg * 8;
                pah = A2h + off; pal = A2l + off;
            } else {
                const size_t off = (size_t)ar * lda + k0 + seg * 8;
                pah = Ah + off; pal = Al + off;
            }
            CP_ASYNC16(st + OFF_AH + sw, pah);
            if (ALO) CP_ASYNC16(st + OFF_AL + sw, pal);
        }
#pragma unroll
        for (int i = 0; i < 4; i++) {
            const int idx = tid + 256 * i;
            const int row = idx >> 3;
            const int seg = idx & 7;
            const uint32_t sw = sw128(row * 128 + seg * 16);
            int br = bn + row;
            if (NDYN && br >= Nlim) br = Nlim - 1;
            const __half* pbh;
            if (BMODE == 2 && k0 >= K1) {
                pbh = B2h + (size_t)br * ldb2 + (k0 - K1) + seg * 8;
            } else {
                pbh = Bh + (size_t)br * ldb + k0 + seg * 8;
            }
            CP_ASYNC16(st + OFF_BH + sw, pbh);
        }
        CP_COMMIT();
    };

    issue_stage(0);

    // warp tile 32 (M) x 64 (N); warps 4 (M) x 2 (N)
    const int wm = (wid >> 1) * 32;
    const int wn = (wid & 1) * 64;

    float acc[2][8][4];
#pragma unroll
    for (int i = 0; i < 2; i++)
#pragma unroll
        for (int j = 0; j < 8; j++)
#pragma unroll
            for (int t = 0; t < 4; t++) acc[i][j][t] = 0.f;

    const int a_row  = (lane & 15);
    const int a_kb   = (lane >> 4) * 16;
    const int b_row  = (lane & 7) + ((lane >> 4) << 3);
    const int b_kb   = ((lane >> 3) & 1) * 16;

    for (int c = 0; c < nch; c++) {
        CP_WAIT(0);
        __syncthreads();
        if (c + 1 < nch) issue_stage(c + 1);

        const uint32_t st = sb + (c & 1) * STG_BYTES;

#pragma unroll
        for (int ks = 0; ks < 4; ks++) {
            const int kb = ks * 32;
            uint32_t ah[2][4], al[2][4];
#pragma unroll
            for (int i = 0; i < 2; i++) {
                const uint32_t oa = sw128((wm + i * 16 + a_row) * 128 + kb + a_kb);
                LDSM4(ah[i], st + OFF_AH + oa);
                if (ALO) LDSM4(al[i], st + OFF_AL + oa);
            }
            uint32_t bf[4][4];
#pragma unroll
            for (int j2 = 0; j2 < 4; j2++) {
                const uint32_t ob = sw128((wn + j2 * 16 + b_row) * 128 + kb + b_kb);
                LDSM4(bf[j2], st + OFF_BH + ob);
            }
#pragma unroll
            for (int i = 0; i < 2; i++)
#pragma unroll
                for (int j2 = 0; j2 < 4; j2++) {
                    mma16816(acc[i][2 * j2 + 0], ah[i], bf[j2][0], bf[j2][1]);
                    mma16816(acc[i][2 * j2 + 1], ah[i], bf[j2][2], bf[j2][3]);
                    if (ALO) {
                        mma16816(acc[i][2 * j2 + 0], al[i], bf[j2][0], bf[j2][1]);
                        mma16816(acc[i][2 * j2 + 1], al[i], bf[j2][2], bf[j2][3]);
                    }
                }
        }
    }

    // ---- epilogue ----
#pragma unroll
    for (int i = 0; i < 2; i++) {
        const int r0 = bm + wm + i * 16 + (lane >> 2);
        const int r1 = r0 + 8;
        const bool ok0 = !MDYN || (r0 < Mtot);
        const bool ok1 = !MDYN || (r1 < Mtot);
        const float rs0 = HASB2 ? (float)rowscale[r0] : 0.f;
        const float rs1 = HASB2 ? (float)rowscale[r1] : 0.f;
#pragma unroll
        for (int j = 0; j < 8; j++) {
            const int col = bn + wn + j * 8 + (lane & 3) * 2;
            const bool okc = !NDYN || (col < Nlim);
            float b00 = bias[col], b01 = bias[col + 1];
            float b10 = b00, b11 = b01;
            if (HASB2) {
                b00 += rs0 * bias2[col]; b01 += rs0 * bias2[col + 1];
                b10 += rs1 * bias2[col]; b11 += rs1 * bias2[col + 1];
            }
            float2 v0 = make_float2(acc[i][j][0] + b00, acc[i][j][1] + b01);
            float2 v1 = make_float2(acc[i][j][2] + b10, acc[i][j][3] + b11);
            if (RESID) {
                const uint32_t uh0 = *reinterpret_cast<const uint32_t*>(RESh + (size_t)r0 * ldc + col);
                const uint32_t ul0 = *reinterpret_cast<const uint32_t*>(RESl + (size_t)r0 * ldc + col);
                const uint32_t uh1 = *reinterpret_cast<const uint32_t*>(RESh + (size_t)r1 * ldc + col);
                const uint32_t ul1 = *reinterpret_cast<const uint32_t*>(RESl + (size_t)r1 * ldc + col);
                const float2 e0 = recon2(uh0, ul0);
                const float2 e1 = recon2(uh1, ul1);
                v0.x += e0.x; v0.y += e0.y;
                v1.x += e1.x; v1.y += e1.y;
            }
            if (RELU) {
                v0.x = fmaxf(v0.x, 0.f); v0.y = fmaxf(v0.y, 0.f);
                v1.x = fmaxf(v1.x, 0.f); v1.y = fmaxf(v1.y, 0.f);
            }
            if (WF32) {
                if (ok0 && okc) *reinterpret_cast<float2*>(C + (size_t)r0 * ldc + col) = v0;
                if (ok1 && okc) *reinterpret_cast<float2*>(C + (size_t)r1 * ldc + col) = v1;
            }
            if (WSPLIT) {
                uint32_t p, q;
                if (ok0 && okc) {
                    split2(v0.x, v0.y, p, q);
                    reinterpret_cast<uint32_t*>(Ch)[((size_t)r0 * ldc + col) >> 1] = p;
                    if (Cl) reinterpret_cast<uint32_t*>(Cl)[((size_t)r0 * ldc + col) >> 1] = q;
                }
                if (ok1 && okc) {
                    split2(v1.x, v1.y, p, q);
                    reinterpret_cast<uint32_t*>(Ch)[((size_t)r1 * ldc + col) >> 1] = p;
                    if (Cl) reinterpret_cast<uint32_t*>(Cl)[((size_t)r1 * ldc + col) >> 1] = q;
                }
            }
        }
    }
}

// ---------------- name attention: block per (head, sample); emits CE (hi only) ----------------
__global__ __launch_bounds__(192) void name_attn_kernel(
    const float* __restrict__ qk, const int* __restrict__ off,
    const __half* __restrict__ eh, const __half* __restrict__ el,
    __half* __restrict__ CEh)
{
    __shared__ float Qs[LS][DHN];
    __shared__ float Ks[LS][DHN];
    __shared__ float sc[LS][LS + 1];
    __shared__ float cw[LS];

    const int h = blockIdx.x;
    const int b = blockIdx.y;
    const int d = threadIdx.x;

    const int o   = off[b];
    const int len = off[b + 1] - o;

    const float* base = qk + (size_t)o * (2 * DE) + h * DHN + d;
    for (int s = 0; s < len; s++) {
        Qs[s][d] = base[s * (2 * DE)];
        Ks[s][d] = base[s * (2 * DE) + DE];
    }
    if (d < LS) cw[d] = 0.f;
    __syncthreads();

    const int warp = d >> 5, lane = d & 31;
    const float scale = 1.0f / sqrtf((float)DHN);
    const int np = len * len;
    for (int p = warp; p < np; p += 6) {
        const int q = p / len, j = p - q * len;
        float s = 0.f;
#pragma unroll
        for (int i = 0; i < 6; i++) s += Qs[q][lane + 32 * i] * Ks[j][lane + 32 * i];
#pragma unroll
        for (int ofs = 16; ofs; ofs >>= 1) s += __shfl_down_sync(0xffffffffu, s, ofs);
        if (lane == 0) sc[q][j] = s * scale;
    }
    __syncthreads();

    if (d < len) {
        float mx = -1e30f;
        for (int j = 0; j < len; j++) mx = fmaxf(mx, sc[d][j]);
        float sum = 0.f;
        float row[LS];
        for (int j = 0; j < len; j++) { row[j] = expf(sc[d][j] - mx); sum += row[j]; }
        const float inv = 1.f / sum;
        for (int j = 0; j < len; j++) sc[d][j] = row[j] * inv;
    }
    __syncthreads();

    if (d < len) {
        float c = 0.f;
        for (int s = 0; s < len; s++) c += sc[s][d];
        cw[d] = c;
    }
    __syncthreads();

    const uint32_t* ehp = reinterpret_cast<const uint32_t*>(eh);
    const uint32_t* elp = reinterpret_cast<const uint32_t*>(el);
    for (int p = d; p < DE / 2; p += 192) {
        float ce0 = 0.f, ce1 = 0.f;
        for (int j = 0; j < len; j++) {
            const size_t idx = (size_t)(o + j) * (DE / 2) + p;
            const float2 e = recon2(ehp[idx], elp[idx]);
            ce0 += cw[j] * e.x;
            ce1 += cw[j] * e.y;
        }
        uint32_t P, Q;
        split2(ce0, ce1, P, Q);
        const size_t id2 = (size_t)b * (NHN * DE / 2) + h * (DE / 2) + p;
        reinterpret_cast<uint32_t*>(CEh)[id2] = P;
    }
}

// ---------------- LayerNorm of ta (residual pre-added); writes fp16 hi/lo only ----------------
__device__ __forceinline__ float block_reduce_sum(float v) {
    __shared__ float red[8];
    const int lane = threadIdx.x & 31, warp = threadIdx.x >> 5;
#pragma unroll
    for (int o = 16; o; o >>= 1) v += __shfl_down_sync(0xffffffffu, v, o);
    if (lane == 0) red[warp] = v;
    __syncthreads();
    v = (threadIdx.x < 8) ? red[threadIdx.x] : 0.f;
    if (warp == 0)
#pragma unroll
        for (int o = 4; o; o >>= 1) v += __shfl_down_sync(0xffffffffu, v, o);
    return v;
}

template<bool WRITEH, bool DOCLS>
__global__ __launch_bounds__(256) void ln_kernel(
    const float* __restrict__ ta,
    const float* __restrict__ g, const float* __restrict__ b,
    __half* __restrict__ hh, __half* __restrict__ hl,
    const float* __restrict__ clsw, const float* __restrict__ clsb,
    float* __restrict__ out)
{
    const int row = blockIdx.x;
    const int t = threadIdx.x;
    float v[4];
    float s = 0.f;
#pragma unroll
    for (int i = 0; i < 4; i++) {
        const int c = t + 256 * i;
        v[i] = ta[(size_t)row * HD + c];
        s += v[i];
    }
    s = block_reduce_sum(s);
    __shared__ float mean_s, rstd_s;
    if (t == 0) mean_s = s * (1.f / HD);
    __syncthreads();
    const float m = mean_s;
    float s2 = 0.f;
#pragma unroll
    for (int i = 0; i < 4; i++) { const float dd = v[i] - m; s2 += dd * dd; }
    s2 = block_reduce_sum(s2);
    if (t == 0) rstd_s = rsqrtf(s2 * (1.f / HD) + 1e-5f);
    __syncthreads();
    const float r = rstd_s;

    __shared__ float ys[HD];
#pragma unroll
    for (int i = 0; i < 4; i++) {
        const int c = t + 256 * i;
        const float y = (v[i] - m) * r * g[c] + b[c];
        if (WRITEH) {
            const float y1 = __shfl_down_sync(0xffffffffu, y, 1);
            if (!(t & 1)) {
                uint32_t p, q;
                split2(y, y1, p, q);
                const size_t id2 = ((size_t)row * HD + c) >> 1;
                reinterpret_cast<uint32_t*>(hh)[id2] = p;
                reinterpret_cast<uint32_t*>(hl)[id2] = q;
            }
        }
        if (DOCLS) ys[c] = y;
    }
    if (DOCLS) {
        __syncthreads();
        const int warp = t >> 5, lane = t & 31;
        for (int cc = warp; cc < NCLS; cc += 8) {
            const float* wr = clsw + (size_t)cc * HD;
            float sum = 0.f;
#pragma unroll
            for (int i = lane; i < HD; i += 32) sum += ys[i] * wr[i];
#pragma unroll
            for (int o = 16; o; o >>= 1) sum += __shfl_down_sync(0xffffffffu, sum, o);
            if (lane == 0) out[(size_t)row * NCLS + cc] = sum + clsb[cc];
        }
    }
}

// ---------------- orchestration ----------------
static inline void launch_split_s(cudaStream_t st, const float* src,
                                  __half* hi, __half* lo, size_t n) {
    const int n2 = (int)(n / 2);
    split_kernel<<<(n2 + 255) / 256, 256, 0, st>>>(src, hi, lo, n2);
}

extern "C" void kernel_launch(void* const* d_in, const int* in_sizes, int n_in,
                              void* d_out, int out_size)
{
    const int*   name_tokens = (const int*)d_in[0];
    const int*   name_lens   = (const int*)d_in[1];
    const float* x_feats     = (const float*)d_in[2];
    const float* wte         = (const float*)d_in[3];
    const float* mha_in_w    = (const float*)d_in[4];
    const float* mha_in_b    = (const float*)d_in[5];
    const float* mha_out_w   = (const float*)d_in[6];
    const float* mha_out_b   = (const float*)d_in[7];
    const float* bott_w      = (const float*)d_in[8];
    const float* bott_b      = (const float*)d_in[9];
    const float* enc_in_w    = (const float*)d_in[10];
    const float* enc_in_b    = (const float*)d_in[11];
    const float* enc_out_w   = (const float*)d_in[12];
    const float* enc_out_b   = (const float*)d_in[13];
    const float* enc_ln1_g   = (const float*)d_in[14];
    const float* enc_ln1_b   = (const float*)d_in[15];
    const float* enc_ln2_g   = (const float*)d_in[16];
    const float* enc_ln2_b   = (const float*)d_in[17];
    const float* enc_ff1_w   = (const float*)d_in[18];
    const float* enc_ff1_b   = (const float*)d_in[19];
    const float* enc_ff2_w   = (const float*)d_in[20];
    const float* enc_ff2_b   = (const float*)d_in[21];
    const float* cls_w       = (const float*)d_in[22];
    const float* cls_b       = (const float*)d_in[23];
    float* out = (float*)d_out;

    float *qkv, *ta, *zero, *bc, *bao;
    int *off, *total, *rowtok;
    cudaGetSymbolAddress((void**)&qkv,    g_qkv);
    cudaGetSymbolAddress((void**)&ta,     g_ta);
    cudaGetSymbolAddress((void**)&zero,   g_zero);
    cudaGetSymbolAddress((void**)&bc,     g_bc);
    cudaGetSymbolAddress((void**)&bao,    g_bao);
    cudaGetSymbolAddress((void**)&off,    g_off);
    cudaGetSymbolAddress((void**)&total,  g_total);
    cudaGetSymbolAddress((void**)&rowtok, g_rowtok);

    __half *gah, *gal, *ce_h, *attn_h, *xf_h, *hh, *hl, *t1_h;
    __half *wqkv_h, *wbott_h, *wbott_l, *wo_h, *wo_l, *wf1_h, *wf2_h;
    __half *wvt_h, *woutt_h, *wc_h, *wao_h;
    cudaGetSymbolAddress((void**)&gah,    g_gah);     cudaGetSymbolAddress((void**)&gal,    g_gal);
    cudaGetSymbolAddress((void**)&ce_h,   g_ce_h);
    cudaGetSymbolAddress((void**)&attn_h, g_attn_h);
    cudaGetSymbolAddress((void**)&xf_h,   g_xf_h);
    cudaGetSymbolAddress((void**)&hh,     g_hh);      cudaGetSymbolAddress((void**)&hl,     g_hl);
    cudaGetSymbolAddress((void**)&t1_h,   g_t1_h);
    cudaGetSymbolAddress((void**)&wqkv_h, g_wqkv_h);
    cudaGetSymbolAddress((void**)&wbott_h,g_wbott_h); cudaGetSymbolAddress((void**)&wbott_l,g_wbott_l);
    cudaGetSymbolAddress((void**)&wo_h,   g_wo_h);    cudaGetSymbolAddress((void**)&wo_l,   g_wo_l);
    cudaGetSymbolAddress((void**)&wf1_h,  g_wf1_h);
    cudaGetSymbolAddress((void**)&wf2_h,  g_wf2_h);
    cudaGetSymbolAddress((void**)&wvt_h,  g_wvt_h);
    cudaGetSymbolAddress((void**)&woutt_h,g_woutt_h);
    cudaGetSymbolAddress((void**)&wc_h,   g_wc_h);
    cudaGetSymbolAddress((void**)&wao_h,  g_wao_h);

    // ALO (last param): 1-term everywhere on the main path; 2-term only in weight folds
    auto k_qk    = tgemm_kernel<0, 0, false, true,  false, true,  false, false, false, false>;
    auto k_csum  = tgemm_kernel<0, 0, false, false, true,  false, true,  true,  false, false>;
    auto k_bott  = tgemm_kernel<2, 2, false, false, true,  false, true,  false, false, false>;
    auto k_resid = tgemm_kernel<0, 0, false, true,  false, false, false, false, true,  false>;
    auto k_ff1   = tgemm_kernel<0, 0, true,  false, true,  false, false, false, false, false>;
    auto k_pre   = tgemm_kernel<0, 0, false, false, true,  false, false, false, false, true >;
    cudaFuncSetAttribute(k_qk,    cudaFuncAttributeMaxDynamicSharedMemorySize, TG_SMEM);
    cudaFuncSetAttribute(k_csum,  cudaFuncAttributeMaxDynamicSharedMemorySize, TG_SMEM);
    cudaFuncSetAttribute(k_bott,  cudaFuncAttributeMaxDynamicSharedMemorySize, TG_SMEM);
    cudaFuncSetAttribute(k_resid, cudaFuncAttributeMaxDynamicSharedMemorySize, TG_SMEM);
    cudaFuncSetAttribute(k_ff1,   cudaFuncAttributeMaxDynamicSharedMemorySize, TG_SMEM);
    cudaFuncSetAttribute(k_pre,   cudaFuncAttributeMaxDynamicSharedMemorySize, TG_SMEM);

    cudaStream_t side = 0;
    cudaEvent_t evFork = 0, evJoin = 0;
    bool use_side = (cudaStreamCreateWithFlags(&side, cudaStreamNonBlocking) == cudaSuccess)
                 && (cudaEventCreateWithFlags(&evFork, cudaEventDisableTiming) == cudaSuccess)
                 && (cudaEventCreateWithFlags(&evJoin, cudaEventDisableTiming) == cudaSuccess);
    cudaStream_t prepSt = use_side ? side : (cudaStream_t)0;

    // ---- main-path prep ----
    scan_kernel<<<1, 1024>>>(name_lens, off, total);
    fill_rows_kernel<<<NS, 32>>>(name_lens, off, name_tokens, rowtok);
    gather_split_kernel<<<NS * LS, 128>>>(wte, rowtok, total, gah, gal);
    launch_split_s(0, mha_in_w, wqkv_h, nullptr, (size_t)3 * DE * DE);
    launch_split_s(0, bott_w,   wbott_h, wbott_l, (size_t)HD * (XFD + DE));
    launch_split_s(0, x_feats,  xf_h, nullptr, (size_t)NS * XFD);
    transpose_split_kernel<<<dim3(DE / 32, DE / 32, 1), dim3(32, 8)>>>(
        mha_out_w, DE, DE, woutt_h, nullptr, 0, 0);
    bias_fold_kernel<<<dim3(HD, 1), 128>>>(
        bott_w, XFD + DE, XFD, mha_out_b, nullptr, bao, DE, 0, 0, 0, 0);

    // ---- fork: encoder-weight prep on side stream ----
    if (use_side) {
        cudaEventRecord(evFork, 0);
        cudaStreamWaitEvent(side, evFork, 0);
    }
    launch_split_s(prepSt, enc_out_w, wo_h,  wo_l,  (size_t)NLAY * HD * HD);
    launch_split_s(prepSt, enc_ff1_w, wf1_h, nullptr, (size_t)NLAY * 2 * HD * HD);
    launch_split_s(prepSt, enc_ff2_w, wf2_h, nullptr, (size_t)NLAY * HD * 2 * HD);
    transpose_split_kernel<<<dim3(HD / 32, HD / 32, NLAY), dim3(32, 8), 0, prepSt>>>(
        enc_in_w + (size_t)2 * HD * HD, HD, HD, wvt_h, nullptr,
        (size_t)3 * HD * HD, (size_t)HD * HD);
    bias_fold_kernel<<<dim3(HD, NLAY), 128, 0, prepSt>>>(
        enc_out_w, HD, 0, enc_in_b + 2 * HD, enc_out_b, bc, HD,
        (size_t)HD * HD, (size_t)3 * HD, (size_t)HD, (size_t)HD);
    k_pre<<<dim3(HD / 128, HD / 128, NLAY), 256, TG_SMEM, prepSt>>>(
        HD, HD, HD, 0,
        wo_h, wo_l, HD, nullptr, nullptr, 0, nullptr,
        wvt_h, HD, nullptr, 0,
        zero, nullptr, nullptr,
        nullptr, wc_h, nullptr,
        (size_t)HD * HD, (size_t)HD * HD, (size_t)HD * HD, HD, HD, 0, nullptr, nullptr);
    k_pre<<<dim3(DE / 128, HD / 128, 1), 256, TG_SMEM, prepSt>>>(
        HD, DE, DE, 0,
        wbott_h + XFD, wbott_l + XFD, XFD + DE, nullptr, nullptr, 0, nullptr,
        woutt_h, DE, nullptr, 0,
        zero, nullptr, nullptr,
        nullptr, wao_h, nullptr, 0, 0, 0, DE, DE, 0, nullptr, nullptr);
    if (use_side) cudaEventRecord(evJoin, side);

    const int MQ = NS * LS;
    const int KQ = DE;
    const int NQ = 2 * DE;       // Q,K only

    // 1. qk(compact) = gathered_emb @ [Wq;Wk]^T + bias   (1-term fp16)
    k_qk<<<dim3(NQ / 128, MQ / 128, 1), 256, TG_SMEM>>>(
        MQ, NQ, KQ, 0,
        gah, nullptr, KQ, nullptr, nullptr, 0, total,
        wqkv_h, KQ, nullptr, 0,
        mha_in_b, nullptr, nullptr, qkv, nullptr, nullptr, 0, 0, 0, NQ, NQ, 0, nullptr, nullptr);

    // 2. attention weights -> per-head mixed embeddings CE [4096 x 4 x 768]
    name_attn_kernel<<<dim3(NHN, NS), 192>>>(qkv, off, gah, gal, ce_h);

    // 2b. attnsum_h = CE_h @ Wv_h^T + len*bv_h   (1-term)
    k_csum<<<dim3(2, NS / 128, NHN), 256, TG_SMEM>>>(
        NS, DHN, DE, 0,
        ce_h, nullptr, NHN * DE, nullptr, nullptr, 0, nullptr,
        wqkv_h + (size_t)2 * DE * DE, DE, nullptr, 0,
        zero, mha_in_b + 2 * DE, name_lens,
        nullptr, attn_h, nullptr,
        (size_t)DE, (size_t)DHN * DE, (size_t)DHN,
        DE, DHN, (size_t)DHN, nullptr, nullptr);

    // ---- join ----
    if (use_side) cudaStreamWaitEvent(0, evJoin, 0);

    // 3. x = xf@Wb1^T + attnsum@Wao^T + bbott + len*bao -> hh/hl split   (1-term)
    k_bott<<<dim3(HD / 128, NS / 128, 1), 256, TG_SMEM>>>(
        NS, HD, XFD + DE, XFD,
        xf_h, nullptr, XFD, attn_h, nullptr, DE, nullptr,
        wbott_h, XFD + DE, wao_h, DE,
        bott_b, bao, name_lens, nullptr, hh, hl, 0, 0, 0, HD, HD, 0, nullptr, nullptr);

    // 4. encoder layers (1-term A; residual read from hi/lo; LN writes hi/lo)
    for (int l = 0; l < NLAY; l++) {
        k_resid<<<dim3(HD / 128, NS / 128, 1), 256, TG_SMEM>>>(
            NS, HD, HD, 0,
            hh, nullptr, HD, nullptr, nullptr, 0, nullptr,
            wc_h + (size_t)l * HD * HD, HD, nullptr, 0,
            bc + (size_t)l * HD, nullptr, nullptr, ta, nullptr, nullptr, 0, 0, 0, HD, HD, 0, hh, hl);
        ln_kernel<true, false><<<NS, 256>>>(
            ta, enc_ln1_g + (size_t)l * HD, enc_ln1_b + (size_t)l * HD,
            hh, hl, nullptr, nullptr, nullptr);

        k_ff1<<<dim3(2 * HD / 128, NS / 128, 1), 256, TG_SMEM>>>(
            NS, 2 * HD, HD, 0,
            hh, nullptr, HD, nullptr, nullptr, 0, nullptr,
            wf1_h + (size_t)l * 2 * HD * HD, HD, nullptr, 0,
            enc_ff1_b + (size_t)l * 2 * HD, nullptr, nullptr, nullptr, t1_h, nullptr,
            0, 0, 0, 2 * HD, 2 * HD, 0, nullptr, nullptr);
        k_resid<<<dim3(HD / 128, NS / 128, 1), 256, TG_SMEM>>>(
            NS, HD, 2 * HD, 0,
            t1_h, nullptr, 2 * HD, nullptr, nullptr, 0, nullptr,
            wf2_h + (size_t)l * HD * 2 * HD, 2 * HD, nullptr, 0,
            enc_ff2_b + (size_t)l * HD, nullptr, nullptr, ta, nullptr, nullptr, 0, 0, 0, HD, HD, 0, hh, hl);
        if (l < NLAY - 1) {
            ln_kernel<true, false><<<NS, 256>>>(
                ta, enc_ln2_g + (size_t)l * HD, enc_ln2_b + (size_t)l * HD,
                hh, hl, nullptr, nullptr, nullptr);
        } else {
            // final LN fused with classifier head -> out [4096 x 16]
            ln_kernel<false, true><<<NS, 256>>>(
                ta, enc_ln2_g + (size_t)l * HD, enc_ln2_b + (size_t)l * HD,
                nullptr, nullptr, cls_w, cls_b, out);
        }
    }
}